// round 1
// baseline (speedup 1.0000x reference)
#include <cuda_runtime.h>

#define BATCH  4
#define SEQ    2048
#define DMODEL 1024
#define NHEADS 16
#define HDIM   64
#define MTOT   (BATCH * SEQ)          // 8192

// ---- scratch (device globals; no allocation) ----
__device__ float g_Q[BATCH * SEQ * DMODEL];
__device__ float g_K[BATCH * SEQ * DMODEL];
__device__ float g_V[BATCH * SEQ * DMODEL];
__device__ float g_ctx[BATCH * SEQ * DMODEL];

// ============================================================================
// SGEMM: C = A(M,K) @ W(N,K)^T + bias
// MODE 0: A = g_ctx (Aparam ignored), C = Cparam, row-major (final projection)
// MODE 1/2/3: A = Aparam, C = g_Q/g_K/g_V, head-split (B,H,S,Dh) layout
// Tile: 128x128x16, 256 threads, 8x8 per thread.
// ============================================================================
template <int MODE>
__global__ __launch_bounds__(256) void sgemm_bias(
    const float* __restrict__ Aparam,
    const float* __restrict__ W,
    const float* __restrict__ bias,
    float* __restrict__ Cparam,
    int M, int N, int K)
{
    constexpr int BM = 128, BN = 128, BK = 16, TM = 8, TN = 8;
    __shared__ __align__(16) float As[BK * BM];
    __shared__ __align__(16) float Bs[BK * BN];

    const float* A = (MODE == 0) ? (const float*)g_ctx : Aparam;
    float* C;
    if      (MODE == 1) C = g_Q;
    else if (MODE == 2) C = g_K;
    else if (MODE == 3) C = g_V;
    else                C = Cparam;

    const int tid = threadIdx.x;
    const int tx = tid & 15;        // 0..15
    const int ty = tid >> 4;        // 0..15
    const int bm = blockIdx.y * BM;
    const int bn = blockIdx.x * BN;
    const int K4 = K >> 2;

    const float4* A4 = reinterpret_cast<const float4*>(A + (size_t)bm * K);
    const float4* W4 = reinterpret_cast<const float4*>(W + (size_t)bn * K);

    float acc[TM][TN] = {};

    for (int kt = 0; kt < K; kt += BK) {
        // Load tiles: 512 float4 each. idx layout: row = idx&127, kq = idx>>7
        // (conflict-free transposed smem stores; global loads are row-strided
        //  but total A/W traffic is tiny relative to compute)
        #pragma unroll
        for (int i = 0; i < 2; i++) {
            int idx = tid + i * 256;          // 0..511
            int row = idx & 127;
            int kq  = idx >> 7;               // 0..3
            float4 a = A4[(size_t)row * K4 + (kt >> 2) + kq];
            As[(kq * 4 + 0) * BM + row] = a.x;
            As[(kq * 4 + 1) * BM + row] = a.y;
            As[(kq * 4 + 2) * BM + row] = a.z;
            As[(kq * 4 + 3) * BM + row] = a.w;
            float4 b = W4[(size_t)row * K4 + (kt >> 2) + kq];
            Bs[(kq * 4 + 0) * BN + row] = b.x;
            Bs[(kq * 4 + 1) * BN + row] = b.y;
            Bs[(kq * 4 + 2) * BN + row] = b.z;
            Bs[(kq * 4 + 3) * BN + row] = b.w;
        }
        __syncthreads();

        #pragma unroll
        for (int k = 0; k < BK; k++) {
            float ra[TM], rb[TN];
            #pragma unroll
            for (int i = 0; i < TM; i++) ra[i] = As[k * BM + ty * TM + i];
            #pragma unroll
            for (int j = 0; j < TN; j++) rb[j] = Bs[k * BN + tx * TN + j];
            #pragma unroll
            for (int i = 0; i < TM; i++)
                #pragma unroll
                for (int j = 0; j < TN; j++)
                    acc[i][j] += ra[i] * rb[j];
        }
        __syncthreads();
    }

    // Epilogue: add bias, write out
    #pragma unroll
    for (int i = 0; i < TM; i++) {
        int m = bm + ty * TM + i;
        #pragma unroll
        for (int j = 0; j < TN; j++) {
            int n = bn + tx * TN + j;
            float v = acc[i][j] + bias[n];
            if (MODE == 0) {
                C[(size_t)m * N + n] = v;
            } else {
                int b  = m >> 11;           // m / SEQ
                int s  = m & (SEQ - 1);
                int h  = n >> 6;            // n / HDIM
                int dh = n & (HDIM - 1);
                C[((((size_t)b * NHEADS + h) * SEQ) + s) * HDIM + dh] = v;
            }
        }
    }
}

// ============================================================================
// Flash attention fp32. One thread per query row; q and o in registers.
// K/V tiles of 64 keys staged in smem (all threads iterate the same key ->
// pure broadcast LDS, conflict-free). Masked keys skipped exactly.
// Output written in (B, S, DMODEL) layout for the final projection.
// ============================================================================
__global__ __launch_bounds__(128) void flash_attn(const int* __restrict__ mask)
{
    constexpr int TK = 64;
    __shared__ __align__(16) float sK[TK * HDIM];
    __shared__ __align__(16) float sV[TK * HDIM];
    __shared__ int sM[TK];

    const int tid = threadIdx.x;
    const int h = blockIdx.y;
    const int b = blockIdx.z;
    const int row = blockIdx.x * 128 + tid;

    const size_t headBase = ((size_t)b * NHEADS + h) * SEQ * HDIM;
    const float4* Qp = reinterpret_cast<const float4*>(g_Q + headBase + (size_t)row * HDIM);
    const float4* Kbase = reinterpret_cast<const float4*>(g_K + headBase);
    const float4* Vbase = reinterpret_cast<const float4*>(g_V + headBase);
    const int* mb = mask + b * SEQ;

    float q[HDIM];
    #pragma unroll
    for (int i = 0; i < HDIM / 4; i++) {
        float4 t = Qp[i];
        q[4 * i + 0] = t.x; q[4 * i + 1] = t.y;
        q[4 * i + 2] = t.z; q[4 * i + 3] = t.w;
    }

    float o[HDIM];
    #pragma unroll
    for (int d = 0; d < HDIM; d++) o[d] = 0.f;
    float mmax = -1e30f;
    float l = 0.f;

    for (int kt = 0; kt < SEQ; kt += TK) {
        __syncthreads();
        // cooperative tile load: TK*HDIM floats = 1024 float4 per tile
        #pragma unroll
        for (int i = 0; i < (TK * HDIM / 4) / 128; i++) {
            int idx = tid + i * 128;
            reinterpret_cast<float4*>(sK)[idx] = Kbase[(size_t)kt * (HDIM / 4) + idx];
            reinterpret_cast<float4*>(sV)[idx] = Vbase[(size_t)kt * (HDIM / 4) + idx];
        }
        if (tid < TK) sM[tid] = mb[kt + tid];
        __syncthreads();

        for (int j = 0; j < TK; j++) {
            if (sM[j] == 0) continue;   // uniform across block -> no divergence
            const float4* kr = reinterpret_cast<const float4*>(sK + j * HDIM);
            float s = 0.f;
            #pragma unroll
            for (int i = 0; i < HDIM / 4; i++) {
                float4 kv = kr[i];
                s += q[4 * i + 0] * kv.x + q[4 * i + 1] * kv.y
                   + q[4 * i + 2] * kv.z + q[4 * i + 3] * kv.w;
            }
            s *= 0.125f;   // 1/sqrt(HDIM)

            if (s > mmax) {
                float corr = __expf(mmax - s);
                l *= corr;
                #pragma unroll
                for (int d = 0; d < HDIM; d++) o[d] *= corr;
                mmax = s;
            }
            float p = __expf(s - mmax);
            l += p;
            const float4* vr = reinterpret_cast<const float4*>(sV + j * HDIM);
            #pragma unroll
            for (int i = 0; i < HDIM / 4; i++) {
                float4 vv = vr[i];
                o[4 * i + 0] += p * vv.x; o[4 * i + 1] += p * vv.y;
                o[4 * i + 2] += p * vv.z; o[4 * i + 3] += p * vv.w;
            }
        }
    }

    const float inv = 1.f / l;
    float* op = g_ctx + ((size_t)b * SEQ + row) * DMODEL + h * HDIM;
    #pragma unroll
    for (int i = 0; i < HDIM / 4; i++) {
        float4 t;
        t.x = o[4 * i + 0] * inv; t.y = o[4 * i + 1] * inv;
        t.z = o[4 * i + 2] * inv; t.w = o[4 * i + 3] * inv;
        reinterpret_cast<float4*>(op)[i] = t;
    }
}

// ============================================================================
// Launch
// ============================================================================
extern "C" void kernel_launch(void* const* d_in, const int* in_sizes, int n_in,
                              void* d_out, int out_size)
{
    const float* query = (const float*)d_in[0];
    const float* key   = (const float*)d_in[1];
    const float* value = (const float*)d_in[2];
    const int*   mask  = (const int*)  d_in[3];
    const float* Wq    = (const float*)d_in[4];
    const float* bq    = (const float*)d_in[5];
    const float* Wk    = (const float*)d_in[6];
    const float* bk    = (const float*)d_in[7];
    const float* Wv    = (const float*)d_in[8];
    const float* bv    = (const float*)d_in[9];
    const float* Wo    = (const float*)d_in[10];
    const float* bo    = (const float*)d_in[11];
    float* out = (float*)d_out;

    dim3 gemmGrid(DMODEL / 128, MTOT / 128);   // (8, 64)
    sgemm_bias<1><<<gemmGrid, 256>>>(query, Wq, bq, nullptr, MTOT, DMODEL, DMODEL);
    sgemm_bias<2><<<gemmGrid, 256>>>(key,   Wk, bk, nullptr, MTOT, DMODEL, DMODEL);
    sgemm_bias<3><<<gemmGrid, 256>>>(value, Wv, bv, nullptr, MTOT, DMODEL, DMODEL);

    dim3 attnGrid(SEQ / 128, NHEADS, BATCH);   // (16, 16, 4)
    flash_attn<<<attnGrid, 128>>>(mask);

    sgemm_bias<0><<<gemmGrid, 256>>>(nullptr, Wo, bo, out, MTOT, DMODEL, DMODEL);
}

// round 6
// speedup vs baseline: 1.4960x; 1.4960x over previous
#include <cuda_runtime.h>
#include <cuda_bf16.h>
#include <cstdint>

#define BATCH  4
#define SEQ    2048
#define DMODEL 1024
#define NHEADS 16
#define HDIM   64
#define MTOT   (BATCH * SEQ)          // 8192

// ---- scratch (device globals; no allocation) ----
__device__ float g_Q[BATCH * SEQ * DMODEL];
__device__ float g_K[BATCH * SEQ * DMODEL];
__device__ float g_V[BATCH * SEQ * DMODEL];
__device__ float g_ctx[BATCH * SEQ * DMODEL];

// ============================================================================
// Helpers
// ============================================================================
__device__ __forceinline__ uint32_t smem_u32(const void* p) {
    uint32_t a;
    asm("{ .reg .u64 t; cvta.to.shared.u64 t, %1; cvt.u32.u64 %0, t; }"
        : "=r"(a) : "l"(p));
    return a;
}

__device__ __forceinline__ void ldsm_x4(uint32_t& r0, uint32_t& r1,
                                        uint32_t& r2, uint32_t& r3, uint32_t addr) {
    asm volatile("ldmatrix.sync.aligned.m8n8.x4.shared.b16 {%0,%1,%2,%3}, [%4];"
                 : "=r"(r0), "=r"(r1), "=r"(r2), "=r"(r3) : "r"(addr));
}

__device__ __forceinline__ void mma_bf16(float& c0, float& c1, float& c2, float& c3,
                                         uint32_t a0, uint32_t a1, uint32_t a2, uint32_t a3,
                                         uint32_t b0, uint32_t b1) {
    asm volatile(
        "mma.sync.aligned.m16n8k16.row.col.f32.bf16.bf16.f32 "
        "{%0,%1,%2,%3}, {%4,%5,%6,%7}, {%8,%9}, {%0,%1,%2,%3};"
        : "+f"(c0), "+f"(c1), "+f"(c2), "+f"(c3)
        : "r"(a0), "r"(a1), "r"(a2), "r"(a3), "r"(b0), "r"(b1));
}

// ============================================================================
// bf16x2-split tensor-core GEMM:  C = A(M,K) @ W(N,K)^T + bias
// acc += Ah*Bh + Ah*Bl + Al*Bh   (Al*Bl ~ 2^-18, dropped)
// Block tile 128x64, BK=32, 256 threads (8 warps), warp tile 32x32.
// MODE 0: A = g_ctx, C = Cparam (row-major, final projection)
// MODE 1/2/3: A = Aparam, C = g_Q/g_K/g_V in head-split (B,H,S,Dh) layout
// ============================================================================
#define SA_STRIDE 40   // bf16 elems per row (32 + 8 pad) -> 80B, conflict-free ldsm

template <int MODE>
__global__ __launch_bounds__(256) void gemm_mma(
    const float* __restrict__ Aparam,
    const float* __restrict__ W,
    const float* __restrict__ bias,
    float* __restrict__ Cparam)
{
    __shared__ __align__(16) __nv_bfloat16 sAh[128][SA_STRIDE];
    __shared__ __align__(16) __nv_bfloat16 sAl[128][SA_STRIDE];
    __shared__ __align__(16) __nv_bfloat16 sBh[64][SA_STRIDE];
    __shared__ __align__(16) __nv_bfloat16 sBl[64][SA_STRIDE];

    const float* A = (MODE == 0) ? (const float*)g_ctx : Aparam;
    float* C;
    if      (MODE == 1) C = g_Q;
    else if (MODE == 2) C = g_K;
    else if (MODE == 3) C = g_V;
    else                C = Cparam;

    const int tid = threadIdx.x;
    const int wid = tid >> 5;
    const int lid = tid & 31;
    const int bm = blockIdx.y * 128;
    const int bn = blockIdx.x * 64;
    const int wm = (wid >> 1) * 32;    // warp m offset (4 warps down)
    const int wn = (wid & 1) * 32;     // warp n offset (2 warps across)

    const float4* A4 = reinterpret_cast<const float4*>(A + (size_t)bm * DMODEL);
    const float4* W4 = reinterpret_cast<const float4*>(W + (size_t)bn * DMODEL);

    // ldmatrix lane address components (precomputed)
    const uint32_t sAh_base = smem_u32(&sAh[0][0]);
    const uint32_t sAl_base = smem_u32(&sAl[0][0]);
    const uint32_t sBh_base = smem_u32(&sBh[0][0]);
    const uint32_t sBl_base = smem_u32(&sBl[0][0]);

    // A tiles: T0=(m0-7,k0-7) T1=(m8-15,k0-7) T2=(m0-7,k8-15) T3=(m8-15,k8-15)
    const int a_row = wm + ((lid >> 3) & 1) * 8 + (lid & 7);
    const uint32_t a_koff = ((lid >> 4) * 8) * 2;
    // B tiles: T0=(n0-7,k0-7) T1=(n0-7,k8-15) T2=(n8-15,k0-7) T3=(n8-15,k8-15)
    const int b_row = wn + ((lid >> 4) & 1) * 8 + (lid & 7);
    const uint32_t b_koff = (((lid >> 3) & 1) * 8) * 2;

    float acc[2][4][4];
    #pragma unroll
    for (int i = 0; i < 2; i++)
        #pragma unroll
        for (int j = 0; j < 4; j++)
            #pragma unroll
            for (int r = 0; r < 4; r++) acc[i][j][r] = 0.f;

    for (int ch = 0; ch < 32; ch++) {
        // ---- load + split + stage ----
        // A: 128x32 f32 = 1024 float4, 4 per thread
        #pragma unroll
        for (int j = 0; j < 4; j++) {
            int idx = tid + 256 * j;
            int r = idx >> 3, q = idx & 7;
            float4 a = A4[(size_t)r * 256 + ch * 8 + q];
            __nv_bfloat16 h0 = __float2bfloat16(a.x), h1 = __float2bfloat16(a.y);
            __nv_bfloat16 h2 = __float2bfloat16(a.z), h3 = __float2bfloat16(a.w);
            __nv_bfloat16 l0 = __float2bfloat16(a.x - __bfloat162float(h0));
            __nv_bfloat16 l1 = __float2bfloat16(a.y - __bfloat162float(h1));
            __nv_bfloat16 l2 = __float2bfloat16(a.z - __bfloat162float(h2));
            __nv_bfloat16 l3 = __float2bfloat16(a.w - __bfloat162float(h3));
            __nv_bfloat162* ph = reinterpret_cast<__nv_bfloat162*>(&sAh[r][q * 4]);
            __nv_bfloat162* pl = reinterpret_cast<__nv_bfloat162*>(&sAl[r][q * 4]);
            ph[0] = __nv_bfloat162(h0, h1); ph[1] = __nv_bfloat162(h2, h3);
            pl[0] = __nv_bfloat162(l0, l1); pl[1] = __nv_bfloat162(l2, l3);
        }
        // B: 64x32 f32 = 512 float4, 2 per thread
        #pragma unroll
        for (int j = 0; j < 2; j++) {
            int idx = tid + 256 * j;
            int r = idx >> 3, q = idx & 7;
            float4 b = W4[(size_t)r * 256 + ch * 8 + q];
            __nv_bfloat16 h0 = __float2bfloat16(b.x), h1 = __float2bfloat16(b.y);
            __nv_bfloat16 h2 = __float2bfloat16(b.z), h3 = __float2bfloat16(b.w);
            __nv_bfloat16 l0 = __float2bfloat16(b.x - __bfloat162float(h0));
            __nv_bfloat16 l1 = __float2bfloat16(b.y - __bfloat162float(h1));
            __nv_bfloat16 l2 = __float2bfloat16(b.z - __bfloat162float(h2));
            __nv_bfloat16 l3 = __float2bfloat16(b.w - __bfloat162float(h3));
            __nv_bfloat162* ph = reinterpret_cast<__nv_bfloat162*>(&sBh[r][q * 4]);
            __nv_bfloat162* pl = reinterpret_cast<__nv_bfloat162*>(&sBl[r][q * 4]);
            ph[0] = __nv_bfloat162(h0, h1); ph[1] = __nv_bfloat162(h2, h3);
            pl[0] = __nv_bfloat162(l0, l1); pl[1] = __nv_bfloat162(l2, l3);
        }
        __syncthreads();

        // ---- mma phase ----
        #pragma unroll
        for (int ks = 0; ks < 2; ks++) {
            const uint32_t kbyte = ks * 32;   // 16 bf16 * 2B

            uint32_t ah[2][4], al[2][4], bh[4][2], bl[4][2];
            #pragma unroll
            for (int mi = 0; mi < 2; mi++) {
                uint32_t ad = sAh_base + (uint32_t)(a_row + mi * 16) * (SA_STRIDE * 2) + kbyte + a_koff;
                ldsm_x4(ah[mi][0], ah[mi][1], ah[mi][2], ah[mi][3], ad);
                uint32_t ad2 = sAl_base + (uint32_t)(a_row + mi * 16) * (SA_STRIDE * 2) + kbyte + a_koff;
                ldsm_x4(al[mi][0], al[mi][1], al[mi][2], al[mi][3], ad2);
            }
            #pragma unroll
            for (int njp = 0; njp < 2; njp++) {
                uint32_t r0, r1, r2, r3;
                uint32_t bd = sBh_base + (uint32_t)(b_row + njp * 16) * (SA_STRIDE * 2) + kbyte + b_koff;
                ldsm_x4(r0, r1, r2, r3, bd);
                bh[njp * 2][0] = r0; bh[njp * 2][1] = r1;
                bh[njp * 2 + 1][0] = r2; bh[njp * 2 + 1][1] = r3;
                uint32_t bd2 = sBl_base + (uint32_t)(b_row + njp * 16) * (SA_STRIDE * 2) + kbyte + b_koff;
                ldsm_x4(r0, r1, r2, r3, bd2);
                bl[njp * 2][0] = r0; bl[njp * 2][1] = r1;
                bl[njp * 2 + 1][0] = r2; bl[njp * 2 + 1][1] = r3;
            }

            #pragma unroll
            for (int mi = 0; mi < 2; mi++)
                #pragma unroll
                for (int nj = 0; nj < 4; nj++) {
                    float* c = acc[mi][nj];
                    mma_bf16(c[0], c[1], c[2], c[3],
                             ah[mi][0], ah[mi][1], ah[mi][2], ah[mi][3],
                             bh[nj][0], bh[nj][1]);
                    mma_bf16(c[0], c[1], c[2], c[3],
                             ah[mi][0], ah[mi][1], ah[mi][2], ah[mi][3],
                             bl[nj][0], bl[nj][1]);
                    mma_bf16(c[0], c[1], c[2], c[3],
                             al[mi][0], al[mi][1], al[mi][2], al[mi][3],
                             bh[nj][0], bh[nj][1]);
                }
        }
        __syncthreads();
    }

    // ---- epilogue: bias + store ----
    // m16n8 frag: c0,c1 at (row=lid/4, col=(lid%4)*2 +{0,1}); c2,c3 at row+8
    const int fr = lid >> 2;
    const int fc = (lid & 3) * 2;
    #pragma unroll
    for (int mi = 0; mi < 2; mi++)
        #pragma unroll
        for (int nj = 0; nj < 4; nj++) {
            int n = bn + wn + nj * 8 + fc;
            float2 bv = *reinterpret_cast<const float2*>(bias + n);
            #pragma unroll
            for (int half = 0; half < 2; half++) {
                int m = bm + wm + mi * 16 + fr + half * 8;
                float2 o;
                o.x = acc[mi][nj][half * 2 + 0] + bv.x;
                o.y = acc[mi][nj][half * 2 + 1] + bv.y;
                if (MODE == 0) {
                    *reinterpret_cast<float2*>(C + (size_t)m * DMODEL + n) = o;
                } else {
                    int b  = m >> 11;
                    int s  = m & (SEQ - 1);
                    int h  = n >> 6;
                    int dh = n & (HDIM - 1);
                    *reinterpret_cast<float2*>(
                        C + ((((size_t)b * NHEADS + h) * SEQ) + s) * HDIM + dh) = o;
                }
            }
        }
}

// ============================================================================
// Flash attention fp32 (unchanged). One thread per query row.
// ============================================================================
__global__ __launch_bounds__(128) void flash_attn(const int* __restrict__ mask)
{
    constexpr int TK = 64;
    __shared__ __align__(16) float sK[TK * HDIM];
    __shared__ __align__(16) float sV[TK * HDIM];
    __shared__ int sM[TK];

    const int tid = threadIdx.x;
    const int h = blockIdx.y;
    const int b = blockIdx.z;
    const int row = blockIdx.x * 128 + tid;

    const size_t headBase = ((size_t)b * NHEADS + h) * SEQ * HDIM;
    const float4* Qp = reinterpret_cast<const float4*>(g_Q + headBase + (size_t)row * HDIM);
    const float4* Kbase = reinterpret_cast<const float4*>(g_K + headBase);
    const float4* Vbase = reinterpret_cast<const float4*>(g_V + headBase);
    const int* mb = mask + b * SEQ;

    float q[HDIM];
    #pragma unroll
    for (int i = 0; i < HDIM / 4; i++) {
        float4 t = Qp[i];
        q[4 * i + 0] = t.x; q[4 * i + 1] = t.y;
        q[4 * i + 2] = t.z; q[4 * i + 3] = t.w;
    }

    float o[HDIM];
    #pragma unroll
    for (int d = 0; d < HDIM; d++) o[d] = 0.f;
    float mmax = -1e30f;
    float l = 0.f;

    for (int kt = 0; kt < SEQ; kt += TK) {
        __syncthreads();
        #pragma unroll
        for (int i = 0; i < (TK * HDIM / 4) / 128; i++) {
            int idx = tid + i * 128;
            reinterpret_cast<float4*>(sK)[idx] = Kbase[(size_t)kt * (HDIM / 4) + idx];
            reinterpret_cast<float4*>(sV)[idx] = Vbase[(size_t)kt * (HDIM / 4) + idx];
        }
        if (tid < TK) sM[tid] = mb[kt + tid];
        __syncthreads();

        for (int j = 0; j < TK; j++) {
            if (sM[j] == 0) continue;
            const float4* kr = reinterpret_cast<const float4*>(sK + j * HDIM);
            float s = 0.f;
            #pragma unroll
            for (int i = 0; i < HDIM / 4; i++) {
                float4 kv = kr[i];
                s += q[4 * i + 0] * kv.x + q[4 * i + 1] * kv.y
                   + q[4 * i + 2] * kv.z + q[4 * i + 3] * kv.w;
            }
            s *= 0.125f;

            if (s > mmax) {
                float corr = __expf(mmax - s);
                l *= corr;
                #pragma unroll
                for (int d = 0; d < HDIM; d++) o[d] *= corr;
                mmax = s;
            }
            float p = __expf(s - mmax);
            l += p;
            const float4* vr = reinterpret_cast<const float4*>(sV + j * HDIM);
            #pragma unroll
            for (int i = 0; i < HDIM / 4; i++) {
                float4 vv = vr[i];
                o[4 * i + 0] += p * vv.x; o[4 * i + 1] += p * vv.y;
                o[4 * i + 2] += p * vv.z; o[4 * i + 3] += p * vv.w;
            }
        }
    }

    const float inv = 1.f / l;
    float* op = g_ctx + ((size_t)b * SEQ + row) * DMODEL + h * HDIM;
    #pragma unroll
    for (int i = 0; i < HDIM / 4; i++) {
        float4 t;
        t.x = o[4 * i + 0] * inv; t.y = o[4 * i + 1] * inv;
        t.z = o[4 * i + 2] * inv; t.w = o[4 * i + 3] * inv;
        reinterpret_cast<float4*>(op)[i] = t;
    }
}

// ============================================================================
// Launch
// ============================================================================
extern "C" void kernel_launch(void* const* d_in, const int* in_sizes, int n_in,
                              void* d_out, int out_size)
{
    const float* query = (const float*)d_in[0];
    const float* key   = (const float*)d_in[1];
    const float* value = (const float*)d_in[2];
    const int*   mask  = (const int*)  d_in[3];
    const float* Wq    = (const float*)d_in[4];
    const float* bq    = (const float*)d_in[5];
    const float* Wk    = (const float*)d_in[6];
    const float* bk    = (const float*)d_in[7];
    const float* Wv    = (const float*)d_in[8];
    const float* bv    = (const float*)d_in[9];
    const float* Wo    = (const float*)d_in[10];
    const float* bo    = (const float*)d_in[11];
    float* out = (float*)d_out;

    dim3 gemmGrid(DMODEL / 64, MTOT / 128);   // (16, 64)
    gemm_mma<1><<<gemmGrid, 256>>>(query, Wq, bq, nullptr);
    gemm_mma<2><<<gemmGrid, 256>>>(key,   Wk, bk, nullptr);
    gemm_mma<3><<<gemmGrid, 256>>>(value, Wv, bv, nullptr);

    dim3 attnGrid(SEQ / 128, NHEADS, BATCH);   // (16, 16, 4)
    flash_attn<<<attnGrid, 128>>>(mask);

    gemm_mma<0><<<gemmGrid, 256>>>(nullptr, Wo, bo, out);
}

// round 8
// speedup vs baseline: 3.1282x; 2.0910x over previous
#include <cuda_runtime.h>
#include <cuda_bf16.h>
#include <cstdint>

#define BATCH  4
#define SEQ    2048
#define DMODEL 1024
#define NHEADS 16
#define HDIM   64
#define MTOT   (BATCH * SEQ)          // 8192
// 1/sqrt(HDIM) * log2(e), folded into Q so softmax uses exp2 directly
#define QSCALE 0.1803368801111204f
#define NEGI   -1e30f

// ---- scratch (device globals; zero-initialized, no allocation) ----
__device__ __nv_bfloat16 g_Xh[3][MTOT * DMODEL];   // query,key,value hi
__device__ __nv_bfloat16 g_Xl[3][MTOT * DMODEL];   // lo
__device__ __nv_bfloat16 g_Wh[4][DMODEL * DMODEL]; // Wq,Wk,Wv,Wo hi
__device__ __nv_bfloat16 g_Wl[4][DMODEL * DMODEL];
__device__ __nv_bfloat16 g_Qh[MTOT * DMODEL], g_Ql[MTOT * DMODEL]; // (B,H,S,Dh), scaled
__device__ __nv_bfloat16 g_Kh[MTOT * DMODEL], g_Kl[MTOT * DMODEL]; // compacted
__device__ __nv_bfloat16 g_Vh[MTOT * DMODEL], g_Vl[MTOT * DMODEL]; // compacted
__device__ __nv_bfloat16 g_Ch[MTOT * DMODEL], g_Cl[MTOT * DMODEL]; // ctx (B,S,D)
__device__ int g_pos[BATCH * SEQ];
__device__ int g_cnt[BATCH];

// ============================================================================
// Helpers
// ============================================================================
__device__ __forceinline__ uint32_t smem_u32(const void* p) {
    uint32_t a;
    asm("{ .reg .u64 t; cvta.to.shared.u64 t, %1; cvt.u32.u64 %0, t; }"
        : "=r"(a) : "l"(p));
    return a;
}

__device__ __forceinline__ void ldsm_x4(uint32_t& r0, uint32_t& r1,
                                        uint32_t& r2, uint32_t& r3, uint32_t addr) {
    asm volatile("ldmatrix.sync.aligned.m8n8.x4.shared.b16 {%0,%1,%2,%3}, [%4];"
                 : "=r"(r0), "=r"(r1), "=r"(r2), "=r"(r3) : "r"(addr));
}

__device__ __forceinline__ void ldsm_x4t(uint32_t& r0, uint32_t& r1,
                                         uint32_t& r2, uint32_t& r3, uint32_t addr) {
    asm volatile("ldmatrix.sync.aligned.m8n8.x4.trans.shared.b16 {%0,%1,%2,%3}, [%4];"
                 : "=r"(r0), "=r"(r1), "=r"(r2), "=r"(r3) : "r"(addr));
}

__device__ __forceinline__ void mma_bf16(float* c,
                                         const uint32_t* a,
                                         uint32_t b0, uint32_t b1) {
    asm volatile(
        "mma.sync.aligned.m16n8k16.row.col.f32.bf16.bf16.f32 "
        "{%0,%1,%2,%3}, {%4,%5,%6,%7}, {%8,%9}, {%0,%1,%2,%3};"
        : "+f"(c[0]), "+f"(c[1]), "+f"(c[2]), "+f"(c[3])
        : "r"(a[0]), "r"(a[1]), "r"(a[2]), "r"(a[3]), "r"(b0), "r"(b1));
}

__device__ __forceinline__ uint32_t pack2(float x, float y) {
    __nv_bfloat162 t = __floats2bfloat162_rn(x, y);
    return *reinterpret_cast<uint32_t*>(&t);
}
__device__ __forceinline__ float rb(float x) {   // round to bf16 and back
    return __bfloat162float(__float2bfloat16(x));
}
__device__ __forceinline__ float ex2(float x) {
    float r;
    asm("ex2.approx.f32 %0, %1;" : "=f"(r) : "f"(x));
    return r;
}

// ============================================================================
// Mask compaction: per batch, exclusive-scan the key mask.
// ============================================================================
__global__ void compact_mask(const int* __restrict__ mask) {
    __shared__ int ssum[1024];
    const int b = blockIdx.x, t = threadIdx.x;
    const int* mb = mask + b * SEQ;
    const int m0 = mb[2 * t] != 0, m1 = mb[2 * t + 1] != 0;
    ssum[t] = m0 + m1;
    __syncthreads();
    for (int off = 1; off < 1024; off <<= 1) {
        int v = (t >= off) ? ssum[t - off] : 0;
        __syncthreads();
        ssum[t] += v;
        __syncthreads();
    }
    const int excl = (t > 0) ? ssum[t - 1] : 0;
    g_pos[b * SEQ + 2 * t]     = m0 ? excl : -1;
    g_pos[b * SEQ + 2 * t + 1] = m1 ? (excl + m0) : -1;
    if (t == 1023) g_cnt[b] = ssum[1023];
}

// ============================================================================
// fp32 -> bf16 hi/lo split.  KIND 0-2: activations, 3-6: weights.
// ============================================================================
template <int KIND>
__global__ void convert_split(const float4* __restrict__ src, int n4) {
    const int i = blockIdx.x * blockDim.x + threadIdx.x;
    if (i >= n4) return;
    __nv_bfloat16 *H, *L;
    if (KIND < 3) { H = g_Xh[KIND]; L = g_Xl[KIND]; }
    else          { H = g_Wh[KIND - 3]; L = g_Wl[KIND - 3]; }
    const float4 v = src[i];
    const float h0 = rb(v.x), h1 = rb(v.y), h2 = rb(v.z), h3 = rb(v.w);
    uint2 uh, ul;
    uh.x = pack2(v.x, v.y); uh.y = pack2(v.z, v.w);
    ul.x = pack2(v.x - h0, v.y - h1); ul.y = pack2(v.z - h2, v.w - h3);
    reinterpret_cast<uint2*>(H)[i] = uh;
    reinterpret_cast<uint2*>(L)[i] = ul;
}

// ============================================================================
// bf16-split tensor-core GEMM:  C = A(M,K) @ W(N,K)^T + bias
// acc += Ah*Bh + Ah*Bl + Al*Bh.  Tile 128x64, BK=32, 256 thr, warp 32x32.
// ============================================================================
#define SA_STRIDE 40

template <int MODE>
__global__ __launch_bounds__(256) void gemm_bs(
    const float* __restrict__ bias,
    float* __restrict__ Cout)
{
    __shared__ __align__(16) __nv_bfloat16 sAh[128][SA_STRIDE];
    __shared__ __align__(16) __nv_bfloat16 sAl[128][SA_STRIDE];
    __shared__ __align__(16) __nv_bfloat16 sBh[64][SA_STRIDE];
    __shared__ __align__(16) __nv_bfloat16 sBl[64][SA_STRIDE];

    const __nv_bfloat16 *Ah, *Al, *Wh, *Wl;
    if      (MODE == 1) { Ah = g_Xh[0]; Al = g_Xl[0]; Wh = g_Wh[0]; Wl = g_Wl[0]; }
    else if (MODE == 2) { Ah = g_Xh[1]; Al = g_Xl[1]; Wh = g_Wh[1]; Wl = g_Wl[1]; }
    else if (MODE == 3) { Ah = g_Xh[2]; Al = g_Xl[2]; Wh = g_Wh[2]; Wl = g_Wl[2]; }
    else                { Ah = g_Ch;    Al = g_Cl;    Wh = g_Wh[3]; Wl = g_Wl[3]; }

    const int tid = threadIdx.x;
    const int wid = tid >> 5;
    const int lid = tid & 31;
    const int bm = blockIdx.y * 128;
    const int bn = blockIdx.x * 64;
    const int wm = (wid >> 1) * 32;
    const int wn = (wid & 1) * 32;

    const uint4* A4h = reinterpret_cast<const uint4*>(Ah) + (size_t)bm * 128;
    const uint4* A4l = reinterpret_cast<const uint4*>(Al) + (size_t)bm * 128;
    const uint4* W4h = reinterpret_cast<const uint4*>(Wh) + (size_t)bn * 128;
    const uint4* W4l = reinterpret_cast<const uint4*>(Wl) + (size_t)bn * 128;

    const uint32_t sAh_base = smem_u32(&sAh[0][0]);
    const uint32_t sAl_base = smem_u32(&sAl[0][0]);
    const uint32_t sBh_base = smem_u32(&sBh[0][0]);
    const uint32_t sBl_base = smem_u32(&sBl[0][0]);

    const int a_row = wm + ((lid >> 3) & 1) * 8 + (lid & 7);
    const uint32_t a_koff = ((lid >> 4) * 8) * 2;
    const int b_row = wn + ((lid >> 4) & 1) * 8 + (lid & 7);
    const uint32_t b_koff = (((lid >> 3) & 1) * 8) * 2;

    float acc[2][4][4];
    #pragma unroll
    for (int i = 0; i < 2; i++)
        #pragma unroll
        for (int j = 0; j < 4; j++)
            #pragma unroll
            for (int r = 0; r < 4; r++) acc[i][j][r] = 0.f;

    for (int ch = 0; ch < 32; ch++) {
        #pragma unroll
        for (int j = 0; j < 2; j++) {
            int idx = tid + 256 * j;
            int r = idx >> 2, q = idx & 3;
            size_t gi = (size_t)r * 128 + ch * 4 + q;
            *reinterpret_cast<uint4*>(&sAh[r][q * 8]) = A4h[gi];
            *reinterpret_cast<uint4*>(&sAl[r][q * 8]) = A4l[gi];
        }
        {
            int r = tid >> 2, q = tid & 3;
            size_t gi = (size_t)r * 128 + ch * 4 + q;
            *reinterpret_cast<uint4*>(&sBh[r][q * 8]) = W4h[gi];
            *reinterpret_cast<uint4*>(&sBl[r][q * 8]) = W4l[gi];
        }
        __syncthreads();

        #pragma unroll
        for (int ks = 0; ks < 2; ks++) {
            const uint32_t kbyte = ks * 32;
            uint32_t ah[2][4], al[2][4], bh[4][2], bl[4][2];
            #pragma unroll
            for (int mi = 0; mi < 2; mi++) {
                uint32_t ad = sAh_base + (uint32_t)(a_row + mi * 16) * (SA_STRIDE * 2) + kbyte + a_koff;
                ldsm_x4(ah[mi][0], ah[mi][1], ah[mi][2], ah[mi][3], ad);
                uint32_t ad2 = sAl_base + (uint32_t)(a_row + mi * 16) * (SA_STRIDE * 2) + kbyte + a_koff;
                ldsm_x4(al[mi][0], al[mi][1], al[mi][2], al[mi][3], ad2);
            }
            #pragma unroll
            for (int p = 0; p < 2; p++) {
                uint32_t r0, r1, r2, r3;
                uint32_t bd = sBh_base + (uint32_t)(b_row + p * 16) * (SA_STRIDE * 2) + kbyte + b_koff;
                ldsm_x4(r0, r1, r2, r3, bd);
                bh[p * 2][0] = r0; bh[p * 2][1] = r1;
                bh[p * 2 + 1][0] = r2; bh[p * 2 + 1][1] = r3;
                uint32_t bd2 = sBl_base + (uint32_t)(b_row + p * 16) * (SA_STRIDE * 2) + kbyte + b_koff;
                ldsm_x4(r0, r1, r2, r3, bd2);
                bl[p * 2][0] = r0; bl[p * 2][1] = r1;
                bl[p * 2 + 1][0] = r2; bl[p * 2 + 1][1] = r3;
            }
            #pragma unroll
            for (int mi = 0; mi < 2; mi++)
                #pragma unroll
                for (int nj = 0; nj < 4; nj++) {
                    float* c = acc[mi][nj];
                    mma_bf16(c, ah[mi], bh[nj][0], bh[nj][1]);
                    mma_bf16(c, ah[mi], bl[nj][0], bl[nj][1]);
                    mma_bf16(c, al[mi], bh[nj][0], bh[nj][1]);
                }
        }
        __syncthreads();
    }

    // ---- epilogue ----
    const int fr = lid >> 2;
    const int fc = (lid & 3) * 2;

    int prow[2][2];
    if (MODE == 2 || MODE == 3) {
        #pragma unroll
        for (int mi = 0; mi < 2; mi++)
            #pragma unroll
            for (int half = 0; half < 2; half++) {
                int m = bm + wm + mi * 16 + fr + half * 8;
                prow[mi][half] = g_pos[(m >> 11) * SEQ + (m & (SEQ - 1))];
            }
    }

    #pragma unroll
    for (int mi = 0; mi < 2; mi++)
        #pragma unroll
        for (int nj = 0; nj < 4; nj++) {
            int n = bn + wn + nj * 8 + fc;
            float2 bv = *reinterpret_cast<const float2*>(bias + n);
            #pragma unroll
            for (int half = 0; half < 2; half++) {
                int m = bm + wm + mi * 16 + fr + half * 8;
                float ox = acc[mi][nj][half * 2 + 0] + bv.x;
                float oy = acc[mi][nj][half * 2 + 1] + bv.y;
                if (MODE == 0) {
                    float2 o; o.x = ox; o.y = oy;
                    *reinterpret_cast<float2*>(Cout + (size_t)m * DMODEL + n) = o;
                } else {
                    int b  = m >> 11;
                    int s  = m & (SEQ - 1);
                    int hh = n >> 6;
                    int dh = n & (HDIM - 1);
                    if (MODE == 1) {
                        ox *= QSCALE; oy *= QSCALE;
                        size_t off = (((size_t)(b * NHEADS + hh)) * SEQ + s) * HDIM + dh;
                        float hx = rb(ox), hy = rb(oy);
                        *reinterpret_cast<uint32_t*>(g_Qh + off) = pack2(ox, oy);
                        *reinterpret_cast<uint32_t*>(g_Ql + off) = pack2(ox - hx, oy - hy);
                    } else {
                        int pr = prow[mi][half];
                        if (pr >= 0) {
                            size_t off = (((size_t)(b * NHEADS + hh)) * SEQ + pr) * HDIM + dh;
                            float hx = rb(ox), hy = rb(oy);
                            if (MODE == 2) {
                                *reinterpret_cast<uint32_t*>(g_Kh + off) = pack2(ox, oy);
                                *reinterpret_cast<uint32_t*>(g_Kl + off) = pack2(ox - hx, oy - hy);
                            } else {
                                *reinterpret_cast<uint32_t*>(g_Vh + off) = pack2(ox, oy);
                                *reinterpret_cast<uint32_t*>(g_Vl + off) = pack2(ox - hx, oy - hy);
                            }
                        }
                    }
                }
            }
        }
}

// ============================================================================
// Tensor-core flash attention over COMPACTED keys.
// ============================================================================
__global__ __launch_bounds__(256) void attn_mma()
{
    __shared__ __align__(16) __nv_bfloat16 sbuf[4 * 64 * 72];   // 36864 B

    const int tid = threadIdx.x;
    const int wid = tid >> 5;
    const int lid = tid & 31;
    const int hh = blockIdx.y;
    const int b  = blockIdx.z;
    const int qb = blockIdx.x * 128;
    const int wq = wid * 16;
    const int cnt = g_cnt[b];

    const size_t hb = ((size_t)(b * NHEADS + hh)) * SEQ * HDIM;
    const uint4* Qh4 = reinterpret_cast<const uint4*>(g_Qh + hb + (size_t)qb * HDIM);
    const uint4* Ql4 = reinterpret_cast<const uint4*>(g_Ql + hb + (size_t)qb * HDIM);
    const uint4* Kh4 = reinterpret_cast<const uint4*>(g_Kh + hb);
    const uint4* Kl4 = reinterpret_cast<const uint4*>(g_Kl + hb);
    const uint4* Vh4 = reinterpret_cast<const uint4*>(g_Vh + hb);
    const uint4* Vl4 = reinterpret_cast<const uint4*>(g_Vl + hb);

    uint4* sb4 = reinterpret_cast<uint4*>(sbuf);
    const uint32_t SB = smem_u32(sbuf);

    // ---- stage Q (128x64 hi/lo) and load fragments ----
    #pragma unroll
    for (int j = 0; j < 4; j++) {
        int idx = tid + 256 * j;
        int r = idx >> 3, q = idx & 7;
        sb4[9 * r + q]        = Qh4[r * 8 + q];
        sb4[1152 + 9 * r + q] = Ql4[r * 8 + q];
    }
    __syncthreads();

    uint32_t qfh[4][4], qfl[4][4];
    {
        const int arow = wq + (lid & 7) + ((lid >> 3) & 1) * 8;
        const int akoff = (lid >> 4) * 8;
        #pragma unroll
        for (int ks = 0; ks < 4; ks++) {
            uint32_t ad = SB + (uint32_t)(arow * 72 + ks * 16 + akoff) * 2;
            ldsm_x4(qfh[ks][0], qfh[ks][1], qfh[ks][2], qfh[ks][3], ad);
            ldsm_x4(qfl[ks][0], qfl[ks][1], qfl[ks][2], qfl[ks][3], ad + 18432);
        }
    }
    __syncthreads();

    float oacc[8][4];
    #pragma unroll
    for (int ng = 0; ng < 8; ng++)
        #pragma unroll
        for (int r = 0; r < 4; r++) oacc[ng][r] = 0.f;

    float mrow0 = NEGI, mrow1 = NEGI, lrow0 = 0.f, lrow1 = 0.f;
    const int ntl = (cnt + 63) >> 6;

    const int brow = (lid & 7) + ((lid >> 4) & 1) * 8;
    const int bko  = ((lid >> 3) & 1) * 8;
    const int vrow = lid & 15;
    const int vco  = (lid >> 4) * 8;
    const int fc   = (lid & 3) * 2;

    for (int kt = 0; kt < ntl; kt++) {
        #pragma unroll
        for (int j = 0; j < 2; j++) {
            int idx = tid + 256 * j;
            int r = idx >> 3, q = idx & 7;
            int gi = (kt * 64 + r) * 8 + q;
            sb4[9 * r + q]        = Kh4[gi];
            sb4[576  + 9 * r + q] = Kl4[gi];
            sb4[1152 + 9 * r + q] = Vh4[gi];
            sb4[1728 + 9 * r + q] = Vl4[gi];
        }
        __syncthreads();

        // ---- scores: S = Q K^T (3-term) ----
        float sacc[8][4];
        #pragma unroll
        for (int nt = 0; nt < 8; nt++)
            #pragma unroll
            for (int r = 0; r < 4; r++) sacc[nt][r] = 0.f;

        #pragma unroll
        for (int ks = 0; ks < 4; ks++) {
            uint32_t kh[8][2], kl[8][2];
            #pragma unroll
            for (int p = 0; p < 4; p++) {
                uint32_t r0, r1, r2, r3;
                uint32_t ad = SB + (uint32_t)((p * 16 + brow) * 72 + ks * 16 + bko) * 2;
                ldsm_x4(r0, r1, r2, r3, ad);
                kh[p * 2][0] = r0; kh[p * 2][1] = r1;
                kh[p * 2 + 1][0] = r2; kh[p * 2 + 1][1] = r3;
                ldsm_x4(r0, r1, r2, r3, ad + 9216);
                kl[p * 2][0] = r0; kl[p * 2][1] = r1;
                kl[p * 2 + 1][0] = r2; kl[p * 2 + 1][1] = r3;
            }
            #pragma unroll
            for (int nt = 0; nt < 8; nt++) {
                mma_bf16(sacc[nt], qfh[ks], kh[nt][0], kh[nt][1]);
                mma_bf16(sacc[nt], qfh[ks], kl[nt][0], kl[nt][1]);
                mma_bf16(sacc[nt], qfl[ks], kh[nt][0], kh[nt][1]);
            }
        }

        // ---- tail masking + row max ----
        const int key0 = kt * 64 + fc;
        float tm0 = NEGI, tm1 = NEGI;
        #pragma unroll
        for (int nt = 0; nt < 8; nt++) {
            bool v0 = (key0 + nt * 8) < cnt;
            bool v1 = (key0 + nt * 8 + 1) < cnt;
            if (!v0) { sacc[nt][0] = NEGI; sacc[nt][2] = NEGI; }
            if (!v1) { sacc[nt][1] = NEGI; sacc[nt][3] = NEGI; }
            tm0 = fmaxf(tm0, fmaxf(sacc[nt][0], sacc[nt][1]));
            tm1 = fmaxf(tm1, fmaxf(sacc[nt][2], sacc[nt][3]));
        }
        tm0 = fmaxf(tm0, __shfl_xor_sync(0xffffffffu, tm0, 1));
        tm0 = fmaxf(tm0, __shfl_xor_sync(0xffffffffu, tm0, 2));
        tm1 = fmaxf(tm1, __shfl_xor_sync(0xffffffffu, tm1, 1));
        tm1 = fmaxf(tm1, __shfl_xor_sync(0xffffffffu, tm1, 2));

        const float mn0 = fmaxf(mrow0, tm0), mn1 = fmaxf(mrow1, tm1);
        const float c0 = ex2(mrow0 - mn0), c1 = ex2(mrow1 - mn1);
        mrow0 = mn0; mrow1 = mn1;

        // ---- p = exp2(s - m), split to bf16 hi/lo A-fragments ----
        uint32_t pah[4][4], pal[4][4];
        float ls0 = 0.f, ls1 = 0.f;
        #pragma unroll
        for (int nt = 0; nt < 8; nt++) {
            float p0 = ex2(sacc[nt][0] - mn0), p1 = ex2(sacc[nt][1] - mn0);
            float p2 = ex2(sacc[nt][2] - mn1), p3 = ex2(sacc[nt][3] - mn1);
            ls0 += p0 + p1; ls1 += p2 + p3;
            float h0 = rb(p0), h1 = rb(p1), h2 = rb(p2), h3 = rb(p3);
            int kc = nt >> 1, o2 = (nt & 1) * 2;
            pah[kc][o2 + 0] = pack2(p0, p1);
            pah[kc][o2 + 1] = pack2(p2, p3);
            pal[kc][o2 + 0] = pack2(p0 - h0, p1 - h1);
            pal[kc][o2 + 1] = pack2(p2 - h2, p3 - h3);
        }
        lrow0 = lrow0 * c0 + ls0;
        lrow1 = lrow1 * c1 + ls1;
        #pragma unroll
        for (int ng = 0; ng < 8; ng++) {
            oacc[ng][0] *= c0; oacc[ng][1] *= c0;
            oacc[ng][2] *= c1; oacc[ng][3] *= c1;
        }

        // ---- O += P V (3-term), V fragments via ldmatrix.trans ----
        #pragma unroll
        for (int kc = 0; kc < 4; kc++) {
            uint32_t vh[8][2], vl[8][2];
            #pragma unroll
            for (int p = 0; p < 4; p++) {
                uint32_t r0, r1, r2, r3;
                uint32_t ad = SB + 18432 + (uint32_t)((kc * 16 + vrow) * 72 + p * 16 + vco) * 2;
                ldsm_x4t(r0, r1, r2, r3, ad);
                vh[p * 2][0] = r0; vh[p * 2][1] = r1;
                vh[p * 2 + 1][0] = r2; vh[p * 2 + 1][1] = r3;
                ldsm_x4t(r0, r1, r2, r3, ad + 9216);
                vl[p * 2][0] = r0; vl[p * 2][1] = r1;
                vl[p * 2 + 1][0] = r2; vl[p * 2 + 1][1] = r3;
            }
            #pragma unroll
            for (int ng = 0; ng < 8; ng++) {
                mma_bf16(oacc[ng], pah[kc], vh[ng][0], vh[ng][1]);
                mma_bf16(oacc[ng], pah[kc], vl[ng][0], vl[ng][1]);
                mma_bf16(oacc[ng], pal[kc], vh[ng][0], vh[ng][1]);
            }
        }
        __syncthreads();
    }

    // ---- FIX: reduce softmax denominator across the quad (was missing) ----
    lrow0 += __shfl_xor_sync(0xffffffffu, lrow0, 1);
    lrow0 += __shfl_xor_sync(0xffffffffu, lrow0, 2);
    lrow1 += __shfl_xor_sync(0xffffffffu, lrow1, 1);
    lrow1 += __shfl_xor_sync(0xffffffffu, lrow1, 2);

    // ---- epilogue: normalize, split, write ctx ----
    const float inv0 = 1.0f / lrow0;
    const float inv1 = 1.0f / lrow1;
    const int r0 = qb + wq + (lid >> 2);
    const int r1 = r0 + 8;
    #pragma unroll
    for (int ng = 0; ng < 8; ng++) {
        int col = hh * HDIM + ng * 8 + fc;
        float a0 = oacc[ng][0] * inv0, a1 = oacc[ng][1] * inv0;
        float a2 = oacc[ng][2] * inv1, a3 = oacc[ng][3] * inv1;
        size_t off0 = ((size_t)(b * SEQ + r0)) * DMODEL + col;
        size_t off1 = ((size_t)(b * SEQ + r1)) * DMODEL + col;
        float h0 = rb(a0), h1 = rb(a1), h2 = rb(a2), h3 = rb(a3);
        *reinterpret_cast<uint32_t*>(g_Ch + off0) = pack2(a0, a1);
        *reinterpret_cast<uint32_t*>(g_Cl + off0) = pack2(a0 - h0, a1 - h1);
        *reinterpret_cast<uint32_t*>(g_Ch + off1) = pack2(a2, a3);
        *reinterpret_cast<uint32_t*>(g_Cl + off1) = pack2(a2 - h2, a3 - h3);
    }
}

// ============================================================================
// Launch
// ============================================================================
extern "C" void kernel_launch(void* const* d_in, const int* in_sizes, int n_in,
                              void* d_out, int out_size)
{
    const float* query = (const float*)d_in[0];
    const float* key   = (const float*)d_in[1];
    const float* value = (const float*)d_in[2];
    const int*   mask  = (const int*)  d_in[3];
    const float* Wq    = (const float*)d_in[4];
    const float* bq    = (const float*)d_in[5];
    const float* Wk    = (const float*)d_in[6];
    const float* bk    = (const float*)d_in[7];
    const float* Wv    = (const float*)d_in[8];
    const float* bv    = (const float*)d_in[9];
    const float* Wo    = (const float*)d_in[10];
    const float* bo    = (const float*)d_in[11];
    float* out = (float*)d_out;

    const int nx4 = MTOT * DMODEL / 4;
    const int nw4 = DMODEL * DMODEL / 4;

    compact_mask<<<BATCH, 1024>>>(mask);
    convert_split<0><<<nx4 / 256, 256>>>((const float4*)query, nx4);
    convert_split<1><<<nx4 / 256, 256>>>((const float4*)key,   nx4);
    convert_split<2><<<nx4 / 256, 256>>>((const float4*)value, nx4);
    convert_split<3><<<nw4 / 256, 256>>>((const float4*)Wq, nw4);
    convert_split<4><<<nw4 / 256, 256>>>((const float4*)Wk, nw4);
    convert_split<5><<<nw4 / 256, 256>>>((const float4*)Wv, nw4);
    convert_split<6><<<nw4 / 256, 256>>>((const float4*)Wo, nw4);

    dim3 gemmGrid(DMODEL / 64, MTOT / 128);   // (16, 64)
    gemm_bs<1><<<gemmGrid, 256>>>(bq, nullptr);
    gemm_bs<2><<<gemmGrid, 256>>>(bk, nullptr);
    gemm_bs<3><<<gemmGrid, 256>>>(bv, nullptr);

    dim3 attnGrid(SEQ / 128, NHEADS, BATCH);  // (16, 16, 4)
    attn_mma<<<attnGrid, 256>>>();

    gemm_bs<0><<<gemmGrid, 256>>>(bo, out);
}

// round 9
// speedup vs baseline: 4.0963x; 1.3095x over previous
#include <cuda_runtime.h>
#include <cuda_bf16.h>
#include <cstdint>

#define BATCH  4
#define SEQ    2048
#define DMODEL 1024
#define NHEADS 16
#define HDIM   64
#define MTOT   (BATCH * SEQ)          // 8192
#define QSCALE 0.1803368801111204f   // 1/sqrt(HDIM) * log2(e)
#define NEGI   -1e30f

// ---- scratch (device globals; no allocation) ----
__device__ __nv_bfloat16 g_Xh[3][MTOT * DMODEL];
__device__ __nv_bfloat16 g_Xl[3][MTOT * DMODEL];
__device__ __nv_bfloat16 g_Wh[4][DMODEL * DMODEL];
__device__ __nv_bfloat16 g_Wl[4][DMODEL * DMODEL];
__device__ __nv_bfloat16 g_Qh[MTOT * DMODEL], g_Ql[MTOT * DMODEL]; // (B,H,S,Dh), scaled
__device__ __nv_bfloat16 g_Kh[MTOT * DMODEL], g_Kl[MTOT * DMODEL]; // compacted
__device__ __nv_bfloat16 g_Vh[MTOT * DMODEL], g_Vl[MTOT * DMODEL]; // compacted
__device__ __nv_bfloat16 g_Ch[MTOT * DMODEL], g_Cl[MTOT * DMODEL]; // ctx (B,S,D)
__device__ int g_inv[BATCH * SEQ];   // compact pos -> source row
__device__ int g_cnt[BATCH];

// ============================================================================
// Helpers
// ============================================================================
__device__ __forceinline__ uint32_t smem_u32(const void* p) {
    uint32_t a;
    asm("{ .reg .u64 t; cvta.to.shared.u64 t, %1; cvt.u32.u64 %0, t; }"
        : "=r"(a) : "l"(p));
    return a;
}

__device__ __forceinline__ void ldsm_x4(uint32_t& r0, uint32_t& r1,
                                        uint32_t& r2, uint32_t& r3, uint32_t addr) {
    asm volatile("ldmatrix.sync.aligned.m8n8.x4.shared.b16 {%0,%1,%2,%3}, [%4];"
                 : "=r"(r0), "=r"(r1), "=r"(r2), "=r"(r3) : "r"(addr));
}

__device__ __forceinline__ void ldsm_x4t(uint32_t& r0, uint32_t& r1,
                                         uint32_t& r2, uint32_t& r3, uint32_t addr) {
    asm volatile("ldmatrix.sync.aligned.m8n8.x4.trans.shared.b16 {%0,%1,%2,%3}, [%4];"
                 : "=r"(r0), "=r"(r1), "=r"(r2), "=r"(r3) : "r"(addr));
}

__device__ __forceinline__ void mma_bf16(float* c,
                                         const uint32_t* a,
                                         uint32_t b0, uint32_t b1) {
    asm volatile(
        "mma.sync.aligned.m16n8k16.row.col.f32.bf16.bf16.f32 "
        "{%0,%1,%2,%3}, {%4,%5,%6,%7}, {%8,%9}, {%0,%1,%2,%3};"
        : "+f"(c[0]), "+f"(c[1]), "+f"(c[2]), "+f"(c[3])
        : "r"(a[0]), "r"(a[1]), "r"(a[2]), "r"(a[3]), "r"(b0), "r"(b1));
}

__device__ __forceinline__ uint32_t pack2(float x, float y) {
    __nv_bfloat162 t = __floats2bfloat162_rn(x, y);
    return *reinterpret_cast<uint32_t*>(&t);
}
__device__ __forceinline__ float rb(float x) {
    return __bfloat162float(__float2bfloat16(x));
}
__device__ __forceinline__ float ex2(float x) {
    float r;
    asm("ex2.approx.f32 %0, %1;" : "=f"(r) : "f"(x));
    return r;
}
__device__ __forceinline__ void cp16(uint32_t dst, const void* src) {
    asm volatile("cp.async.cg.shared.global [%0], [%1], 16;" :: "r"(dst), "l"(src));
}
#define CP_COMMIT() asm volatile("cp.async.commit_group;" ::: "memory")

// ============================================================================
// Mask compaction: per batch, exclusive scan; emits compact->source map.
// ============================================================================
__global__ void compact_mask(const int* __restrict__ mask) {
    __shared__ int ssum[1024];
    const int b = blockIdx.x, t = threadIdx.x;
    const int* mb = mask + b * SEQ;
    const int m0 = mb[2 * t] != 0, m1 = mb[2 * t + 1] != 0;
    ssum[t] = m0 + m1;
    __syncthreads();
    for (int off = 1; off < 1024; off <<= 1) {
        int v = (t >= off) ? ssum[t - off] : 0;
        __syncthreads();
        ssum[t] += v;
        __syncthreads();
    }
    const int excl = (t > 0) ? ssum[t - 1] : 0;
    if (m0) g_inv[b * SEQ + excl]      = 2 * t;
    if (m1) g_inv[b * SEQ + excl + m0] = 2 * t + 1;
    if (t == 1023) g_cnt[b] = ssum[1023];
}

// ============================================================================
// fp32 -> bf16 hi/lo splits (merged launches).
// ============================================================================
__global__ void convert_acts(const float4* __restrict__ q,
                             const float4* __restrict__ k,
                             const float4* __restrict__ v) {
    const int kind = blockIdx.y;
    const float4* src = (kind == 0) ? q : (kind == 1) ? k : v;
    const int i = blockIdx.x * blockDim.x + threadIdx.x;
    __nv_bfloat16* H = g_Xh[kind];
    __nv_bfloat16* L = g_Xl[kind];
    const float4 val = src[i];
    const float h0 = rb(val.x), h1 = rb(val.y), h2 = rb(val.z), h3 = rb(val.w);
    uint2 uh, ul;
    uh.x = pack2(val.x, val.y); uh.y = pack2(val.z, val.w);
    ul.x = pack2(val.x - h0, val.y - h1); ul.y = pack2(val.z - h2, val.w - h3);
    reinterpret_cast<uint2*>(H)[i] = uh;
    reinterpret_cast<uint2*>(L)[i] = ul;
}

__global__ void convert_wts(const float4* __restrict__ wq,
                            const float4* __restrict__ wk,
                            const float4* __restrict__ wv,
                            const float4* __restrict__ wo) {
    const int kind = blockIdx.y;
    const float4* src = (kind == 0) ? wq : (kind == 1) ? wk : (kind == 2) ? wv : wo;
    const int i = blockIdx.x * blockDim.x + threadIdx.x;
    __nv_bfloat16* H = g_Wh[kind];
    __nv_bfloat16* L = g_Wl[kind];
    const float4 val = src[i];
    const float h0 = rb(val.x), h1 = rb(val.y), h2 = rb(val.z), h3 = rb(val.w);
    uint2 uh, ul;
    uh.x = pack2(val.x, val.y); uh.y = pack2(val.z, val.w);
    ul.x = pack2(val.x - h0, val.y - h1); ul.y = pack2(val.z - h2, val.w - h3);
    reinterpret_cast<uint2*>(H)[i] = uh;
    reinterpret_cast<uint2*>(L)[i] = ul;
}

// ============================================================================
// bf16-split tensor-core GEMM with cp.async 2-stage pipeline.
// C = A(M,K) @ W(N,K)^T + bias;  acc += Ah*Bh + Ah*Bl + Al*Bh.
// Tile 128x64, BK=32, 256 thr, warp 32x32.
// MODE 1: full M, -> g_Qh/g_Ql head-split, scaled by QSCALE
// MODE 2/3: COMPACTED M per batch (gather A rows via g_inv) -> g_K*/g_V*
// MODE 0: A = g_Ch/g_Cl, -> Cout fp32 row-major
// Dynamic smem: A stages 2x(hi+lo)x128x40 bf16 = 40960 B at offset 0,
//               B stages 2x(hi+lo)x 64x40 bf16 = 20480 B at offset 40960.
// ============================================================================
#define SA_STRIDE 40
#define GEMM_SMEM 61440

template <int MODE>
__global__ __launch_bounds__(256) void gemm_bs(
    const float* __restrict__ bias,
    float* __restrict__ Cout)
{
    extern __shared__ __align__(16) char dsm[];
    const uint32_t SBASE = smem_u32(dsm);

    const __nv_bfloat16 *Ah, *Al, *Wh, *Wl;
    if      (MODE == 1) { Ah = g_Xh[0]; Al = g_Xl[0]; Wh = g_Wh[0]; Wl = g_Wl[0]; }
    else if (MODE == 2) { Ah = g_Xh[1]; Al = g_Xl[1]; Wh = g_Wh[1]; Wl = g_Wl[1]; }
    else if (MODE == 3) { Ah = g_Xh[2]; Al = g_Xl[2]; Wh = g_Wh[2]; Wl = g_Wl[2]; }
    else                { Ah = g_Ch;    Al = g_Cl;    Wh = g_Wh[3]; Wl = g_Wl[3]; }

    const int tid = threadIdx.x;
    const int wid = tid >> 5;
    const int lid = tid & 31;
    const int bn = blockIdx.x * 64;
    const int wm = (wid >> 1) * 32;
    const int wn = (wid & 1) * 32;

    // ---- M-tile resolution (compacted for K/V) ----
    int bm = 0, bb = 0, tile = 0, cnt = 0;
    if (MODE == 2 || MODE == 3) {
        bb   = blockIdx.y >> 4;
        tile = blockIdx.y & 15;
        cnt  = g_cnt[bb];
        if (tile * 128 >= cnt) return;
    } else {
        bm = blockIdx.y * 128;
    }

    const uint4* A4h = reinterpret_cast<const uint4*>(Ah);
    const uint4* A4l = reinterpret_cast<const uint4*>(Al);
    const uint4* W4h = reinterpret_cast<const uint4*>(Wh);
    const uint4* W4l = reinterpret_cast<const uint4*>(Wl);

    // ---- per-thread load descriptors (row gather computed once) ----
    const int lr0 = tid >> 2;          // 0..63
    const int lq  = tid & 3;           // 16B slot within 64B row
    size_t aoff0, aoff1, boff;
    if (MODE == 2 || MODE == 3) {
        int p0 = tile * 128 + lr0;
        int p1 = p0 + 64;
        int s0 = (p0 < cnt) ? g_inv[bb * SEQ + p0] : 0;
        int s1 = (p1 < cnt) ? g_inv[bb * SEQ + p1] : 0;
        aoff0 = ((size_t)(bb * SEQ + s0)) * 128 + lq;
        aoff1 = ((size_t)(bb * SEQ + s1)) * 128 + lq;
    } else {
        aoff0 = (size_t)(bm + lr0) * 128 + lq;
        aoff1 = aoff0 + (size_t)64 * 128;
    }
    boff = (size_t)(bn + lr0) * 128 + lq;

    const uint32_t dA0 = (uint32_t)(lr0 * SA_STRIDE + lq * 8) * 2;
    const uint32_t dA1 = dA0 + (uint32_t)64 * SA_STRIDE * 2;
    const uint32_t dB  = dA0;

    // stage bases
    auto stage_load = [&](int ch, int st) {
        const uint32_t a_h = SBASE + st * 20480;
        const uint32_t a_l = a_h + 10240;
        const uint32_t b_h = SBASE + 40960 + st * 10240;
        const uint32_t b_l = b_h + 5120;
        cp16(a_h + dA0, A4h + aoff0 + ch * 4);
        cp16(a_h + dA1, A4h + aoff1 + ch * 4);
        cp16(a_l + dA0, A4l + aoff0 + ch * 4);
        cp16(a_l + dA1, A4l + aoff1 + ch * 4);
        cp16(b_h + dB,  W4h + boff + ch * 4);
        cp16(b_l + dB,  W4l + boff + ch * 4);
    };

    // ---- ldmatrix lane addressing ----
    const int a_row = wm + ((lid >> 3) & 1) * 8 + (lid & 7);
    const uint32_t a_koff = ((lid >> 4) * 8) * 2;
    const int b_row = wn + ((lid >> 4) & 1) * 8 + (lid & 7);
    const uint32_t b_koff = (((lid >> 3) & 1) * 8) * 2;

    float acc[2][4][4];
    #pragma unroll
    for (int i = 0; i < 2; i++)
        #pragma unroll
        for (int j = 0; j < 4; j++)
            #pragma unroll
            for (int r = 0; r < 4; r++) acc[i][j][r] = 0.f;

    // ---- pipeline prologue ----
    stage_load(0, 0); CP_COMMIT();
    stage_load(1, 1); CP_COMMIT();

    for (int ch = 0; ch < 32; ch++) {
        const int st = ch & 1;
        if (ch < 31) asm volatile("cp.async.wait_group 1;" ::: "memory");
        else         asm volatile("cp.async.wait_group 0;" ::: "memory");
        __syncthreads();

        const uint32_t sAh_base = SBASE + st * 20480;
        const uint32_t sAl_base = sAh_base + 10240;
        const uint32_t sBh_base = SBASE + 40960 + st * 10240;
        const uint32_t sBl_base = sBh_base + 5120;

        #pragma unroll
        for (int ks = 0; ks < 2; ks++) {
            const uint32_t kbyte = ks * 32;
            uint32_t ah[2][4], al[2][4], bh[4][2], bl[4][2];
            #pragma unroll
            for (int mi = 0; mi < 2; mi++) {
                uint32_t ad = sAh_base + (uint32_t)(a_row + mi * 16) * (SA_STRIDE * 2) + kbyte + a_koff;
                ldsm_x4(ah[mi][0], ah[mi][1], ah[mi][2], ah[mi][3], ad);
                uint32_t ad2 = sAl_base + (uint32_t)(a_row + mi * 16) * (SA_STRIDE * 2) + kbyte + a_koff;
                ldsm_x4(al[mi][0], al[mi][1], al[mi][2], al[mi][3], ad2);
            }
            #pragma unroll
            for (int p = 0; p < 2; p++) {
                uint32_t r0, r1, r2, r3;
                uint32_t bd = sBh_base + (uint32_t)(b_row + p * 16) * (SA_STRIDE * 2) + kbyte + b_koff;
                ldsm_x4(r0, r1, r2, r3, bd);
                bh[p * 2][0] = r0; bh[p * 2][1] = r1;
                bh[p * 2 + 1][0] = r2; bh[p * 2 + 1][1] = r3;
                uint32_t bd2 = sBl_base + (uint32_t)(b_row + p * 16) * (SA_STRIDE * 2) + kbyte + b_koff;
                ldsm_x4(r0, r1, r2, r3, bd2);
                bl[p * 2][0] = r0; bl[p * 2][1] = r1;
                bl[p * 2 + 1][0] = r2; bl[p * 2 + 1][1] = r3;
            }
            #pragma unroll
            for (int mi = 0; mi < 2; mi++)
                #pragma unroll
                for (int nj = 0; nj < 4; nj++) {
                    float* c = acc[mi][nj];
                    mma_bf16(c, ah[mi], bh[nj][0], bh[nj][1]);
                    mma_bf16(c, ah[mi], bl[nj][0], bl[nj][1]);
                    mma_bf16(c, al[mi], bh[nj][0], bh[nj][1]);
                }
        }
        __syncthreads();
        if (ch + 2 < 32) { stage_load(ch + 2, st); CP_COMMIT(); }
    }

    // ---- epilogue ----
    const int fr = lid >> 2;
    const int fc = (lid & 3) * 2;

    #pragma unroll
    for (int mi = 0; mi < 2; mi++)
        #pragma unroll
        for (int nj = 0; nj < 4; nj++) {
            int n = bn + wn + nj * 8 + fc;
            float2 bv = *reinterpret_cast<const float2*>(bias + n);
            #pragma unroll
            for (int half = 0; half < 2; half++) {
                float ox = acc[mi][nj][half * 2 + 0] + bv.x;
                float oy = acc[mi][nj][half * 2 + 1] + bv.y;
                if (MODE == 0) {
                    int m = bm + wm + mi * 16 + fr + half * 8;
                    float2 o; o.x = ox; o.y = oy;
                    *reinterpret_cast<float2*>(Cout + (size_t)m * DMODEL + n) = o;
                } else if (MODE == 1) {
                    int m = bm + wm + mi * 16 + fr + half * 8;
                    int b  = m >> 11;
                    int s  = m & (SEQ - 1);
                    int hh = n >> 6;
                    int dh = n & (HDIM - 1);
                    ox *= QSCALE; oy *= QSCALE;
                    size_t off = (((size_t)(b * NHEADS + hh)) * SEQ + s) * HDIM + dh;
                    float hx = rb(ox), hy = rb(oy);
                    *reinterpret_cast<uint32_t*>(g_Qh + off) = pack2(ox, oy);
                    *reinterpret_cast<uint32_t*>(g_Ql + off) = pack2(ox - hx, oy - hy);
                } else {
                    int pos = tile * 128 + wm + mi * 16 + fr + half * 8;
                    if (pos < cnt) {
                        int hh = n >> 6;
                        int dh = n & (HDIM - 1);
                        size_t off = (((size_t)(bb * NHEADS + hh)) * SEQ + pos) * HDIM + dh;
                        float hx = rb(ox), hy = rb(oy);
                        if (MODE == 2) {
                            *reinterpret_cast<uint32_t*>(g_Kh + off) = pack2(ox, oy);
                            *reinterpret_cast<uint32_t*>(g_Kl + off) = pack2(ox - hx, oy - hy);
                        } else {
                            *reinterpret_cast<uint32_t*>(g_Vh + off) = pack2(ox, oy);
                            *reinterpret_cast<uint32_t*>(g_Vl + off) = pack2(ox - hx, oy - hy);
                        }
                    }
                }
            }
        }
}

// ============================================================================
// Tensor-core flash attention over COMPACTED keys (unchanged from round 8).
// ============================================================================
__global__ __launch_bounds__(256) void attn_mma()
{
    __shared__ __align__(16) __nv_bfloat16 sbuf[4 * 64 * 72];   // 36864 B

    const int tid = threadIdx.x;
    const int wid = tid >> 5;
    const int lid = tid & 31;
    const int hh = blockIdx.y;
    const int b  = blockIdx.z;
    const int qb = blockIdx.x * 128;
    const int wq = wid * 16;
    const int cnt = g_cnt[b];

    const size_t hb = ((size_t)(b * NHEADS + hh)) * SEQ * HDIM;
    const uint4* Qh4 = reinterpret_cast<const uint4*>(g_Qh + hb + (size_t)qb * HDIM);
    const uint4* Ql4 = reinterpret_cast<const uint4*>(g_Ql + hb + (size_t)qb * HDIM);
    const uint4* Kh4 = reinterpret_cast<const uint4*>(g_Kh + hb);
    const uint4* Kl4 = reinterpret_cast<const uint4*>(g_Kl + hb);
    const uint4* Vh4 = reinterpret_cast<const uint4*>(g_Vh + hb);
    const uint4* Vl4 = reinterpret_cast<const uint4*>(g_Vl + hb);

    uint4* sb4 = reinterpret_cast<uint4*>(sbuf);
    const uint32_t SB = smem_u32(sbuf);

    #pragma unroll
    for (int j = 0; j < 4; j++) {
        int idx = tid + 256 * j;
        int r = idx >> 3, q = idx & 7;
        sb4[9 * r + q]        = Qh4[r * 8 + q];
        sb4[1152 + 9 * r + q] = Ql4[r * 8 + q];
    }
    __syncthreads();

    uint32_t qfh[4][4], qfl[4][4];
    {
        const int arow = wq + (lid & 7) + ((lid >> 3) & 1) * 8;
        const int akoff = (lid >> 4) * 8;
        #pragma unroll
        for (int ks = 0; ks < 4; ks++) {
            uint32_t ad = SB + (uint32_t)(arow * 72 + ks * 16 + akoff) * 2;
            ldsm_x4(qfh[ks][0], qfh[ks][1], qfh[ks][2], qfh[ks][3], ad);
            ldsm_x4(qfl[ks][0], qfl[ks][1], qfl[ks][2], qfl[ks][3], ad + 18432);
        }
    }
    __syncthreads();

    float oacc[8][4];
    #pragma unroll
    for (int ng = 0; ng < 8; ng++)
        #pragma unroll
        for (int r = 0; r < 4; r++) oacc[ng][r] = 0.f;

    float mrow0 = NEGI, mrow1 = NEGI, lrow0 = 0.f, lrow1 = 0.f;
    const int ntl = (cnt + 63) >> 6;

    const int brow = (lid & 7) + ((lid >> 4) & 1) * 8;
    const int bko  = ((lid >> 3) & 1) * 8;
    const int vrow = lid & 15;
    const int vco  = (lid >> 4) * 8;
    const int fc   = (lid & 3) * 2;

    for (int kt = 0; kt < ntl; kt++) {
        #pragma unroll
        for (int j = 0; j < 2; j++) {
            int idx = tid + 256 * j;
            int r = idx >> 3, q = idx & 7;
            int gi = (kt * 64 + r) * 8 + q;
            sb4[9 * r + q]        = Kh4[gi];
            sb4[576  + 9 * r + q] = Kl4[gi];
            sb4[1152 + 9 * r + q] = Vh4[gi];
            sb4[1728 + 9 * r + q] = Vl4[gi];
        }
        __syncthreads();

        float sacc[8][4];
        #pragma unroll
        for (int nt = 0; nt < 8; nt++)
            #pragma unroll
            for (int r = 0; r < 4; r++) sacc[nt][r] = 0.f;

        #pragma unroll
        for (int ks = 0; ks < 4; ks++) {
            uint32_t kh[8][2], kl[8][2];
            #pragma unroll
            for (int p = 0; p < 4; p++) {
                uint32_t r0, r1, r2, r3;
                uint32_t ad = SB + (uint32_t)((p * 16 + brow) * 72 + ks * 16 + bko) * 2;
                ldsm_x4(r0, r1, r2, r3, ad);
                kh[p * 2][0] = r0; kh[p * 2][1] = r1;
                kh[p * 2 + 1][0] = r2; kh[p * 2 + 1][1] = r3;
                ldsm_x4(r0, r1, r2, r3, ad + 9216);
                kl[p * 2][0] = r0; kl[p * 2][1] = r1;
                kl[p * 2 + 1][0] = r2; kl[p * 2 + 1][1] = r3;
            }
            #pragma unroll
            for (int nt = 0; nt < 8; nt++) {
                mma_bf16(sacc[nt], qfh[ks], kh[nt][0], kh[nt][1]);
                mma_bf16(sacc[nt], qfh[ks], kl[nt][0], kl[nt][1]);
                mma_bf16(sacc[nt], qfl[ks], kh[nt][0], kh[nt][1]);
            }
        }

        const int key0 = kt * 64 + fc;
        float tm0 = NEGI, tm1 = NEGI;
        #pragma unroll
        for (int nt = 0; nt < 8; nt++) {
            bool v0 = (key0 + nt * 8) < cnt;
            bool v1 = (key0 + nt * 8 + 1) < cnt;
            if (!v0) { sacc[nt][0] = NEGI; sacc[nt][2] = NEGI; }
            if (!v1) { sacc[nt][1] = NEGI; sacc[nt][3] = NEGI; }
            tm0 = fmaxf(tm0, fmaxf(sacc[nt][0], sacc[nt][1]));
            tm1 = fmaxf(tm1, fmaxf(sacc[nt][2], sacc[nt][3]));
        }
        tm0 = fmaxf(tm0, __shfl_xor_sync(0xffffffffu, tm0, 1));
        tm0 = fmaxf(tm0, __shfl_xor_sync(0xffffffffu, tm0, 2));
        tm1 = fmaxf(tm1, __shfl_xor_sync(0xffffffffu, tm1, 1));
        tm1 = fmaxf(tm1, __shfl_xor_sync(0xffffffffu, tm1, 2));

        const float mn0 = fmaxf(mrow0, tm0), mn1 = fmaxf(mrow1, tm1);
        const float c0 = ex2(mrow0 - mn0), c1 = ex2(mrow1 - mn1);
        mrow0 = mn0; mrow1 = mn1;

        uint32_t pah[4][4], pal[4][4];
        float ls0 = 0.f, ls1 = 0.f;
        #pragma unroll
        for (int nt = 0; nt < 8; nt++) {
            float p0 = ex2(sacc[nt][0] - mn0), p1 = ex2(sacc[nt][1] - mn0);
            float p2 = ex2(sacc[nt][2] - mn1), p3 = ex2(sacc[nt][3] - mn1);
            ls0 += p0 + p1; ls1 += p2 + p3;
            float h0 = rb(p0), h1 = rb(p1), h2 = rb(p2), h3 = rb(p3);
            int kc = nt >> 1, o2 = (nt & 1) * 2;
            pah[kc][o2 + 0] = pack2(p0, p1);
            pah[kc][o2 + 1] = pack2(p2, p3);
            pal[kc][o2 + 0] = pack2(p0 - h0, p1 - h1);
            pal[kc][o2 + 1] = pack2(p2 - h2, p3 - h3);
        }
        lrow0 = lrow0 * c0 + ls0;
        lrow1 = lrow1 * c1 + ls1;
        #pragma unroll
        for (int ng = 0; ng < 8; ng++) {
            oacc[ng][0] *= c0; oacc[ng][1] *= c0;
            oacc[ng][2] *= c1; oacc[ng][3] *= c1;
        }

        #pragma unroll
        for (int kc = 0; kc < 4; kc++) {
            uint32_t vh[8][2], vl[8][2];
            #pragma unroll
            for (int p = 0; p < 4; p++) {
                uint32_t r0, r1, r2, r3;
                uint32_t ad = SB + 18432 + (uint32_t)((kc * 16 + vrow) * 72 + p * 16 + vco) * 2;
                ldsm_x4t(r0, r1, r2, r3, ad);
                vh[p * 2][0] = r0; vh[p * 2][1] = r1;
                vh[p * 2 + 1][0] = r2; vh[p * 2 + 1][1] = r3;
                ldsm_x4t(r0, r1, r2, r3, ad + 9216);
                vl[p * 2][0] = r0; vl[p * 2][1] = r1;
                vl[p * 2 + 1][0] = r2; vl[p * 2 + 1][1] = r3;
            }
            #pragma unroll
            for (int ng = 0; ng < 8; ng++) {
                mma_bf16(oacc[ng], pah[kc], vh[ng][0], vh[ng][1]);
                mma_bf16(oacc[ng], pah[kc], vl[ng][0], vl[ng][1]);
                mma_bf16(oacc[ng], pal[kc], vh[ng][0], vh[ng][1]);
            }
        }
        __syncthreads();
    }

    lrow0 += __shfl_xor_sync(0xffffffffu, lrow0, 1);
    lrow0 += __shfl_xor_sync(0xffffffffu, lrow0, 2);
    lrow1 += __shfl_xor_sync(0xffffffffu, lrow1, 1);
    lrow1 += __shfl_xor_sync(0xffffffffu, lrow1, 2);

    const float inv0 = 1.0f / lrow0;
    const float inv1 = 1.0f / lrow1;
    const int r0 = qb + wq + (lid >> 2);
    const int r1 = r0 + 8;
    #pragma unroll
    for (int ng = 0; ng < 8; ng++) {
        int col = hh * HDIM + ng * 8 + fc;
        float a0 = oacc[ng][0] * inv0, a1 = oacc[ng][1] * inv0;
        float a2 = oacc[ng][2] * inv1, a3 = oacc[ng][3] * inv1;
        size_t off0 = ((size_t)(b * SEQ + r0)) * DMODEL + col;
        size_t off1 = ((size_t)(b * SEQ + r1)) * DMODEL + col;
        float h0 = rb(a0), h1 = rb(a1), h2 = rb(a2), h3 = rb(a3);
        *reinterpret_cast<uint32_t*>(g_Ch + off0) = pack2(a0, a1);
        *reinterpret_cast<uint32_t*>(g_Cl + off0) = pack2(a0 - h0, a1 - h1);
        *reinterpret_cast<uint32_t*>(g_Ch + off1) = pack2(a2, a3);
        *reinterpret_cast<uint32_t*>(g_Cl + off1) = pack2(a2 - h2, a3 - h3);
    }
}

// ============================================================================
// Launch
// ============================================================================
extern "C" void kernel_launch(void* const* d_in, const int* in_sizes, int n_in,
                              void* d_out, int out_size)
{
    const float* query = (const float*)d_in[0];
    const float* key   = (const float*)d_in[1];
    const float* value = (const float*)d_in[2];
    const int*   mask  = (const int*)  d_in[3];
    const float* Wq    = (const float*)d_in[4];
    const float* bq    = (const float*)d_in[5];
    const float* Wk    = (const float*)d_in[6];
    const float* bk    = (const float*)d_in[7];
    const float* Wv    = (const float*)d_in[8];
    const float* bv    = (const float*)d_in[9];
    const float* Wo    = (const float*)d_in[10];
    const float* bo    = (const float*)d_in[11];
    float* out = (float*)d_out;

    static bool attr_done = false;
    if (!attr_done) {
        cudaFuncSetAttribute(gemm_bs<0>, cudaFuncAttributeMaxDynamicSharedMemorySize, GEMM_SMEM);
        cudaFuncSetAttribute(gemm_bs<1>, cudaFuncAttributeMaxDynamicSharedMemorySize, GEMM_SMEM);
        cudaFuncSetAttribute(gemm_bs<2>, cudaFuncAttributeMaxDynamicSharedMemorySize, GEMM_SMEM);
        cudaFuncSetAttribute(gemm_bs<3>, cudaFuncAttributeMaxDynamicSharedMemorySize, GEMM_SMEM);
        attr_done = true;
    }

    const int nx4 = MTOT * DMODEL / 4;
    const int nw4 = DMODEL * DMODEL / 4;

    compact_mask<<<BATCH, 1024>>>(mask);
    convert_acts<<<dim3(nx4 / 256, 3), 256>>>((const float4*)query,
                                              (const float4*)key,
                                              (const float4*)value);
    convert_wts<<<dim3(nw4 / 256, 4), 256>>>((const float4*)Wq, (const float4*)Wk,
                                             (const float4*)Wv, (const float4*)Wo);

    dim3 gemmGrid(DMODEL / 64, MTOT / 128);   // (16, 64)
    gemm_bs<1><<<gemmGrid, 256, GEMM_SMEM>>>(bq, nullptr);
    gemm_bs<2><<<gemmGrid, 256, GEMM_SMEM>>>(bk, nullptr);  // y = b*16+tile, early exit
    gemm_bs<3><<<gemmGrid, 256, GEMM_SMEM>>>(bv, nullptr);

    dim3 attnGrid(SEQ / 128, NHEADS, BATCH);  // (16, 16, 4)
    attn_mma<<<attnGrid, 256>>>();

    gemm_bs<0><<<gemmGrid, 256, GEMM_SMEM>>>(bo, out);
}

// round 10
// speedup vs baseline: 4.1154x; 1.0047x over previous
#include <cuda_runtime.h>
#include <cuda_bf16.h>
#include <cstdint>

#define BATCH  4
#define SEQ    2048
#define DMODEL 1024
#define NHEADS 16
#define HDIM   64
#define MTOT   (BATCH * SEQ)          // 8192
#define QSCALE 0.1803368801111204f   // 1/sqrt(HDIM) * log2(e)
#define NEGI   -1e30f

// ---- scratch (device globals; no allocation) ----
__device__ __nv_bfloat16 g_Xh[3][MTOT * DMODEL];
__device__ __nv_bfloat16 g_Xl[3][MTOT * DMODEL];
__device__ __nv_bfloat16 g_Wh[4][DMODEL * DMODEL];
__device__ __nv_bfloat16 g_Wl[4][DMODEL * DMODEL];
__device__ __nv_bfloat16 g_Qh[MTOT * DMODEL], g_Ql[MTOT * DMODEL]; // (B,H,S,Dh), scaled
__device__ __nv_bfloat16 g_Kh[MTOT * DMODEL], g_Kl[MTOT * DMODEL]; // compacted
__device__ __nv_bfloat16 g_Vh[MTOT * DMODEL], g_Vl[MTOT * DMODEL]; // compacted
__device__ __nv_bfloat16 g_Ch[MTOT * DMODEL], g_Cl[MTOT * DMODEL]; // ctx (B,S,D)
__device__ int g_inv[BATCH * SEQ];   // compact pos -> source row
__device__ int g_cnt[BATCH];

// ============================================================================
// Helpers
// ============================================================================
__device__ __forceinline__ uint32_t smem_u32(const void* p) {
    uint32_t a;
    asm("{ .reg .u64 t; cvta.to.shared.u64 t, %1; cvt.u32.u64 %0, t; }"
        : "=r"(a) : "l"(p));
    return a;
}

__device__ __forceinline__ void ldsm_x4(uint32_t& r0, uint32_t& r1,
                                        uint32_t& r2, uint32_t& r3, uint32_t addr) {
    asm volatile("ldmatrix.sync.aligned.m8n8.x4.shared.b16 {%0,%1,%2,%3}, [%4];"
                 : "=r"(r0), "=r"(r1), "=r"(r2), "=r"(r3) : "r"(addr));
}

__device__ __forceinline__ void ldsm_x4t(uint32_t& r0, uint32_t& r1,
                                         uint32_t& r2, uint32_t& r3, uint32_t addr) {
    asm volatile("ldmatrix.sync.aligned.m8n8.x4.trans.shared.b16 {%0,%1,%2,%3}, [%4];"
                 : "=r"(r0), "=r"(r1), "=r"(r2), "=r"(r3) : "r"(addr));
}

__device__ __forceinline__ void mma_bf16(float* c,
                                         const uint32_t* a,
                                         uint32_t b0, uint32_t b1) {
    asm volatile(
        "mma.sync.aligned.m16n8k16.row.col.f32.bf16.bf16.f32 "
        "{%0,%1,%2,%3}, {%4,%5,%6,%7}, {%8,%9}, {%0,%1,%2,%3};"
        : "+f"(c[0]), "+f"(c[1]), "+f"(c[2]), "+f"(c[3])
        : "r"(a[0]), "r"(a[1]), "r"(a[2]), "r"(a[3]), "r"(b0), "r"(b1));
}

__device__ __forceinline__ uint32_t pack2(float x, float y) {
    __nv_bfloat162 t = __floats2bfloat162_rn(x, y);
    return *reinterpret_cast<uint32_t*>(&t);
}
__device__ __forceinline__ float rb(float x) {
    return __bfloat162float(__float2bfloat16(x));
}
__device__ __forceinline__ float ex2(float x) {
    float r;
    asm("ex2.approx.f32 %0, %1;" : "=f"(r) : "f"(x));
    return r;
}
__device__ __forceinline__ void cp16(uint32_t dst, const void* src) {
    asm volatile("cp.async.cg.shared.global [%0], [%1], 16;" :: "r"(dst), "l"(src));
}
#define CP_COMMIT() asm volatile("cp.async.commit_group;" ::: "memory")
#define CP_WAIT1()  asm volatile("cp.async.wait_group 1;" ::: "memory")
#define CP_WAIT0()  asm volatile("cp.async.wait_group 0;" ::: "memory")

// ============================================================================
// Mask compaction
// ============================================================================
__global__ void compact_mask(const int* __restrict__ mask) {
    __shared__ int ssum[1024];
    const int b = blockIdx.x, t = threadIdx.x;
    const int* mb = mask + b * SEQ;
    const int m0 = mb[2 * t] != 0, m1 = mb[2 * t + 1] != 0;
    ssum[t] = m0 + m1;
    __syncthreads();
    for (int off = 1; off < 1024; off <<= 1) {
        int v = (t >= off) ? ssum[t - off] : 0;
        __syncthreads();
        ssum[t] += v;
        __syncthreads();
    }
    const int excl = (t > 0) ? ssum[t - 1] : 0;
    if (m0) g_inv[b * SEQ + excl]      = 2 * t;
    if (m1) g_inv[b * SEQ + excl + m0] = 2 * t + 1;
    if (t == 1023) g_cnt[b] = ssum[1023];
}

// ============================================================================
// fp32 -> bf16 hi/lo splits
// ============================================================================
__global__ void convert_acts(const float4* __restrict__ q,
                             const float4* __restrict__ k,
                             const float4* __restrict__ v) {
    const int kind = blockIdx.y;
    const float4* src = (kind == 0) ? q : (kind == 1) ? k : v;
    const int i = blockIdx.x * blockDim.x + threadIdx.x;
    __nv_bfloat16* H = g_Xh[kind];
    __nv_bfloat16* L = g_Xl[kind];
    const float4 val = src[i];
    const float h0 = rb(val.x), h1 = rb(val.y), h2 = rb(val.z), h3 = rb(val.w);
    uint2 uh, ul;
    uh.x = pack2(val.x, val.y); uh.y = pack2(val.z, val.w);
    ul.x = pack2(val.x - h0, val.y - h1); ul.y = pack2(val.z - h2, val.w - h3);
    reinterpret_cast<uint2*>(H)[i] = uh;
    reinterpret_cast<uint2*>(L)[i] = ul;
}

__global__ void convert_wts(const float4* __restrict__ wq,
                            const float4* __restrict__ wk,
                            const float4* __restrict__ wv,
                            const float4* __restrict__ wo) {
    const int kind = blockIdx.y;
    const float4* src = (kind == 0) ? wq : (kind == 1) ? wk : (kind == 2) ? wv : wo;
    const int i = blockIdx.x * blockDim.x + threadIdx.x;
    __nv_bfloat16* H = g_Wh[kind];
    __nv_bfloat16* L = g_Wl[kind];
    const float4 val = src[i];
    const float h0 = rb(val.x), h1 = rb(val.y), h2 = rb(val.z), h3 = rb(val.w);
    uint2 uh, ul;
    uh.x = pack2(val.x, val.y); uh.y = pack2(val.z, val.w);
    ul.x = pack2(val.x - h0, val.y - h1); ul.y = pack2(val.z - h2, val.w - h3);
    reinterpret_cast<uint2*>(H)[i] = uh;
    reinterpret_cast<uint2*>(L)[i] = ul;
}

// ============================================================================
// bf16-split tensor-core GEMM, 3-stage cp.async pipeline, ONE sync per chunk.
// C = A(M,K) @ W(N,K)^T + bias;  acc += Ah*Bh + Ah*Bl + Al*Bh.
// Tile 128x64, BK=32, 256 thr, warp 32x32.
// Stage layout (30720 B each, 3 stages = 92160 B):
//   +0 Ah(10240) +10240 Al(10240) +20480 Bh(5120) +25600 Bl(5120)
// ============================================================================
#define SA_STRIDE 40
#define GSTAGE    30720
#define GEMM_SMEM (3 * GSTAGE)

template <int MODE>
__global__ __launch_bounds__(256) void gemm_bs(
    const float* __restrict__ bias,
    float* __restrict__ Cout)
{
    extern __shared__ __align__(16) char dsm[];
    const uint32_t SBASE = smem_u32(dsm);

    const __nv_bfloat16 *Ah, *Al, *Wh, *Wl;
    if      (MODE == 1) { Ah = g_Xh[0]; Al = g_Xl[0]; Wh = g_Wh[0]; Wl = g_Wl[0]; }
    else if (MODE == 2) { Ah = g_Xh[1]; Al = g_Xl[1]; Wh = g_Wh[1]; Wl = g_Wl[1]; }
    else if (MODE == 3) { Ah = g_Xh[2]; Al = g_Xl[2]; Wh = g_Wh[2]; Wl = g_Wl[2]; }
    else                { Ah = g_Ch;    Al = g_Cl;    Wh = g_Wh[3]; Wl = g_Wl[3]; }

    const int tid = threadIdx.x;
    const int wid = tid >> 5;
    const int lid = tid & 31;
    const int bn = blockIdx.x * 64;
    const int wm = (wid >> 1) * 32;
    const int wn = (wid & 1) * 32;

    int bm = 0, bb = 0, tile = 0, cnt = 0;
    if (MODE == 2 || MODE == 3) {
        bb   = blockIdx.y >> 4;
        tile = blockIdx.y & 15;
        cnt  = g_cnt[bb];
        if (tile * 128 >= cnt) return;
    } else {
        bm = blockIdx.y * 128;
    }

    const uint4* A4h = reinterpret_cast<const uint4*>(Ah);
    const uint4* A4l = reinterpret_cast<const uint4*>(Al);
    const uint4* W4h = reinterpret_cast<const uint4*>(Wh);
    const uint4* W4l = reinterpret_cast<const uint4*>(Wl);

    const int lr0 = tid >> 2;          // 0..63
    const int lq  = tid & 3;           // 16B slot within 64B chunk-row
    size_t aoff0, aoff1, boff;
    if (MODE == 2 || MODE == 3) {
        int p0 = tile * 128 + lr0;
        int p1 = p0 + 64;
        int s0 = (p0 < cnt) ? g_inv[bb * SEQ + p0] : 0;
        int s1 = (p1 < cnt) ? g_inv[bb * SEQ + p1] : 0;
        aoff0 = ((size_t)(bb * SEQ + s0)) * 128 + lq;
        aoff1 = ((size_t)(bb * SEQ + s1)) * 128 + lq;
    } else {
        aoff0 = (size_t)(bm + lr0) * 128 + lq;
        aoff1 = aoff0 + (size_t)64 * 128;
    }
    boff = (size_t)(bn + lr0) * 128 + lq;

    const uint32_t dA0 = (uint32_t)(lr0 * SA_STRIDE + lq * 8) * 2;
    const uint32_t dA1 = dA0 + (uint32_t)64 * SA_STRIDE * 2;
    const uint32_t dB  = dA0;

    auto stage_load = [&](int ch, int st) {
        const uint32_t a_h = SBASE + st * GSTAGE;
        const uint32_t a_l = a_h + 10240;
        const uint32_t b_h = a_h + 20480;
        const uint32_t b_l = a_h + 25600;
        cp16(a_h + dA0, A4h + aoff0 + ch * 4);
        cp16(a_h + dA1, A4h + aoff1 + ch * 4);
        cp16(a_l + dA0, A4l + aoff0 + ch * 4);
        cp16(a_l + dA1, A4l + aoff1 + ch * 4);
        cp16(b_h + dB,  W4h + boff + ch * 4);
        cp16(b_l + dB,  W4l + boff + ch * 4);
    };

    const int a_row = wm + ((lid >> 3) & 1) * 8 + (lid & 7);
    const uint32_t a_koff = ((lid >> 4) * 8) * 2;
    const int b_row = wn + ((lid >> 4) & 1) * 8 + (lid & 7);
    const uint32_t b_koff = (((lid >> 3) & 1) * 8) * 2;

    float acc[2][4][4];
    #pragma unroll
    for (int i = 0; i < 2; i++)
        #pragma unroll
        for (int j = 0; j < 4; j++)
            #pragma unroll
            for (int r = 0; r < 4; r++) acc[i][j][r] = 0.f;

    stage_load(0, 0); CP_COMMIT();
    stage_load(1, 1); CP_COMMIT();

    int st = 0;
    for (int ch = 0; ch < 32; ch++) {
        if (ch < 31) CP_WAIT1(); else CP_WAIT0();
        __syncthreads();
        // all warps are past mma(ch-1), so stage (ch+2)%3 == (ch-1)%3 is free
        if (ch + 2 < 32) {
            int st2 = st + 2; if (st2 >= 3) st2 -= 3;
            stage_load(ch + 2, st2); CP_COMMIT();
        }

        const uint32_t sAh_base = SBASE + st * GSTAGE;
        const uint32_t sAl_base = sAh_base + 10240;
        const uint32_t sBh_base = sAh_base + 20480;
        const uint32_t sBl_base = sAh_base + 25600;

        #pragma unroll
        for (int ks = 0; ks < 2; ks++) {
            const uint32_t kbyte = ks * 32;
            uint32_t ah[2][4], al[2][4], bh[4][2], bl[4][2];
            #pragma unroll
            for (int mi = 0; mi < 2; mi++) {
                uint32_t ad = sAh_base + (uint32_t)(a_row + mi * 16) * (SA_STRIDE * 2) + kbyte + a_koff;
                ldsm_x4(ah[mi][0], ah[mi][1], ah[mi][2], ah[mi][3], ad);
                uint32_t ad2 = sAl_base + (uint32_t)(a_row + mi * 16) * (SA_STRIDE * 2) + kbyte + a_koff;
                ldsm_x4(al[mi][0], al[mi][1], al[mi][2], al[mi][3], ad2);
            }
            #pragma unroll
            for (int p = 0; p < 2; p++) {
                uint32_t r0, r1, r2, r3;
                uint32_t bd = sBh_base + (uint32_t)(b_row + p * 16) * (SA_STRIDE * 2) + kbyte + b_koff;
                ldsm_x4(r0, r1, r2, r3, bd);
                bh[p * 2][0] = r0; bh[p * 2][1] = r1;
                bh[p * 2 + 1][0] = r2; bh[p * 2 + 1][1] = r3;
                uint32_t bd2 = sBl_base + (uint32_t)(b_row + p * 16) * (SA_STRIDE * 2) + kbyte + b_koff;
                ldsm_x4(r0, r1, r2, r3, bd2);
                bl[p * 2][0] = r0; bl[p * 2][1] = r1;
                bl[p * 2 + 1][0] = r2; bl[p * 2 + 1][1] = r3;
            }
            #pragma unroll
            for (int mi = 0; mi < 2; mi++)
                #pragma unroll
                for (int nj = 0; nj < 4; nj++) {
                    float* c = acc[mi][nj];
                    mma_bf16(c, ah[mi], bh[nj][0], bh[nj][1]);
                    mma_bf16(c, ah[mi], bl[nj][0], bl[nj][1]);
                    mma_bf16(c, al[mi], bh[nj][0], bh[nj][1]);
                }
        }
        if (++st == 3) st = 0;
    }

    // ---- epilogue ----
    const int fr = lid >> 2;
    const int fc = (lid & 3) * 2;

    #pragma unroll
    for (int mi = 0; mi < 2; mi++)
        #pragma unroll
        for (int nj = 0; nj < 4; nj++) {
            int n = bn + wn + nj * 8 + fc;
            float2 bv = *reinterpret_cast<const float2*>(bias + n);
            #pragma unroll
            for (int half = 0; half < 2; half++) {
                float ox = acc[mi][nj][half * 2 + 0] + bv.x;
                float oy = acc[mi][nj][half * 2 + 1] + bv.y;
                if (MODE == 0) {
                    int m = bm + wm + mi * 16 + fr + half * 8;
                    float2 o; o.x = ox; o.y = oy;
                    *reinterpret_cast<float2*>(Cout + (size_t)m * DMODEL + n) = o;
                } else if (MODE == 1) {
                    int m = bm + wm + mi * 16 + fr + half * 8;
                    int b  = m >> 11;
                    int s  = m & (SEQ - 1);
                    int hh = n >> 6;
                    int dh = n & (HDIM - 1);
                    ox *= QSCALE; oy *= QSCALE;
                    size_t off = (((size_t)(b * NHEADS + hh)) * SEQ + s) * HDIM + dh;
                    float hx = rb(ox), hy = rb(oy);
                    *reinterpret_cast<uint32_t*>(g_Qh + off) = pack2(ox, oy);
                    *reinterpret_cast<uint32_t*>(g_Ql + off) = pack2(ox - hx, oy - hy);
                } else {
                    int pos = tile * 128 + wm + mi * 16 + fr + half * 8;
                    if (pos < cnt) {
                        int hh = n >> 6;
                        int dh = n & (HDIM - 1);
                        size_t off = (((size_t)(bb * NHEADS + hh)) * SEQ + pos) * HDIM + dh;
                        float hx = rb(ox), hy = rb(oy);
                        if (MODE == 2) {
                            *reinterpret_cast<uint32_t*>(g_Kh + off) = pack2(ox, oy);
                            *reinterpret_cast<uint32_t*>(g_Kl + off) = pack2(ox - hx, oy - hy);
                        } else {
                            *reinterpret_cast<uint32_t*>(g_Vh + off) = pack2(ox, oy);
                            *reinterpret_cast<uint32_t*>(g_Vl + off) = pack2(ox - hx, oy - hy);
                        }
                    }
                }
            }
        }
}

// ============================================================================
// Tensor-core flash attention, 3-stage cp.async K/V pipeline, ONE sync/tile.
// Stage layout (36864 B each, 3 stages = 110592 B dynamic smem):
//   +0 Kh(9216) +9216 Kl +18432 Vh +27648 Vl    (rows: 72-elem stride)
// Q staged through stage 0 before the pipeline starts.
// ============================================================================
#define ASTAGE    36864
#define ATTN_SMEM (3 * ASTAGE)

__global__ __launch_bounds__(256) void attn_mma()
{
    extern __shared__ __align__(16) char dsm[];
    const uint32_t SB = smem_u32(dsm);

    const int tid = threadIdx.x;
    const int wid = tid >> 5;
    const int lid = tid & 31;
    const int hh = blockIdx.y;
    const int b  = blockIdx.z;
    const int qb = blockIdx.x * 128;
    const int wq = wid * 16;
    const int cnt = g_cnt[b];

    const size_t hb = ((size_t)(b * NHEADS + hh)) * SEQ * HDIM;
    const uint4* Qh4 = reinterpret_cast<const uint4*>(g_Qh + hb + (size_t)qb * HDIM);
    const uint4* Ql4 = reinterpret_cast<const uint4*>(g_Ql + hb + (size_t)qb * HDIM);
    const uint4* Kh4 = reinterpret_cast<const uint4*>(g_Kh + hb);
    const uint4* Kl4 = reinterpret_cast<const uint4*>(g_Kl + hb);
    const uint4* Vh4 = reinterpret_cast<const uint4*>(g_Vh + hb);
    const uint4* Vl4 = reinterpret_cast<const uint4*>(g_Vl + hb);

    // ---- stage Q (128x64 hi/lo) through stage 0, extract fragments ----
    uint4* sb4 = reinterpret_cast<uint4*>(dsm);
    #pragma unroll
    for (int j = 0; j < 4; j++) {
        int idx = tid + 256 * j;              // 0..1023
        int r = idx >> 3, q = idx & 7;
        sb4[9 * r + q]        = Qh4[r * 8 + q];
        sb4[1152 + 9 * r + q] = Ql4[r * 8 + q];
    }
    __syncthreads();

    uint32_t qfh[4][4], qfl[4][4];
    {
        const int arow = wq + (lid & 7) + ((lid >> 3) & 1) * 8;
        const int akoff = (lid >> 4) * 8;
        #pragma unroll
        for (int ks = 0; ks < 4; ks++) {
            uint32_t ad = SB + (uint32_t)(arow * 72 + ks * 16 + akoff) * 2;
            ldsm_x4(qfh[ks][0], qfh[ks][1], qfh[ks][2], qfh[ks][3], ad);
            ldsm_x4(qfl[ks][0], qfl[ks][1], qfl[ks][2], qfl[ks][3], ad + 18432);
        }
    }
    __syncthreads();

    // ---- per-thread cp.async tile-load descriptors ----
    // 512 chunks (16B) per array; thread does 2 per array.
    const int lr = tid >> 2;                 // unused placeholder (kept regs low)
    (void)lr;
    const int ntl = (cnt + 63) >> 6;

    auto load_tile = [&](int kt, int st) {
        const uint32_t base = SB + st * ASTAGE;
        #pragma unroll
        for (int j = 0; j < 2; j++) {
            int idx = tid + 256 * j;          // 0..511
            int r = idx >> 3, q = idx & 7;
            uint32_t so = base + (uint32_t)(r * 144 + q * 16);
            int gi = (kt * 64 + r) * 8 + q;
            cp16(so,         Kh4 + gi);
            cp16(so + 9216,  Kl4 + gi);
            cp16(so + 18432, Vh4 + gi);
            cp16(so + 27648, Vl4 + gi);
        }
    };

    float oacc[8][4];
    #pragma unroll
    for (int ng = 0; ng < 8; ng++)
        #pragma unroll
        for (int r = 0; r < 4; r++) oacc[ng][r] = 0.f;

    float mrow0 = NEGI, mrow1 = NEGI, lrow0 = 0.f, lrow1 = 0.f;

    const int brow = (lid & 7) + ((lid >> 4) & 1) * 8;
    const int bko  = ((lid >> 3) & 1) * 8;
    const int vrow = lid & 15;
    const int vco  = (lid >> 4) * 8;
    const int fc   = (lid & 3) * 2;

    load_tile(0, 0); CP_COMMIT();
    if (ntl > 1) { load_tile(1, 1); CP_COMMIT(); }

    int st = 0;
    for (int kt = 0; kt < ntl; kt++) {
        if (kt + 1 < ntl) CP_WAIT1(); else CP_WAIT0();
        __syncthreads();
        if (kt + 2 < ntl) {
            int st2 = st + 2; if (st2 >= 3) st2 -= 3;
            load_tile(kt + 2, st2); CP_COMMIT();
        }
        const uint32_t SBS = SB + st * ASTAGE;

        // ---- scores: S = Q K^T (3-term) ----
        float sacc[8][4];
        #pragma unroll
        for (int nt = 0; nt < 8; nt++)
            #pragma unroll
            for (int r = 0; r < 4; r++) sacc[nt][r] = 0.f;

        #pragma unroll
        for (int ks = 0; ks < 4; ks++) {
            uint32_t kh[8][2], kl[8][2];
            #pragma unroll
            for (int p = 0; p < 4; p++) {
                uint32_t r0, r1, r2, r3;
                uint32_t ad = SBS + (uint32_t)((p * 16 + brow) * 72 + ks * 16 + bko) * 2;
                ldsm_x4(r0, r1, r2, r3, ad);
                kh[p * 2][0] = r0; kh[p * 2][1] = r1;
                kh[p * 2 + 1][0] = r2; kh[p * 2 + 1][1] = r3;
                ldsm_x4(r0, r1, r2, r3, ad + 9216);
                kl[p * 2][0] = r0; kl[p * 2][1] = r1;
                kl[p * 2 + 1][0] = r2; kl[p * 2 + 1][1] = r3;
            }
            #pragma unroll
            for (int nt = 0; nt < 8; nt++) {
                mma_bf16(sacc[nt], qfh[ks], kh[nt][0], kh[nt][1]);
                mma_bf16(sacc[nt], qfh[ks], kl[nt][0], kl[nt][1]);
                mma_bf16(sacc[nt], qfl[ks], kh[nt][0], kh[nt][1]);
            }
        }

        // ---- tail masking + row max ----
        const int key0 = kt * 64 + fc;
        float tm0 = NEGI, tm1 = NEGI;
        #pragma unroll
        for (int nt = 0; nt < 8; nt++) {
            bool v0 = (key0 + nt * 8) < cnt;
            bool v1 = (key0 + nt * 8 + 1) < cnt;
            if (!v0) { sacc[nt][0] = NEGI; sacc[nt][2] = NEGI; }
            if (!v1) { sacc[nt][1] = NEGI; sacc[nt][3] = NEGI; }
            tm0 = fmaxf(tm0, fmaxf(sacc[nt][0], sacc[nt][1]));
            tm1 = fmaxf(tm1, fmaxf(sacc[nt][2], sacc[nt][3]));
        }
        tm0 = fmaxf(tm0, __shfl_xor_sync(0xffffffffu, tm0, 1));
        tm0 = fmaxf(tm0, __shfl_xor_sync(0xffffffffu, tm0, 2));
        tm1 = fmaxf(tm1, __shfl_xor_sync(0xffffffffu, tm1, 1));
        tm1 = fmaxf(tm1, __shfl_xor_sync(0xffffffffu, tm1, 2));

        const float mn0 = fmaxf(mrow0, tm0), mn1 = fmaxf(mrow1, tm1);
        const float c0 = ex2(mrow0 - mn0), c1 = ex2(mrow1 - mn1);
        mrow0 = mn0; mrow1 = mn1;

        // ---- p = exp2(s - m), split to bf16 hi/lo A-fragments ----
        uint32_t pah[4][4], pal[4][4];
        float ls0 = 0.f, ls1 = 0.f;
        #pragma unroll
        for (int nt = 0; nt < 8; nt++) {
            float p0 = ex2(sacc[nt][0] - mn0), p1 = ex2(sacc[nt][1] - mn0);
            float p2 = ex2(sacc[nt][2] - mn1), p3 = ex2(sacc[nt][3] - mn1);
            ls0 += p0 + p1; ls1 += p2 + p3;
            float h0 = rb(p0), h1 = rb(p1), h2 = rb(p2), h3 = rb(p3);
            int kc = nt >> 1, o2 = (nt & 1) * 2;
            pah[kc][o2 + 0] = pack2(p0, p1);
            pah[kc][o2 + 1] = pack2(p2, p3);
            pal[kc][o2 + 0] = pack2(p0 - h0, p1 - h1);
            pal[kc][o2 + 1] = pack2(p2 - h2, p3 - h3);
        }
        lrow0 = lrow0 * c0 + ls0;
        lrow1 = lrow1 * c1 + ls1;
        #pragma unroll
        for (int ng = 0; ng < 8; ng++) {
            oacc[ng][0] *= c0; oacc[ng][1] *= c0;
            oacc[ng][2] *= c1; oacc[ng][3] *= c1;
        }

        // ---- O += P V (3-term), V fragments via ldmatrix.trans ----
        #pragma unroll
        for (int kc = 0; kc < 4; kc++) {
            uint32_t vh[8][2], vl[8][2];
            #pragma unroll
            for (int p = 0; p < 4; p++) {
                uint32_t r0, r1, r2, r3;
                uint32_t ad = SBS + 18432 + (uint32_t)((kc * 16 + vrow) * 72 + p * 16 + vco) * 2;
                ldsm_x4t(r0, r1, r2, r3, ad);
                vh[p * 2][0] = r0; vh[p * 2][1] = r1;
                vh[p * 2 + 1][0] = r2; vh[p * 2 + 1][1] = r3;
                ldsm_x4t(r0, r1, r2, r3, ad + 9216);
                vl[p * 2][0] = r0; vl[p * 2][1] = r1;
                vl[p * 2 + 1][0] = r2; vl[p * 2 + 1][1] = r3;
            }
            #pragma unroll
            for (int ng = 0; ng < 8; ng++) {
                mma_bf16(oacc[ng], pah[kc], vh[ng][0], vh[ng][1]);
                mma_bf16(oacc[ng], pah[kc], vl[ng][0], vl[ng][1]);
                mma_bf16(oacc[ng], pal[kc], vh[ng][0], vh[ng][1]);
            }
        }
        if (++st == 3) st = 0;
    }

    // ---- reduce softmax denominator across the quad ----
    lrow0 += __shfl_xor_sync(0xffffffffu, lrow0, 1);
    lrow0 += __shfl_xor_sync(0xffffffffu, lrow0, 2);
    lrow1 += __shfl_xor_sync(0xffffffffu, lrow1, 1);
    lrow1 += __shfl_xor_sync(0xffffffffu, lrow1, 2);

    const float inv0 = 1.0f / lrow0;
    const float inv1 = 1.0f / lrow1;
    const int r0 = qb + wq + (lid >> 2);
    const int r1 = r0 + 8;
    #pragma unroll
    for (int ng = 0; ng < 8; ng++) {
        int col = hh * HDIM + ng * 8 + fc;
        float a0 = oacc[ng][0] * inv0, a1 = oacc[ng][1] * inv0;
        float a2 = oacc[ng][2] * inv1, a3 = oacc[ng][3] * inv1;
        size_t off0 = ((size_t)(b * SEQ + r0)) * DMODEL + col;
        size_t off1 = ((size_t)(b * SEQ + r1)) * DMODEL + col;
        float h0 = rb(a0), h1 = rb(a1), h2 = rb(a2), h3 = rb(a3);
        *reinterpret_cast<uint32_t*>(g_Ch + off0) = pack2(a0, a1);
        *reinterpret_cast<uint32_t*>(g_Cl + off0) = pack2(a0 - h0, a1 - h1);
        *reinterpret_cast<uint32_t*>(g_Ch + off1) = pack2(a2, a3);
        *reinterpret_cast<uint32_t*>(g_Cl + off1) = pack2(a2 - h2, a3 - h3);
    }
}

// ============================================================================
// Launch
// ============================================================================
extern "C" void kernel_launch(void* const* d_in, const int* in_sizes, int n_in,
                              void* d_out, int out_size)
{
    const float* query = (const float*)d_in[0];
    const float* key   = (const float*)d_in[1];
    const float* value = (const float*)d_in[2];
    const int*   mask  = (const int*)  d_in[3];
    const float* Wq    = (const float*)d_in[4];
    const float* bq    = (const float*)d_in[5];
    const float* Wk    = (const float*)d_in[6];
    const float* bk    = (const float*)d_in[7];
    const float* Wv    = (const float*)d_in[8];
    const float* bv    = (const float*)d_in[9];
    const float* Wo    = (const float*)d_in[10];
    const float* bo    = (const float*)d_in[11];
    float* out = (float*)d_out;

    static bool attr_done = false;
    if (!attr_done) {
        cudaFuncSetAttribute(gemm_bs<0>, cudaFuncAttributeMaxDynamicSharedMemorySize, GEMM_SMEM);
        cudaFuncSetAttribute(gemm_bs<1>, cudaFuncAttributeMaxDynamicSharedMemorySize, GEMM_SMEM);
        cudaFuncSetAttribute(gemm_bs<2>, cudaFuncAttributeMaxDynamicSharedMemorySize, GEMM_SMEM);
        cudaFuncSetAttribute(gemm_bs<3>, cudaFuncAttributeMaxDynamicSharedMemorySize, GEMM_SMEM);
        cudaFuncSetAttribute(attn_mma,   cudaFuncAttributeMaxDynamicSharedMemorySize, ATTN_SMEM);
        attr_done = true;
    }

    const int nx4 = MTOT * DMODEL / 4;
    const int nw4 = DMODEL * DMODEL / 4;

    compact_mask<<<BATCH, 1024>>>(mask);
    convert_acts<<<dim3(nx4 / 256, 3), 256>>>((const float4*)query,
                                              (const float4*)key,
                                              (const float4*)value);
    convert_wts<<<dim3(nw4 / 256, 4), 256>>>((const float4*)Wq, (const float4*)Wk,
                                             (const float4*)Wv, (const float4*)Wo);

    dim3 gemmGrid(DMODEL / 64, MTOT / 128);   // (16, 64)
    gemm_bs<1><<<gemmGrid, 256, GEMM_SMEM>>>(bq, nullptr);
    gemm_bs<2><<<gemmGrid, 256, GEMM_SMEM>>>(bk, nullptr);
    gemm_bs<3><<<gemmGrid, 256, GEMM_SMEM>>>(bv, nullptr);

    dim3 attnGrid(SEQ / 128, NHEADS, BATCH);  // (16, 16, 4)
    attn_mma<<<attnGrid, 256, ATTN_SMEM>>>();

    gemm_bs<0><<<gemmGrid, 256, GEMM_SMEM>>>(bo, out);
}

// round 12
// speedup vs baseline: 4.4033x; 1.0699x over previous
#include <cuda_runtime.h>
#include <cuda_bf16.h>
#include <cstdint>

#define BATCH  4
#define SEQ    2048
#define DMODEL 1024
#define NHEADS 16
#define HDIM   64
#define MTOT   (BATCH * SEQ)          // 8192
#define QSCALE 0.1803368801111204f   // 1/sqrt(HDIM) * log2(e)
#define NEGI   -1e30f

// ---- scratch (device globals; no allocation) ----
__device__ __nv_bfloat16 g_Xh[3][MTOT * DMODEL];
__device__ __nv_bfloat16 g_Xl[3][MTOT * DMODEL];
__device__ __nv_bfloat16 g_Wh[4][DMODEL * DMODEL];
__device__ __nv_bfloat16 g_Wl[4][DMODEL * DMODEL];
__device__ __nv_bfloat16 g_Qh[MTOT * DMODEL], g_Ql[MTOT * DMODEL]; // (B,H,S,Dh), scaled
__device__ __nv_bfloat16 g_Kh[MTOT * DMODEL], g_Kl[MTOT * DMODEL]; // compacted
__device__ __nv_bfloat16 g_Vh[MTOT * DMODEL], g_Vl[MTOT * DMODEL]; // compacted
__device__ __nv_bfloat16 g_Ch[MTOT * DMODEL], g_Cl[MTOT * DMODEL]; // ctx (B,S,D)
__device__ int g_inv[BATCH * SEQ];   // compact pos -> source row
__device__ int g_cnt[BATCH];

// ============================================================================
// Helpers
// ============================================================================
__device__ __forceinline__ uint32_t smem_u32(const void* p) {
    uint32_t a;
    asm("{ .reg .u64 t; cvta.to.shared.u64 t, %1; cvt.u32.u64 %0, t; }"
        : "=r"(a) : "l"(p));
    return a;
}

__device__ __forceinline__ void ldsm_x4(uint32_t& r0, uint32_t& r1,
                                        uint32_t& r2, uint32_t& r3, uint32_t addr) {
    asm volatile("ldmatrix.sync.aligned.m8n8.x4.shared.b16 {%0,%1,%2,%3}, [%4];"
                 : "=r"(r0), "=r"(r1), "=r"(r2), "=r"(r3) : "r"(addr));
}

__device__ __forceinline__ void ldsm_x4t(uint32_t& r0, uint32_t& r1,
                                         uint32_t& r2, uint32_t& r3, uint32_t addr) {
    asm volatile("ldmatrix.sync.aligned.m8n8.x4.trans.shared.b16 {%0,%1,%2,%3}, [%4];"
                 : "=r"(r0), "=r"(r1), "=r"(r2), "=r"(r3) : "r"(addr));
}

__device__ __forceinline__ void mma_bf16(float* c,
                                         const uint32_t* a,
                                         uint32_t b0, uint32_t b1) {
    asm volatile(
        "mma.sync.aligned.m16n8k16.row.col.f32.bf16.bf16.f32 "
        "{%0,%1,%2,%3}, {%4,%5,%6,%7}, {%8,%9}, {%0,%1,%2,%3};"
        : "+f"(c[0]), "+f"(c[1]), "+f"(c[2]), "+f"(c[3])
        : "r"(a[0]), "r"(a[1]), "r"(a[2]), "r"(a[3]), "r"(b0), "r"(b1));
}

__device__ __forceinline__ uint32_t pack2(float x, float y) {
    __nv_bfloat162 t = __floats2bfloat162_rn(x, y);
    return *reinterpret_cast<uint32_t*>(&t);
}
__device__ __forceinline__ float rb(float x) {
    return __bfloat162float(__float2bfloat16(x));
}
__device__ __forceinline__ float ex2(float x) {
    float r;
    asm("ex2.approx.f32 %0, %1;" : "=f"(r) : "f"(x));
    return r;
}
__device__ __forceinline__ void cp16(uint32_t dst, const void* src) {
    asm volatile("cp.async.cg.shared.global [%0], [%1], 16;" :: "r"(dst), "l"(src));
}
#define CP_COMMIT() asm volatile("cp.async.commit_group;" ::: "memory")
#define CP_WAIT1()  asm volatile("cp.async.wait_group 1;" ::: "memory")
#define CP_WAIT0()  asm volatile("cp.async.wait_group 0;" ::: "memory")

// ============================================================================
// Mask compaction
// ============================================================================
__global__ void compact_mask(const int* __restrict__ mask) {
    __shared__ int ssum[1024];
    const int b = blockIdx.x, t = threadIdx.x;
    const int* mb = mask + b * SEQ;
    const int m0 = mb[2 * t] != 0, m1 = mb[2 * t + 1] != 0;
    ssum[t] = m0 + m1;
    __syncthreads();
    for (int off = 1; off < 1024; off <<= 1) {
        int v = (t >= off) ? ssum[t - off] : 0;
        __syncthreads();
        ssum[t] += v;
        __syncthreads();
    }
    const int excl = (t > 0) ? ssum[t - 1] : 0;
    if (m0) g_inv[b * SEQ + excl]      = 2 * t;
    if (m1) g_inv[b * SEQ + excl + m0] = 2 * t + 1;
    if (t == 1023) g_cnt[b] = ssum[1023];
}

// ============================================================================
// fp32 -> bf16 hi/lo splits
// ============================================================================
__global__ void convert_acts(const float4* __restrict__ q,
                             const float4* __restrict__ k,
                             const float4* __restrict__ v) {
    const int kind = blockIdx.y;
    const float4* src = (kind == 0) ? q : (kind == 1) ? k : v;
    const int i = blockIdx.x * blockDim.x + threadIdx.x;
    __nv_bfloat16* H = g_Xh[kind];
    __nv_bfloat16* L = g_Xl[kind];
    const float4 val = src[i];
    const float h0 = rb(val.x), h1 = rb(val.y), h2 = rb(val.z), h3 = rb(val.w);
    uint2 uh, ul;
    uh.x = pack2(val.x, val.y); uh.y = pack2(val.z, val.w);
    ul.x = pack2(val.x - h0, val.y - h1); ul.y = pack2(val.z - h2, val.w - h3);
    reinterpret_cast<uint2*>(H)[i] = uh;
    reinterpret_cast<uint2*>(L)[i] = ul;
}

__global__ void convert_wts(const float4* __restrict__ wq,
                            const float4* __restrict__ wk,
                            const float4* __restrict__ wv,
                            const float4* __restrict__ wo) {
    const int kind = blockIdx.y;
    const float4* src = (kind == 0) ? wq : (kind == 1) ? wk : (kind == 2) ? wv : wo;
    const int i = blockIdx.x * blockDim.x + threadIdx.x;
    __nv_bfloat16* H = g_Wh[kind];
    __nv_bfloat16* L = g_Wl[kind];
    const float4 val = src[i];
    const float h0 = rb(val.x), h1 = rb(val.y), h2 = rb(val.z), h3 = rb(val.w);
    uint2 uh, ul;
    uh.x = pack2(val.x, val.y); uh.y = pack2(val.z, val.w);
    ul.x = pack2(val.x - h0, val.y - h1); ul.y = pack2(val.z - h2, val.w - h3);
    reinterpret_cast<uint2*>(H)[i] = uh;
    reinterpret_cast<uint2*>(L)[i] = ul;
}

// ============================================================================
// bf16-split tensor-core GEMM.  Block 128x128, warp tile 32x64, BK=32.
// 2-stage cp.async pipeline (round-9 structure: wait, sync, mma, sync, load).
// acc += Ah*Bh + Ah*Bl + Al*Bh.
// Stage (40960 B): +0 Ah(10240) +10240 Al +20480 Bh(10240) +30720 Bl
// 2 stages = 81920 B -> 2 CTAs/SM; __launch_bounds__(256,2) keeps regs <=128.
// ============================================================================
#define SA_STRIDE 40
#define GSTAGE    40960
#define GEMM_SMEM (2 * GSTAGE)

template <int MODE>
__global__ __launch_bounds__(256, 2) void gemm_bs(
    const float* __restrict__ bias,
    float* __restrict__ Cout)
{
    extern __shared__ __align__(16) char dsm[];
    const uint32_t SBASE = smem_u32(dsm);

    const __nv_bfloat16 *Ah, *Al, *Wh, *Wl;
    if      (MODE == 1) { Ah = g_Xh[0]; Al = g_Xl[0]; Wh = g_Wh[0]; Wl = g_Wl[0]; }
    else if (MODE == 2) { Ah = g_Xh[1]; Al = g_Xl[1]; Wh = g_Wh[1]; Wl = g_Wl[1]; }
    else if (MODE == 3) { Ah = g_Xh[2]; Al = g_Xl[2]; Wh = g_Wh[2]; Wl = g_Wl[2]; }
    else                { Ah = g_Ch;    Al = g_Cl;    Wh = g_Wh[3]; Wl = g_Wl[3]; }

    const int tid = threadIdx.x;
    const int wid = tid >> 5;
    const int lid = tid & 31;
    const int bn = blockIdx.x * 128;
    const int wm = (wid >> 1) * 32;   // 4 warps down
    const int wn = (wid & 1) * 64;    // 2 warps across, 64 cols each

    int bm = 0, bb = 0, tile = 0, cnt = 0;
    if (MODE == 2 || MODE == 3) {
        bb   = blockIdx.y >> 4;
        tile = blockIdx.y & 15;
        cnt  = g_cnt[bb];
        if (tile * 128 >= cnt) return;
    } else {
        bm = blockIdx.y * 128;
    }

    const uint4* A4h = reinterpret_cast<const uint4*>(Ah);
    const uint4* A4l = reinterpret_cast<const uint4*>(Al);
    const uint4* W4h = reinterpret_cast<const uint4*>(Wh);
    const uint4* W4l = reinterpret_cast<const uint4*>(Wl);

    const int lr0 = tid >> 2;          // 0..63
    const int lq  = tid & 3;           // 16B slot within 64B chunk-row
    size_t aoff0, aoff1, boff0, boff1;
    if (MODE == 2 || MODE == 3) {
        int p0 = tile * 128 + lr0;
        int p1 = p0 + 64;
        int s0 = (p0 < cnt) ? g_inv[bb * SEQ + p0] : 0;
        int s1 = (p1 < cnt) ? g_inv[bb * SEQ + p1] : 0;
        aoff0 = ((size_t)(bb * SEQ + s0)) * 128 + lq;
        aoff1 = ((size_t)(bb * SEQ + s1)) * 128 + lq;
    } else {
        aoff0 = (size_t)(bm + lr0) * 128 + lq;
        aoff1 = aoff0 + (size_t)64 * 128;
    }
    boff0 = (size_t)(bn + lr0) * 128 + lq;
    boff1 = boff0 + (size_t)64 * 128;

    const uint32_t dA0 = (uint32_t)(lr0 * SA_STRIDE + lq * 8) * 2;
    const uint32_t dA1 = dA0 + (uint32_t)64 * SA_STRIDE * 2;

    auto stage_load = [&](int ch, int st) {
        const uint32_t a_h = SBASE + st * GSTAGE;
        const uint32_t a_l = a_h + 10240;
        const uint32_t b_h = a_h + 20480;
        const uint32_t b_l = a_h + 30720;
        cp16(a_h + dA0, A4h + aoff0 + ch * 4);
        cp16(a_h + dA1, A4h + aoff1 + ch * 4);
        cp16(a_l + dA0, A4l + aoff0 + ch * 4);
        cp16(a_l + dA1, A4l + aoff1 + ch * 4);
        cp16(b_h + dA0, W4h + boff0 + ch * 4);
        cp16(b_h + dA1, W4h + boff1 + ch * 4);
        cp16(b_l + dA0, W4l + boff0 + ch * 4);
        cp16(b_l + dA1, W4l + boff1 + ch * 4);
    };

    const int a_row = wm + ((lid >> 3) & 1) * 8 + (lid & 7);
    const uint32_t a_koff = ((lid >> 4) * 8) * 2;
    const int b_row = wn + ((lid >> 4) & 1) * 8 + (lid & 7);
    const uint32_t b_koff = (((lid >> 3) & 1) * 8) * 2;

    float acc[2][8][4];
    #pragma unroll
    for (int i = 0; i < 2; i++)
        #pragma unroll
        for (int j = 0; j < 8; j++)
            #pragma unroll
            for (int r = 0; r < 4; r++) acc[i][j][r] = 0.f;

    stage_load(0, 0); CP_COMMIT();
    stage_load(1, 1); CP_COMMIT();

    for (int ch = 0; ch < 32; ch++) {
        const int st = ch & 1;
        if (ch < 31) CP_WAIT1(); else CP_WAIT0();
        __syncthreads();

        const uint32_t sAh_base = SBASE + st * GSTAGE;
        const uint32_t sAl_base = sAh_base + 10240;
        const uint32_t sBh_base = sAh_base + 20480;
        const uint32_t sBl_base = sAh_base + 30720;

        #pragma unroll
        for (int ks = 0; ks < 2; ks++) {
            const uint32_t kbyte = ks * 32;
            uint32_t ah[2][4], al[2][4];
            #pragma unroll
            for (int mi = 0; mi < 2; mi++) {
                uint32_t ad = sAh_base + (uint32_t)(a_row + mi * 16) * (SA_STRIDE * 2) + kbyte + a_koff;
                ldsm_x4(ah[mi][0], ah[mi][1], ah[mi][2], ah[mi][3], ad);
                uint32_t ad2 = sAl_base + (uint32_t)(a_row + mi * 16) * (SA_STRIDE * 2) + kbyte + a_koff;
                ldsm_x4(al[mi][0], al[mi][1], al[mi][2], al[mi][3], ad2);
            }
            #pragma unroll
            for (int p = 0; p < 4; p++) {
                uint32_t bh0, bh1, bh2, bh3, bl0, bl1, bl2, bl3;
                uint32_t bd = sBh_base + (uint32_t)(b_row + p * 16) * (SA_STRIDE * 2) + kbyte + b_koff;
                ldsm_x4(bh0, bh1, bh2, bh3, bd);
                uint32_t bd2 = sBl_base + (uint32_t)(b_row + p * 16) * (SA_STRIDE * 2) + kbyte + b_koff;
                ldsm_x4(bl0, bl1, bl2, bl3, bd2);
                #pragma unroll
                for (int mi = 0; mi < 2; mi++) {
                    float* c0 = acc[mi][2 * p];
                    float* c1 = acc[mi][2 * p + 1];
                    mma_bf16(c0, ah[mi], bh0, bh1);
                    mma_bf16(c0, ah[mi], bl0, bl1);
                    mma_bf16(c0, al[mi], bh0, bh1);
                    mma_bf16(c1, ah[mi], bh2, bh3);
                    mma_bf16(c1, ah[mi], bl2, bl3);
                    mma_bf16(c1, al[mi], bh2, bh3);
                }
            }
        }
        __syncthreads();
        if (ch + 2 < 32) { stage_load(ch + 2, st); CP_COMMIT(); }
    }

    // ---- epilogue ----
    const int fr = lid >> 2;
    const int fc = (lid & 3) * 2;

    #pragma unroll
    for (int mi = 0; mi < 2; mi++)
        #pragma unroll
        for (int nj = 0; nj < 8; nj++) {
            int n = bn + wn + nj * 8 + fc;
            float2 bv = *reinterpret_cast<const float2*>(bias + n);
            #pragma unroll
            for (int half = 0; half < 2; half++) {
                float ox = acc[mi][nj][half * 2 + 0] + bv.x;
                float oy = acc[mi][nj][half * 2 + 1] + bv.y;
                if (MODE == 0) {
                    int m = bm + wm + mi * 16 + fr + half * 8;
                    float2 o; o.x = ox; o.y = oy;
                    *reinterpret_cast<float2*>(Cout + (size_t)m * DMODEL + n) = o;
                } else if (MODE == 1) {
                    int m = bm + wm + mi * 16 + fr + half * 8;
                    int b  = m >> 11;
                    int s  = m & (SEQ - 1);
                    int hh = n >> 6;
                    int dh = n & (HDIM - 1);
                    ox *= QSCALE; oy *= QSCALE;
                    size_t off = (((size_t)(b * NHEADS + hh)) * SEQ + s) * HDIM + dh;
                    float hx = rb(ox), hy = rb(oy);
                    *reinterpret_cast<uint32_t*>(g_Qh + off) = pack2(ox, oy);
                    *reinterpret_cast<uint32_t*>(g_Ql + off) = pack2(ox - hx, oy - hy);
                } else {
                    int pos = tile * 128 + wm + mi * 16 + fr + half * 8;
                    if (pos < cnt) {
                        int hh = n >> 6;
                        int dh = n & (HDIM - 1);
                        size_t off = (((size_t)(bb * NHEADS + hh)) * SEQ + pos) * HDIM + dh;
                        float hx = rb(ox), hy = rb(oy);
                        if (MODE == 2) {
                            *reinterpret_cast<uint32_t*>(g_Kh + off) = pack2(ox, oy);
                            *reinterpret_cast<uint32_t*>(g_Kl + off) = pack2(ox - hx, oy - hy);
                        } else {
                            *reinterpret_cast<uint32_t*>(g_Vh + off) = pack2(ox, oy);
                            *reinterpret_cast<uint32_t*>(g_Vl + off) = pack2(ox - hx, oy - hy);
                        }
                    }
                }
            }
        }
}

// ============================================================================
// Tensor-core flash attention, 3-stage cp.async K/V pipeline (round-10, kept).
// ============================================================================
#define ASTAGE    36864
#define ATTN_SMEM (3 * ASTAGE)

__global__ __launch_bounds__(256) void attn_mma()
{
    extern __shared__ __align__(16) char dsm[];
    const uint32_t SB = smem_u32(dsm);

    const int tid = threadIdx.x;
    const int wid = tid >> 5;
    const int lid = tid & 31;
    const int hh = blockIdx.y;
    const int b  = blockIdx.z;
    const int qb = blockIdx.x * 128;
    const int wq = wid * 16;
    const int cnt = g_cnt[b];

    const size_t hb = ((size_t)(b * NHEADS + hh)) * SEQ * HDIM;
    const uint4* Qh4 = reinterpret_cast<const uint4*>(g_Qh + hb + (size_t)qb * HDIM);
    const uint4* Ql4 = reinterpret_cast<const uint4*>(g_Ql + hb + (size_t)qb * HDIM);
    const uint4* Kh4 = reinterpret_cast<const uint4*>(g_Kh + hb);
    const uint4* Kl4 = reinterpret_cast<const uint4*>(g_Kl + hb);
    const uint4* Vh4 = reinterpret_cast<const uint4*>(g_Vh + hb);
    const uint4* Vl4 = reinterpret_cast<const uint4*>(g_Vl + hb);

    uint4* sb4 = reinterpret_cast<uint4*>(dsm);
    #pragma unroll
    for (int j = 0; j < 4; j++) {
        int idx = tid + 256 * j;
        int r = idx >> 3, q = idx & 7;
        sb4[9 * r + q]        = Qh4[r * 8 + q];
        sb4[1152 + 9 * r + q] = Ql4[r * 8 + q];
    }
    __syncthreads();

    uint32_t qfh[4][4], qfl[4][4];
    {
        const int arow = wq + (lid & 7) + ((lid >> 3) & 1) * 8;
        const int akoff = (lid >> 4) * 8;
        #pragma unroll
        for (int ks = 0; ks < 4; ks++) {
            uint32_t ad = SB + (uint32_t)(arow * 72 + ks * 16 + akoff) * 2;
            ldsm_x4(qfh[ks][0], qfh[ks][1], qfh[ks][2], qfh[ks][3], ad);
            ldsm_x4(qfl[ks][0], qfl[ks][1], qfl[ks][2], qfl[ks][3], ad + 18432);
        }
    }
    __syncthreads();

    const int ntl = (cnt + 63) >> 6;

    auto load_tile = [&](int kt, int st) {
        const uint32_t base = SB + st * ASTAGE;
        #pragma unroll
        for (int j = 0; j < 2; j++) {
            int idx = tid + 256 * j;
            int r = idx >> 3, q = idx & 7;
            uint32_t so = base + (uint32_t)(r * 144 + q * 16);
            int gi = (kt * 64 + r) * 8 + q;
            cp16(so,         Kh4 + gi);
            cp16(so + 9216,  Kl4 + gi);
            cp16(so + 18432, Vh4 + gi);
            cp16(so + 27648, Vl4 + gi);
        }
    };

    float oacc[8][4];
    #pragma unroll
    for (int ng = 0; ng < 8; ng++)
        #pragma unroll
        for (int r = 0; r < 4; r++) oacc[ng][r] = 0.f;

    float mrow0 = NEGI, mrow1 = NEGI, lrow0 = 0.f, lrow1 = 0.f;

    const int brow = (lid & 7) + ((lid >> 4) & 1) * 8;
    const int bko  = ((lid >> 3) & 1) * 8;
    const int vrow = lid & 15;
    const int vco  = (lid >> 4) * 8;
    const int fc   = (lid & 3) * 2;

    load_tile(0, 0); CP_COMMIT();
    if (ntl > 1) { load_tile(1, 1); CP_COMMIT(); }

    int st = 0;
    for (int kt = 0; kt < ntl; kt++) {
        if (kt + 1 < ntl) CP_WAIT1(); else CP_WAIT0();
        __syncthreads();
        if (kt + 2 < ntl) {
            int st2 = st + 2; if (st2 >= 3) st2 -= 3;
            load_tile(kt + 2, st2); CP_COMMIT();
        }
        const uint32_t SBS = SB + st * ASTAGE;

        float sacc[8][4];
        #pragma unroll
        for (int nt = 0; nt < 8; nt++)
            #pragma unroll
            for (int r = 0; r < 4; r++) sacc[nt][r] = 0.f;

        #pragma unroll
        for (int ks = 0; ks < 4; ks++) {
            uint32_t kh[8][2], kl[8][2];
            #pragma unroll
            for (int p = 0; p < 4; p++) {
                uint32_t r0, r1, r2, r3;
                uint32_t ad = SBS + (uint32_t)((p * 16 + brow) * 72 + ks * 16 + bko) * 2;
                ldsm_x4(r0, r1, r2, r3, ad);
                kh[p * 2][0] = r0; kh[p * 2][1] = r1;
                kh[p * 2 + 1][0] = r2; kh[p * 2 + 1][1] = r3;
                ldsm_x4(r0, r1, r2, r3, ad + 9216);
                kl[p * 2][0] = r0; kl[p * 2][1] = r1;
                kl[p * 2 + 1][0] = r2; kl[p * 2 + 1][1] = r3;
            }
            #pragma unroll
            for (int nt = 0; nt < 8; nt++) {
                mma_bf16(sacc[nt], qfh[ks], kh[nt][0], kh[nt][1]);
                mma_bf16(sacc[nt], qfh[ks], kl[nt][0], kl[nt][1]);
                mma_bf16(sacc[nt], qfl[ks], kh[nt][0], kh[nt][1]);
            }
        }

        const int key0 = kt * 64 + fc;
        float tm0 = NEGI, tm1 = NEGI;
        #pragma unroll
        for (int nt = 0; nt < 8; nt++) {
            bool v0 = (key0 + nt * 8) < cnt;
            bool v1 = (key0 + nt * 8 + 1) < cnt;
            if (!v0) { sacc[nt][0] = NEGI; sacc[nt][2] = NEGI; }
            if (!v1) { sacc[nt][1] = NEGI; sacc[nt][3] = NEGI; }
            tm0 = fmaxf(tm0, fmaxf(sacc[nt][0], sacc[nt][1]));
            tm1 = fmaxf(tm1, fmaxf(sacc[nt][2], sacc[nt][3]));
        }
        tm0 = fmaxf(tm0, __shfl_xor_sync(0xffffffffu, tm0, 1));
        tm0 = fmaxf(tm0, __shfl_xor_sync(0xffffffffu, tm0, 2));
        tm1 = fmaxf(tm1, __shfl_xor_sync(0xffffffffu, tm1, 1));
        tm1 = fmaxf(tm1, __shfl_xor_sync(0xffffffffu, tm1, 2));

        const float mn0 = fmaxf(mrow0, tm0), mn1 = fmaxf(mrow1, tm1);
        const float c0 = ex2(mrow0 - mn0), c1 = ex2(mrow1 - mn1);
        mrow0 = mn0; mrow1 = mn1;

        uint32_t pah[4][4], pal[4][4];
        float ls0 = 0.f, ls1 = 0.f;
        #pragma unroll
        for (int nt = 0; nt < 8; nt++) {
            float p0 = ex2(sacc[nt][0] - mn0), p1 = ex2(sacc[nt][1] - mn0);
            float p2 = ex2(sacc[nt][2] - mn1), p3 = ex2(sacc[nt][3] - mn1);
            ls0 += p0 + p1; ls1 += p2 + p3;
            float h0 = rb(p0), h1 = rb(p1), h2 = rb(p2), h3 = rb(p3);
            int kc = nt >> 1, o2 = (nt & 1) * 2;
            pah[kc][o2 + 0] = pack2(p0, p1);
            pah[kc][o2 + 1] = pack2(p2, p3);
            pal[kc][o2 + 0] = pack2(p0 - h0, p1 - h1);
            pal[kc][o2 + 1] = pack2(p2 - h2, p3 - h3);
        }
        lrow0 = lrow0 * c0 + ls0;
        lrow1 = lrow1 * c1 + ls1;
        #pragma unroll
        for (int ng = 0; ng < 8; ng++) {
            oacc[ng][0] *= c0; oacc[ng][1] *= c0;
            oacc[ng][2] *= c1; oacc[ng][3] *= c1;
        }

        #pragma unroll
        for (int kc = 0; kc < 4; kc++) {
            uint32_t vh[8][2], vl[8][2];
            #pragma unroll
            for (int p = 0; p < 4; p++) {
                uint32_t r0, r1, r2, r3;
                uint32_t ad = SBS + 18432 + (uint32_t)((kc * 16 + vrow) * 72 + p * 16 + vco) * 2;
                ldsm_x4t(r0, r1, r2, r3, ad);
                vh[p * 2][0] = r0; vh[p * 2][1] = r1;
                vh[p * 2 + 1][0] = r2; vh[p * 2 + 1][1] = r3;
                ldsm_x4t(r0, r1, r2, r3, ad + 9216);
                vl[p * 2][0] = r0; vl[p * 2][1] = r1;
                vl[p * 2 + 1][0] = r2; vl[p * 2 + 1][1] = r3;
            }
            #pragma unroll
            for (int ng = 0; ng < 8; ng++) {
                mma_bf16(oacc[ng], pah[kc], vh[ng][0], vh[ng][1]);
                mma_bf16(oacc[ng], pah[kc], vl[ng][0], vl[ng][1]);
                mma_bf16(oacc[ng], pal[kc], vh[ng][0], vh[ng][1]);
            }
        }
        if (++st == 3) st = 0;
    }

    lrow0 += __shfl_xor_sync(0xffffffffu, lrow0, 1);
    lrow0 += __shfl_xor_sync(0xffffffffu, lrow0, 2);
    lrow1 += __shfl_xor_sync(0xffffffffu, lrow1, 1);
    lrow1 += __shfl_xor_sync(0xffffffffu, lrow1, 2);

    const float inv0 = 1.0f / lrow0;
    const float inv1 = 1.0f / lrow1;
    const int r0 = qb + wq + (lid >> 2);
    const int r1 = r0 + 8;
    #pragma unroll
    for (int ng = 0; ng < 8; ng++) {
        int col = hh * HDIM + ng * 8 + fc;
        float a0 = oacc[ng][0] * inv0, a1 = oacc[ng][1] * inv0;
        float a2 = oacc[ng][2] * inv1, a3 = oacc[ng][3] * inv1;
        size_t off0 = ((size_t)(b * SEQ + r0)) * DMODEL + col;
        size_t off1 = ((size_t)(b * SEQ + r1)) * DMODEL + col;
        float h0 = rb(a0), h1 = rb(a1), h2 = rb(a2), h3 = rb(a3);
        *reinterpret_cast<uint32_t*>(g_Ch + off0) = pack2(a0, a1);
        *reinterpret_cast<uint32_t*>(g_Cl + off0) = pack2(a0 - h0, a1 - h1);
        *reinterpret_cast<uint32_t*>(g_Ch + off1) = pack2(a2, a3);
        *reinterpret_cast<uint32_t*>(g_Cl + off1) = pack2(a2 - h2, a3 - h3);
    }
}

// ============================================================================
// Launch
// ============================================================================
extern "C" void kernel_launch(void* const* d_in, const int* in_sizes, int n_in,
                              void* d_out, int out_size)
{
    const float* query = (const float*)d_in[0];
    const float* key   = (const float*)d_in[1];
    const float* value = (const float*)d_in[2];
    const int*   mask  = (const int*)  d_in[3];
    const float* Wq    = (const float*)d_in[4];
    const float* bq    = (const float*)d_in[5];
    const float* Wk    = (const float*)d_in[6];
    const float* bk    = (const float*)d_in[7];
    const float* Wv    = (const float*)d_in[8];
    const float* bv    = (const float*)d_in[9];
    const float* Wo    = (const float*)d_in[10];
    const float* bo    = (const float*)d_in[11];
    float* out = (float*)d_out;

    static bool attr_done = false;
    if (!attr_done) {
        cudaFuncSetAttribute(gemm_bs<0>, cudaFuncAttributeMaxDynamicSharedMemorySize, GEMM_SMEM);
        cudaFuncSetAttribute(gemm_bs<1>, cudaFuncAttributeMaxDynamicSharedMemorySize, GEMM_SMEM);
        cudaFuncSetAttribute(gemm_bs<2>, cudaFuncAttributeMaxDynamicSharedMemorySize, GEMM_SMEM);
        cudaFuncSetAttribute(gemm_bs<3>, cudaFuncAttributeMaxDynamicSharedMemorySize, GEMM_SMEM);
        cudaFuncSetAttribute(attn_mma,   cudaFuncAttributeMaxDynamicSharedMemorySize, ATTN_SMEM);
        attr_done = true;
    }

    const int nx4 = MTOT * DMODEL / 4;
    const int nw4 = DMODEL * DMODEL / 4;

    compact_mask<<<BATCH, 1024>>>(mask);
    convert_acts<<<dim3(nx4 / 256, 3), 256>>>((const float4*)query,
                                              (const float4*)key,
                                              (const float4*)value);
    convert_wts<<<dim3(nw4 / 256, 4), 256>>>((const float4*)Wq, (const float4*)Wk,
                                             (const float4*)Wv, (const float4*)Wo);

    dim3 gemmGrid(DMODEL / 128, MTOT / 128);   // (8, 64)
    gemm_bs<1><<<gemmGrid, 256, GEMM_SMEM>>>(bq, nullptr);
    gemm_bs<2><<<gemmGrid, 256, GEMM_SMEM>>>(bk, nullptr);
    gemm_bs<3><<<gemmGrid, 256, GEMM_SMEM>>>(bv, nullptr);

    dim3 attnGrid(SEQ / 128, NHEADS, BATCH);  // (16, 16, 4)
    attn_mma<<<attnGrid, 256, ATTN_SMEM>>>();

    gemm_bs<0><<<gemmGrid, 256, GEMM_SMEM>>>(bo, out);
}

// round 13
// speedup vs baseline: 4.4545x; 1.0116x over previous
#include <cuda_runtime.h>
#include <cuda_bf16.h>
#include <cstdint>

#define BATCH  4
#define SEQ    2048
#define DMODEL 1024
#define NHEADS 16
#define HDIM   64
#define MTOT   (BATCH * SEQ)          // 8192
#define QSCALE 0.1803368801111204f   // 1/sqrt(HDIM) * log2(e)
#define NEGI   -1e30f

// ---- scratch (device globals; no allocation) ----
__device__ __nv_bfloat16 g_Xh[3][MTOT * DMODEL];
__device__ __nv_bfloat16 g_Xl[3][MTOT * DMODEL];
__device__ __nv_bfloat16 g_Wh[4][DMODEL * DMODEL];
__device__ __nv_bfloat16 g_Wl[4][DMODEL * DMODEL];
__device__ __nv_bfloat16 g_Qh[MTOT * DMODEL], g_Ql[MTOT * DMODEL]; // (B,H,S,Dh), scaled
__device__ __nv_bfloat16 g_Kh[MTOT * DMODEL], g_Kl[MTOT * DMODEL]; // compacted
__device__ __nv_bfloat16 g_Vh[MTOT * DMODEL], g_Vl[MTOT * DMODEL]; // compacted
__device__ __nv_bfloat16 g_Ch[MTOT * DMODEL], g_Cl[MTOT * DMODEL]; // ctx (B,S,D)
__device__ int g_inv[BATCH * SEQ];   // compact pos -> source row
__device__ int g_cnt[BATCH];

// ============================================================================
// Helpers
// ============================================================================
__device__ __forceinline__ uint32_t smem_u32(const void* p) {
    uint32_t a;
    asm("{ .reg .u64 t; cvta.to.shared.u64 t, %1; cvt.u32.u64 %0, t; }"
        : "=r"(a) : "l"(p));
    return a;
}

__device__ __forceinline__ void ldsm_x4(uint32_t& r0, uint32_t& r1,
                                        uint32_t& r2, uint32_t& r3, uint32_t addr) {
    asm volatile("ldmatrix.sync.aligned.m8n8.x4.shared.b16 {%0,%1,%2,%3}, [%4];"
                 : "=r"(r0), "=r"(r1), "=r"(r2), "=r"(r3) : "r"(addr));
}

__device__ __forceinline__ void ldsm_x4t(uint32_t& r0, uint32_t& r1,
                                         uint32_t& r2, uint32_t& r3, uint32_t addr) {
    asm volatile("ldmatrix.sync.aligned.m8n8.x4.trans.shared.b16 {%0,%1,%2,%3}, [%4];"
                 : "=r"(r0), "=r"(r1), "=r"(r2), "=r"(r3) : "r"(addr));
}

__device__ __forceinline__ void mma_bf16(float* c,
                                         const uint32_t* a,
                                         uint32_t b0, uint32_t b1) {
    asm volatile(
        "mma.sync.aligned.m16n8k16.row.col.f32.bf16.bf16.f32 "
        "{%0,%1,%2,%3}, {%4,%5,%6,%7}, {%8,%9}, {%0,%1,%2,%3};"
        : "+f"(c[0]), "+f"(c[1]), "+f"(c[2]), "+f"(c[3])
        : "r"(a[0]), "r"(a[1]), "r"(a[2]), "r"(a[3]), "r"(b0), "r"(b1));
}

__device__ __forceinline__ uint32_t pack2(float x, float y) {
    __nv_bfloat162 t = __floats2bfloat162_rn(x, y);
    return *reinterpret_cast<uint32_t*>(&t);
}
__device__ __forceinline__ float rb(float x) {
    return __bfloat162float(__float2bfloat16(x));
}
__device__ __forceinline__ float ex2(float x) {
    float r;
    asm("ex2.approx.f32 %0, %1;" : "=f"(r) : "f"(x));
    return r;
}
__device__ __forceinline__ void cp16(uint32_t dst, const void* src) {
    asm volatile("cp.async.cg.shared.global [%0], [%1], 16;" :: "r"(dst), "l"(src));
}
#define CP_COMMIT() asm volatile("cp.async.commit_group;" ::: "memory")
#define CP_WAIT1()  asm volatile("cp.async.wait_group 1;" ::: "memory")
#define CP_WAIT0()  asm volatile("cp.async.wait_group 0;" ::: "memory")

// ============================================================================
// Mask compaction
// ============================================================================
__global__ void compact_mask(const int* __restrict__ mask) {
    __shared__ int ssum[1024];
    const int b = blockIdx.x, t = threadIdx.x;
    const int* mb = mask + b * SEQ;
    const int m0 = mb[2 * t] != 0, m1 = mb[2 * t + 1] != 0;
    ssum[t] = m0 + m1;
    __syncthreads();
    for (int off = 1; off < 1024; off <<= 1) {
        int v = (t >= off) ? ssum[t - off] : 0;
        __syncthreads();
        ssum[t] += v;
        __syncthreads();
    }
    const int excl = (t > 0) ? ssum[t - 1] : 0;
    if (m0) g_inv[b * SEQ + excl]      = 2 * t;
    if (m1) g_inv[b * SEQ + excl + m0] = 2 * t + 1;
    if (t == 1023) g_cnt[b] = ssum[1023];
}

// ============================================================================
// fp32 -> bf16 hi/lo splits, single launch (kinds 0-2 acts, 3-6 weights)
// ============================================================================
__global__ void convert_all(const float4* __restrict__ q,
                            const float4* __restrict__ k,
                            const float4* __restrict__ v,
                            const float4* __restrict__ wq,
                            const float4* __restrict__ wk,
                            const float4* __restrict__ wv,
                            const float4* __restrict__ wo,
                            int nx4, int nw4) {
    const int kind = blockIdx.y;
    const int i = blockIdx.x * blockDim.x + threadIdx.x;
    const float4* src;
    __nv_bfloat16 *H, *L;
    if (kind < 3) {
        if (i >= nx4) return;
        src = (kind == 0) ? q : (kind == 1) ? k : v;
        H = g_Xh[kind]; L = g_Xl[kind];
    } else {
        if (i >= nw4) return;
        src = (kind == 3) ? wq : (kind == 4) ? wk : (kind == 5) ? wv : wo;
        H = g_Wh[kind - 3]; L = g_Wl[kind - 3];
    }
    const float4 val = src[i];
    const float h0 = rb(val.x), h1 = rb(val.y), h2 = rb(val.z), h3 = rb(val.w);
    uint2 uh, ul;
    uh.x = pack2(val.x, val.y); uh.y = pack2(val.z, val.w);
    ul.x = pack2(val.x - h0, val.y - h1); ul.y = pack2(val.z - h2, val.w - h3);
    reinterpret_cast<uint2*>(H)[i] = uh;
    reinterpret_cast<uint2*>(L)[i] = ul;
}

// ============================================================================
// GEMM mainloop core (shared by QKV-merged kernel and O kernel).
// Block 128x128, warp tile 32x64, BK=32, 2-stage cp.async.
// Term-major mma order: chains of dependent mmas spaced by 4 independents.
// Stage (40960 B): +0 Ah(10240) +10240 Al +20480 Bh(10240) +30720 Bl
// ============================================================================
#define SA_STRIDE 40
#define GSTAGE    40960
#define GEMM_SMEM (2 * GSTAGE)

struct GemmCtx {
    const __nv_bfloat16 *Ah, *Al, *Wh, *Wl;
    size_t aoff0, aoff1, boff0, boff1;   // uint4 indices (per-thread)
};

__device__ __forceinline__ void gemm_mainloop(
    const GemmCtx& cx, uint32_t SBASE, int tid, int lid, int wm, int wn,
    float acc[2][8][4])
{
    const uint4* A4h = reinterpret_cast<const uint4*>(cx.Ah);
    const uint4* A4l = reinterpret_cast<const uint4*>(cx.Al);
    const uint4* W4h = reinterpret_cast<const uint4*>(cx.Wh);
    const uint4* W4l = reinterpret_cast<const uint4*>(cx.Wl);

    const int lr0 = tid >> 2;
    const int lq  = tid & 3;
    const uint32_t dA0 = (uint32_t)(lr0 * SA_STRIDE + lq * 8) * 2;
    const uint32_t dA1 = dA0 + (uint32_t)64 * SA_STRIDE * 2;

    auto stage_load = [&](int ch, int st) {
        const uint32_t a_h = SBASE + st * GSTAGE;
        const uint32_t a_l = a_h + 10240;
        const uint32_t b_h = a_h + 20480;
        const uint32_t b_l = a_h + 30720;
        cp16(a_h + dA0, A4h + cx.aoff0 + ch * 4);
        cp16(a_h + dA1, A4h + cx.aoff1 + ch * 4);
        cp16(a_l + dA0, A4l + cx.aoff0 + ch * 4);
        cp16(a_l + dA1, A4l + cx.aoff1 + ch * 4);
        cp16(b_h + dA0, W4h + cx.boff0 + ch * 4);
        cp16(b_h + dA1, W4h + cx.boff1 + ch * 4);
        cp16(b_l + dA0, W4l + cx.boff0 + ch * 4);
        cp16(b_l + dA1, W4l + cx.boff1 + ch * 4);
    };

    const int a_row = wm + ((lid >> 3) & 1) * 8 + (lid & 7);
    const uint32_t a_koff = ((lid >> 4) * 8) * 2;
    const int b_row = wn + ((lid >> 4) & 1) * 8 + (lid & 7);
    const uint32_t b_koff = (((lid >> 3) & 1) * 8) * 2;

    stage_load(0, 0); CP_COMMIT();
    stage_load(1, 1); CP_COMMIT();

    for (int ch = 0; ch < 32; ch++) {
        const int st = ch & 1;
        if (ch < 31) CP_WAIT1(); else CP_WAIT0();
        __syncthreads();

        const uint32_t sAh_base = SBASE + st * GSTAGE;
        const uint32_t sAl_base = sAh_base + 10240;
        const uint32_t sBh_base = sAh_base + 20480;
        const uint32_t sBl_base = sAh_base + 30720;

        #pragma unroll
        for (int ks = 0; ks < 2; ks++) {
            const uint32_t kbyte = ks * 32;
            uint32_t ah[2][4], al[2][4];
            #pragma unroll
            for (int mi = 0; mi < 2; mi++) {
                uint32_t ad = sAh_base + (uint32_t)(a_row + mi * 16) * (SA_STRIDE * 2) + kbyte + a_koff;
                ldsm_x4(ah[mi][0], ah[mi][1], ah[mi][2], ah[mi][3], ad);
                uint32_t ad2 = sAl_base + (uint32_t)(a_row + mi * 16) * (SA_STRIDE * 2) + kbyte + a_koff;
                ldsm_x4(al[mi][0], al[mi][1], al[mi][2], al[mi][3], ad2);
            }
            #pragma unroll
            for (int p = 0; p < 4; p++) {
                uint32_t bh0, bh1, bh2, bh3, bl0, bl1, bl2, bl3;
                uint32_t bd = sBh_base + (uint32_t)(b_row + p * 16) * (SA_STRIDE * 2) + kbyte + b_koff;
                ldsm_x4(bh0, bh1, bh2, bh3, bd);
                uint32_t bd2 = sBl_base + (uint32_t)(b_row + p * 16) * (SA_STRIDE * 2) + kbyte + b_koff;
                ldsm_x4(bl0, bl1, bl2, bl3, bd2);
                // term-major: 4 independent mmas between dependent reuses
                #pragma unroll
                for (int mi = 0; mi < 2; mi++) {
                    mma_bf16(acc[mi][2 * p],     ah[mi], bh0, bh1);
                    mma_bf16(acc[mi][2 * p + 1], ah[mi], bh2, bh3);
                }
                #pragma unroll
                for (int mi = 0; mi < 2; mi++) {
                    mma_bf16(acc[mi][2 * p],     ah[mi], bl0, bl1);
                    mma_bf16(acc[mi][2 * p + 1], ah[mi], bl2, bl3);
                }
                #pragma unroll
                for (int mi = 0; mi < 2; mi++) {
                    mma_bf16(acc[mi][2 * p],     al[mi], bh0, bh1);
                    mma_bf16(acc[mi][2 * p + 1], al[mi], bh2, bh3);
                }
            }
        }
        __syncthreads();
        if (ch + 2 < 32) { stage_load(ch + 2, st); CP_COMMIT(); }
    }
}

// ============================================================================
// Merged Q/K/V projection GEMM. blockIdx.z = kind (0=Q,1=K,2=V).
// Q: full M; K/V: compacted M per batch with early-exit.
// ============================================================================
__global__ __launch_bounds__(256, 2) void gemm_qkv(
    const float* __restrict__ bq,
    const float* __restrict__ bk,
    const float* __restrict__ bv)
{
    extern __shared__ __align__(16) char dsm[];
    const uint32_t SBASE = smem_u32(dsm);

    const int kind = blockIdx.z;
    const int tid = threadIdx.x;
    const int wid = tid >> 5;
    const int lid = tid & 31;
    const int bn = blockIdx.x * 128;
    const int wm = (wid >> 1) * 32;
    const int wn = (wid & 1) * 64;

    int bm = 0, bb = 0, tile = 0, cnt = 0;
    if (kind >= 1) {
        bb   = blockIdx.y >> 4;
        tile = blockIdx.y & 15;
        cnt  = g_cnt[bb];
        if (tile * 128 >= cnt) return;
    } else {
        bm = blockIdx.y * 128;
    }

    GemmCtx cx;
    cx.Ah = g_Xh[kind]; cx.Al = g_Xl[kind];
    cx.Wh = g_Wh[kind]; cx.Wl = g_Wl[kind];

    const int lr0 = tid >> 2;
    const int lq  = tid & 3;
    if (kind >= 1) {
        int p0 = tile * 128 + lr0;
        int p1 = p0 + 64;
        int s0 = (p0 < cnt) ? g_inv[bb * SEQ + p0] : 0;
        int s1 = (p1 < cnt) ? g_inv[bb * SEQ + p1] : 0;
        cx.aoff0 = ((size_t)(bb * SEQ + s0)) * 128 + lq;
        cx.aoff1 = ((size_t)(bb * SEQ + s1)) * 128 + lq;
    } else {
        cx.aoff0 = (size_t)(bm + lr0) * 128 + lq;
        cx.aoff1 = cx.aoff0 + (size_t)64 * 128;
    }
    cx.boff0 = (size_t)(bn + lr0) * 128 + lq;
    cx.boff1 = cx.boff0 + (size_t)64 * 128;

    float acc[2][8][4];
    #pragma unroll
    for (int i = 0; i < 2; i++)
        #pragma unroll
        for (int j = 0; j < 8; j++)
            #pragma unroll
            for (int r = 0; r < 4; r++) acc[i][j][r] = 0.f;

    gemm_mainloop(cx, SBASE, tid, lid, wm, wn, acc);

    // ---- epilogue ----
    const float* bias = (kind == 0) ? bq : (kind == 1) ? bk : bv;
    const int fr = lid >> 2;
    const int fc = (lid & 3) * 2;

    #pragma unroll
    for (int mi = 0; mi < 2; mi++)
        #pragma unroll
        for (int nj = 0; nj < 8; nj++) {
            int n = bn + wn + nj * 8 + fc;
            float2 bvv = *reinterpret_cast<const float2*>(bias + n);
            #pragma unroll
            for (int half = 0; half < 2; half++) {
                float ox = acc[mi][nj][half * 2 + 0] + bvv.x;
                float oy = acc[mi][nj][half * 2 + 1] + bvv.y;
                int hh = n >> 6;
                int dh = n & (HDIM - 1);
                if (kind == 0) {
                    int m = bm + wm + mi * 16 + fr + half * 8;
                    int b  = m >> 11;
                    int s  = m & (SEQ - 1);
                    ox *= QSCALE; oy *= QSCALE;
                    size_t off = (((size_t)(b * NHEADS + hh)) * SEQ + s) * HDIM + dh;
                    float hx = rb(ox), hy = rb(oy);
                    *reinterpret_cast<uint32_t*>(g_Qh + off) = pack2(ox, oy);
                    *reinterpret_cast<uint32_t*>(g_Ql + off) = pack2(ox - hx, oy - hy);
                } else {
                    int pos = tile * 128 + wm + mi * 16 + fr + half * 8;
                    if (pos < cnt) {
                        size_t off = (((size_t)(bb * NHEADS + hh)) * SEQ + pos) * HDIM + dh;
                        float hx = rb(ox), hy = rb(oy);
                        if (kind == 1) {
                            *reinterpret_cast<uint32_t*>(g_Kh + off) = pack2(ox, oy);
                            *reinterpret_cast<uint32_t*>(g_Kl + off) = pack2(ox - hx, oy - hy);
                        } else {
                            *reinterpret_cast<uint32_t*>(g_Vh + off) = pack2(ox, oy);
                            *reinterpret_cast<uint32_t*>(g_Vl + off) = pack2(ox - hx, oy - hy);
                        }
                    }
                }
            }
        }
}

// ============================================================================
// Output projection GEMM: A = g_Ch/g_Cl, C = fp32 row-major.
// ============================================================================
__global__ __launch_bounds__(256, 2) void gemm_o(
    const float* __restrict__ bias,
    float* __restrict__ Cout)
{
    extern __shared__ __align__(16) char dsm[];
    const uint32_t SBASE = smem_u32(dsm);

    const int tid = threadIdx.x;
    const int wid = tid >> 5;
    const int lid = tid & 31;
    const int bn = blockIdx.x * 128;
    const int bm = blockIdx.y * 128;
    const int wm = (wid >> 1) * 32;
    const int wn = (wid & 1) * 64;

    GemmCtx cx;
    cx.Ah = g_Ch; cx.Al = g_Cl;
    cx.Wh = g_Wh[3]; cx.Wl = g_Wl[3];

    const int lr0 = tid >> 2;
    const int lq  = tid & 3;
    cx.aoff0 = (size_t)(bm + lr0) * 128 + lq;
    cx.aoff1 = cx.aoff0 + (size_t)64 * 128;
    cx.boff0 = (size_t)(bn + lr0) * 128 + lq;
    cx.boff1 = cx.boff0 + (size_t)64 * 128;

    float acc[2][8][4];
    #pragma unroll
    for (int i = 0; i < 2; i++)
        #pragma unroll
        for (int j = 0; j < 8; j++)
            #pragma unroll
            for (int r = 0; r < 4; r++) acc[i][j][r] = 0.f;

    gemm_mainloop(cx, SBASE, tid, lid, wm, wn, acc);

    const int fr = lid >> 2;
    const int fc = (lid & 3) * 2;
    #pragma unroll
    for (int mi = 0; mi < 2; mi++)
        #pragma unroll
        for (int nj = 0; nj < 8; nj++) {
            int n = bn + wn + nj * 8 + fc;
            float2 bvv = *reinterpret_cast<const float2*>(bias + n);
            #pragma unroll
            for (int half = 0; half < 2; half++) {
                int m = bm + wm + mi * 16 + fr + half * 8;
                float2 o;
                o.x = acc[mi][nj][half * 2 + 0] + bvv.x;
                o.y = acc[mi][nj][half * 2 + 1] + bvv.y;
                *reinterpret_cast<float2*>(Cout + (size_t)m * DMODEL + n) = o;
            }
        }
}

// ============================================================================
// Tensor-core flash attention, 3-stage cp.async K/V pipeline.
// Term-major mma ordering (chains spaced by 8 independents).
// ============================================================================
#define ASTAGE    36864
#define ATTN_SMEM (3 * ASTAGE)

__global__ __launch_bounds__(256) void attn_mma()
{
    extern __shared__ __align__(16) char dsm[];
    const uint32_t SB = smem_u32(dsm);

    const int tid = threadIdx.x;
    const int wid = tid >> 5;
    const int lid = tid & 31;
    const int hh = blockIdx.y;
    const int b  = blockIdx.z;
    const int qb = blockIdx.x * 128;
    const int wq = wid * 16;
    const int cnt = g_cnt[b];

    const size_t hb = ((size_t)(b * NHEADS + hh)) * SEQ * HDIM;
    const uint4* Qh4 = reinterpret_cast<const uint4*>(g_Qh + hb + (size_t)qb * HDIM);
    const uint4* Ql4 = reinterpret_cast<const uint4*>(g_Ql + hb + (size_t)qb * HDIM);
    const uint4* Kh4 = reinterpret_cast<const uint4*>(g_Kh + hb);
    const uint4* Kl4 = reinterpret_cast<const uint4*>(g_Kl + hb);
    const uint4* Vh4 = reinterpret_cast<const uint4*>(g_Vh + hb);
    const uint4* Vl4 = reinterpret_cast<const uint4*>(g_Vl + hb);

    uint4* sb4 = reinterpret_cast<uint4*>(dsm);
    #pragma unroll
    for (int j = 0; j < 4; j++) {
        int idx = tid + 256 * j;
        int r = idx >> 3, q = idx & 7;
        sb4[9 * r + q]        = Qh4[r * 8 + q];
        sb4[1152 + 9 * r + q] = Ql4[r * 8 + q];
    }
    __syncthreads();

    uint32_t qfh[4][4], qfl[4][4];
    {
        const int arow = wq + (lid & 7) + ((lid >> 3) & 1) * 8;
        const int akoff = (lid >> 4) * 8;
        #pragma unroll
        for (int ks = 0; ks < 4; ks++) {
            uint32_t ad = SB + (uint32_t)(arow * 72 + ks * 16 + akoff) * 2;
            ldsm_x4(qfh[ks][0], qfh[ks][1], qfh[ks][2], qfh[ks][3], ad);
            ldsm_x4(qfl[ks][0], qfl[ks][1], qfl[ks][2], qfl[ks][3], ad + 18432);
        }
    }
    __syncthreads();

    const int ntl = (cnt + 63) >> 6;

    auto load_tile = [&](int kt, int st) {
        const uint32_t base = SB + st * ASTAGE;
        #pragma unroll
        for (int j = 0; j < 2; j++) {
            int idx = tid + 256 * j;
            int r = idx >> 3, q = idx & 7;
            uint32_t so = base + (uint32_t)(r * 144 + q * 16);
            int gi = (kt * 64 + r) * 8 + q;
            cp16(so,         Kh4 + gi);
            cp16(so + 9216,  Kl4 + gi);
            cp16(so + 18432, Vh4 + gi);
            cp16(so + 27648, Vl4 + gi);
        }
    };

    float oacc[8][4];
    #pragma unroll
    for (int ng = 0; ng < 8; ng++)
        #pragma unroll
        for (int r = 0; r < 4; r++) oacc[ng][r] = 0.f;

    float mrow0 = NEGI, mrow1 = NEGI, lrow0 = 0.f, lrow1 = 0.f;

    const int brow = (lid & 7) + ((lid >> 4) & 1) * 8;
    const int bko  = ((lid >> 3) & 1) * 8;
    const int vrow = lid & 15;
    const int vco  = (lid >> 4) * 8;
    const int fc   = (lid & 3) * 2;

    load_tile(0, 0); CP_COMMIT();
    if (ntl > 1) { load_tile(1, 1); CP_COMMIT(); }

    int st = 0;
    for (int kt = 0; kt < ntl; kt++) {
        if (kt + 1 < ntl) CP_WAIT1(); else CP_WAIT0();
        __syncthreads();
        if (kt + 2 < ntl) {
            int st2 = st + 2; if (st2 >= 3) st2 -= 3;
            load_tile(kt + 2, st2); CP_COMMIT();
        }
        const uint32_t SBS = SB + st * ASTAGE;

        float sacc[8][4];
        #pragma unroll
        for (int nt = 0; nt < 8; nt++)
            #pragma unroll
            for (int r = 0; r < 4; r++) sacc[nt][r] = 0.f;

        #pragma unroll
        for (int ks = 0; ks < 4; ks++) {
            uint32_t kh[8][2], kl[8][2];
            #pragma unroll
            for (int p = 0; p < 4; p++) {
                uint32_t r0, r1, r2, r3;
                uint32_t ad = SBS + (uint32_t)((p * 16 + brow) * 72 + ks * 16 + bko) * 2;
                ldsm_x4(r0, r1, r2, r3, ad);
                kh[p * 2][0] = r0; kh[p * 2][1] = r1;
                kh[p * 2 + 1][0] = r2; kh[p * 2 + 1][1] = r3;
                ldsm_x4(r0, r1, r2, r3, ad + 9216);
                kl[p * 2][0] = r0; kl[p * 2][1] = r1;
                kl[p * 2 + 1][0] = r2; kl[p * 2 + 1][1] = r3;
            }
            // term-major
            #pragma unroll
            for (int nt = 0; nt < 8; nt++) mma_bf16(sacc[nt], qfh[ks], kh[nt][0], kh[nt][1]);
            #pragma unroll
            for (int nt = 0; nt < 8; nt++) mma_bf16(sacc[nt], qfh[ks], kl[nt][0], kl[nt][1]);
            #pragma unroll
            for (int nt = 0; nt < 8; nt++) mma_bf16(sacc[nt], qfl[ks], kh[nt][0], kh[nt][1]);
        }

        const int key0 = kt * 64 + fc;
        float tm0 = NEGI, tm1 = NEGI;
        #pragma unroll
        for (int nt = 0; nt < 8; nt++) {
            bool v0 = (key0 + nt * 8) < cnt;
            bool v1 = (key0 + nt * 8 + 1) < cnt;
            if (!v0) { sacc[nt][0] = NEGI; sacc[nt][2] = NEGI; }
            if (!v1) { sacc[nt][1] = NEGI; sacc[nt][3] = NEGI; }
            tm0 = fmaxf(tm0, fmaxf(sacc[nt][0], sacc[nt][1]));
            tm1 = fmaxf(tm1, fmaxf(sacc[nt][2], sacc[nt][3]));
        }
        tm0 = fmaxf(tm0, __shfl_xor_sync(0xffffffffu, tm0, 1));
        tm0 = fmaxf(tm0, __shfl_xor_sync(0xffffffffu, tm0, 2));
        tm1 = fmaxf(tm1, __shfl_xor_sync(0xffffffffu, tm1, 1));
        tm1 = fmaxf(tm1, __shfl_xor_sync(0xffffffffu, tm1, 2));

        const float mn0 = fmaxf(mrow0, tm0), mn1 = fmaxf(mrow1, tm1);
        const float c0 = ex2(mrow0 - mn0), c1 = ex2(mrow1 - mn1);
        mrow0 = mn0; mrow1 = mn1;

        uint32_t pah[4][4], pal[4][4];
        float ls0 = 0.f, ls1 = 0.f;
        #pragma unroll
        for (int nt = 0; nt < 8; nt++) {
            float p0 = ex2(sacc[nt][0] - mn0), p1 = ex2(sacc[nt][1] - mn0);
            float p2 = ex2(sacc[nt][2] - mn1), p3 = ex2(sacc[nt][3] - mn1);
            ls0 += p0 + p1; ls1 += p2 + p3;
            float h0 = rb(p0), h1 = rb(p1), h2 = rb(p2), h3 = rb(p3);
            int kc = nt >> 1, o2 = (nt & 1) * 2;
            pah[kc][o2 + 0] = pack2(p0, p1);
            pah[kc][o2 + 1] = pack2(p2, p3);
            pal[kc][o2 + 0] = pack2(p0 - h0, p1 - h1);
            pal[kc][o2 + 1] = pack2(p2 - h2, p3 - h3);
        }
        lrow0 = lrow0 * c0 + ls0;
        lrow1 = lrow1 * c1 + ls1;
        #pragma unroll
        for (int ng = 0; ng < 8; ng++) {
            oacc[ng][0] *= c0; oacc[ng][1] *= c0;
            oacc[ng][2] *= c1; oacc[ng][3] *= c1;
        }

        #pragma unroll
        for (int kc = 0; kc < 4; kc++) {
            uint32_t vh[8][2], vl[8][2];
            #pragma unroll
            for (int p = 0; p < 4; p++) {
                uint32_t r0, r1, r2, r3;
                uint32_t ad = SBS + 18432 + (uint32_t)((kc * 16 + vrow) * 72 + p * 16 + vco) * 2;
                ldsm_x4t(r0, r1, r2, r3, ad);
                vh[p * 2][0] = r0; vh[p * 2][1] = r1;
                vh[p * 2 + 1][0] = r2; vh[p * 2 + 1][1] = r3;
                ldsm_x4t(r0, r1, r2, r3, ad + 9216);
                vl[p * 2][0] = r0; vl[p * 2][1] = r1;
                vl[p * 2 + 1][0] = r2; vl[p * 2 + 1][1] = r3;
            }
            // term-major
            #pragma unroll
            for (int ng = 0; ng < 8; ng++) mma_bf16(oacc[ng], pah[kc], vh[ng][0], vh[ng][1]);
            #pragma unroll
            for (int ng = 0; ng < 8; ng++) mma_bf16(oacc[ng], pah[kc], vl[ng][0], vl[ng][1]);
            #pragma unroll
            for (int ng = 0; ng < 8; ng++) mma_bf16(oacc[ng], pal[kc], vh[ng][0], vh[ng][1]);
        }
        if (++st == 3) st = 0;
    }

    lrow0 += __shfl_xor_sync(0xffffffffu, lrow0, 1);
    lrow0 += __shfl_xor_sync(0xffffffffu, lrow0, 2);
    lrow1 += __shfl_xor_sync(0xffffffffu, lrow1, 1);
    lrow1 += __shfl_xor_sync(0xffffffffu, lrow1, 2);

    const float inv0 = 1.0f / lrow0;
    const float inv1 = 1.0f / lrow1;
    const int r0 = qb + wq + (lid >> 2);
    const int r1 = r0 + 8;
    #pragma unroll
    for (int ng = 0; ng < 8; ng++) {
        int col = hh * HDIM + ng * 8 + fc;
        float a0 = oacc[ng][0] * inv0, a1 = oacc[ng][1] * inv0;
        float a2 = oacc[ng][2] * inv1, a3 = oacc[ng][3] * inv1;
        size_t off0 = ((size_t)(b * SEQ + r0)) * DMODEL + col;
        size_t off1 = ((size_t)(b * SEQ + r1)) * DMODEL + col;
        float h0 = rb(a0), h1 = rb(a1), h2 = rb(a2), h3 = rb(a3);
        *reinterpret_cast<uint32_t*>(g_Ch + off0) = pack2(a0, a1);
        *reinterpret_cast<uint32_t*>(g_Cl + off0) = pack2(a0 - h0, a1 - h1);
        *reinterpret_cast<uint32_t*>(g_Ch + off1) = pack2(a2, a3);
        *reinterpret_cast<uint32_t*>(g_Cl + off1) = pack2(a2 - h2, a3 - h3);
    }
}

// ============================================================================
// Launch
// ============================================================================
extern "C" void kernel_launch(void* const* d_in, const int* in_sizes, int n_in,
                              void* d_out, int out_size)
{
    const float* query = (const float*)d_in[0];
    const float* key   = (const float*)d_in[1];
    const float* value = (const float*)d_in[2];
    const int*   mask  = (const int*)  d_in[3];
    const float* Wq    = (const float*)d_in[4];
    const float* bq    = (const float*)d_in[5];
    const float* Wk    = (const float*)d_in[6];
    const float* bk    = (const float*)d_in[7];
    const float* Wv    = (const float*)d_in[8];
    const float* bv    = (const float*)d_in[9];
    const float* Wo    = (const float*)d_in[10];
    const float* bo    = (const float*)d_in[11];
    float* out = (float*)d_out;

    static bool attr_done = false;
    if (!attr_done) {
        cudaFuncSetAttribute(gemm_qkv, cudaFuncAttributeMaxDynamicSharedMemorySize, GEMM_SMEM);
        cudaFuncSetAttribute(gemm_o,   cudaFuncAttributeMaxDynamicSharedMemorySize, GEMM_SMEM);
        cudaFuncSetAttribute(attn_mma, cudaFuncAttributeMaxDynamicSharedMemorySize, ATTN_SMEM);
        attr_done = true;
    }

    const int nx4 = MTOT * DMODEL / 4;
    const int nw4 = DMODEL * DMODEL / 4;

    compact_mask<<<BATCH, 1024>>>(mask);
    convert_all<<<dim3(nx4 / 256, 7), 256>>>((const float4*)query, (const float4*)key,
                                             (const float4*)value,
                                             (const float4*)Wq, (const float4*)Wk,
                                             (const float4*)Wv, (const float4*)Wo,
                                             nx4, nw4);

    dim3 qkvGrid(DMODEL / 128, MTOT / 128, 3);   // (8, 64, 3)
    gemm_qkv<<<qkvGrid, 256, GEMM_SMEM>>>(bq, bk, bv);

    dim3 attnGrid(SEQ / 128, NHEADS, BATCH);     // (16, 16, 4)
    attn_mma<<<attnGrid, 256, ATTN_SMEM>>>();

    dim3 oGrid(DMODEL / 128, MTOT / 128);        // (8, 64)
    gemm_o<<<oGrid, 256, GEMM_SMEM>>>(bo, out);
}

// round 15
// speedup vs baseline: 4.6647x; 1.0472x over previous
#include <cuda_runtime.h>
#include <cuda_bf16.h>
#include <cstdint>

#define BATCH  4
#define SEQ    2048
#define DMODEL 1024
#define NHEADS 16
#define HDIM   64
#define MTOT   (BATCH * SEQ)          // 8192
#define QSCALE 0.1803368801111204f   // 1/sqrt(HDIM) * log2(e)
#define NEGI   -1e30f

// ---- scratch (device globals; no allocation) ----
__device__ __nv_bfloat16 g_Xh[3][MTOT * DMODEL];
__device__ __nv_bfloat16 g_Xl[3][MTOT * DMODEL];
__device__ __nv_bfloat16 g_Wh[4][DMODEL * DMODEL];
__device__ __nv_bfloat16 g_Wl[4][DMODEL * DMODEL];
__device__ __nv_bfloat16 g_Qh[MTOT * DMODEL], g_Ql[MTOT * DMODEL]; // (B,H,S,Dh), scaled
__device__ __nv_bfloat16 g_Kh[MTOT * DMODEL], g_Kl[MTOT * DMODEL]; // compacted
__device__ __nv_bfloat16 g_Vh[MTOT * DMODEL], g_Vl[MTOT * DMODEL]; // compacted
__device__ __nv_bfloat16 g_Ch[MTOT * DMODEL], g_Cl[MTOT * DMODEL]; // ctx (B,S,D)
__device__ int g_inv[BATCH * SEQ];   // compact pos -> source row
__device__ int g_cnt[BATCH];

// ============================================================================
// Helpers
// ============================================================================
__device__ __forceinline__ uint32_t smem_u32(const void* p) {
    uint32_t a;
    asm("{ .reg .u64 t; cvta.to.shared.u64 t, %1; cvt.u32.u64 %0, t; }"
        : "=r"(a) : "l"(p));
    return a;
}

__device__ __forceinline__ void ldsm_x4(uint32_t& r0, uint32_t& r1,
                                        uint32_t& r2, uint32_t& r3, uint32_t addr) {
    asm volatile("ldmatrix.sync.aligned.m8n8.x4.shared.b16 {%0,%1,%2,%3}, [%4];"
                 : "=r"(r0), "=r"(r1), "=r"(r2), "=r"(r3) : "r"(addr));
}

__device__ __forceinline__ void ldsm_x4t(uint32_t& r0, uint32_t& r1,
                                         uint32_t& r2, uint32_t& r3, uint32_t addr) {
    asm volatile("ldmatrix.sync.aligned.m8n8.x4.trans.shared.b16 {%0,%1,%2,%3}, [%4];"
                 : "=r"(r0), "=r"(r1), "=r"(r2), "=r"(r3) : "r"(addr));
}

__device__ __forceinline__ void mma_bf16(float* c,
                                         const uint32_t* a,
                                         uint32_t b0, uint32_t b1) {
    asm volatile(
        "mma.sync.aligned.m16n8k16.row.col.f32.bf16.bf16.f32 "
        "{%0,%1,%2,%3}, {%4,%5,%6,%7}, {%8,%9}, {%0,%1,%2,%3};"
        : "+f"(c[0]), "+f"(c[1]), "+f"(c[2]), "+f"(c[3])
        : "r"(a[0]), "r"(a[1]), "r"(a[2]), "r"(a[3]), "r"(b0), "r"(b1));
}

__device__ __forceinline__ uint32_t pack2(float x, float y) {
    __nv_bfloat162 t = __floats2bfloat162_rn(x, y);
    return *reinterpret_cast<uint32_t*>(&t);
}
__device__ __forceinline__ float rb(float x) {
    return __bfloat162float(__float2bfloat16(x));
}
__device__ __forceinline__ float ex2(float x) {
    float r;
    asm("ex2.approx.f32 %0, %1;" : "=f"(r) : "f"(x));
    return r;
}
__device__ __forceinline__ void cp16(uint32_t dst, const void* src) {
    asm volatile("cp.async.cg.shared.global [%0], [%1], 16;" :: "r"(dst), "l"(src));
}
#define CP_COMMIT() asm volatile("cp.async.commit_group;" ::: "memory")
#define CP_WAIT1()  asm volatile("cp.async.wait_group 1;" ::: "memory")
#define CP_WAIT0()  asm volatile("cp.async.wait_group 0;" ::: "memory")

// ============================================================================
// Mask compaction
// ============================================================================
__global__ void compact_mask(const int* __restrict__ mask) {
    __shared__ int ssum[1024];
    const int b = blockIdx.x, t = threadIdx.x;
    const int* mb = mask + b * SEQ;
    const int m0 = mb[2 * t] != 0, m1 = mb[2 * t + 1] != 0;
    ssum[t] = m0 + m1;
    __syncthreads();
    for (int off = 1; off < 1024; off <<= 1) {
        int v = (t >= off) ? ssum[t - off] : 0;
        __syncthreads();
        ssum[t] += v;
        __syncthreads();
    }
    const int excl = (t > 0) ? ssum[t - 1] : 0;
    if (m0) g_inv[b * SEQ + excl]      = 2 * t;
    if (m1) g_inv[b * SEQ + excl + m0] = 2 * t + 1;
    if (t == 1023) g_cnt[b] = ssum[1023];
}

// ============================================================================
// fp32 -> bf16 hi/lo splits, single launch (kinds 0-2 acts, 3-6 weights)
// ============================================================================
__global__ void convert_all(const float4* __restrict__ q,
                            const float4* __restrict__ k,
                            const float4* __restrict__ v,
                            const float4* __restrict__ wq,
                            const float4* __restrict__ wk,
                            const float4* __restrict__ wv,
                            const float4* __restrict__ wo,
                            int nx4, int nw4) {
    const int kind = blockIdx.y;
    const int i = blockIdx.x * blockDim.x + threadIdx.x;
    const float4* src;
    __nv_bfloat16 *H, *L;
    if (kind < 3) {
        if (i >= nx4) return;
        src = (kind == 0) ? q : (kind == 1) ? k : v;
        H = g_Xh[kind]; L = g_Xl[kind];
    } else {
        if (i >= nw4) return;
        src = (kind == 3) ? wq : (kind == 4) ? wk : (kind == 5) ? wv : wo;
        H = g_Wh[kind - 3]; L = g_Wl[kind - 3];
    }
    const float4 val = src[i];
    const float h0 = rb(val.x), h1 = rb(val.y), h2 = rb(val.z), h3 = rb(val.w);
    uint2 uh, ul;
    uh.x = pack2(val.x, val.y); uh.y = pack2(val.z, val.w);
    ul.x = pack2(val.x - h0, val.y - h1); ul.y = pack2(val.z - h2, val.w - h3);
    reinterpret_cast<uint2*>(H)[i] = uh;
    reinterpret_cast<uint2*>(L)[i] = ul;
}

// ============================================================================
// GEMM mainloop core.  Block 128x128, warp tile 32x64, BK=32, 2-stage cp.async.
// Term-major mma ordering.  Stage (40960 B): Ah/Al/Bh/Bl.
// ============================================================================
#define SA_STRIDE 40
#define GSTAGE    40960
#define GEMM_SMEM (2 * GSTAGE)

struct GemmCtx {
    const __nv_bfloat16 *Ah, *Al, *Wh, *Wl;
    size_t aoff0, aoff1, boff0, boff1;   // uint4 indices (per-thread)
};

__device__ __forceinline__ void gemm_mainloop(
    const GemmCtx& cx, uint32_t SBASE, int tid, int lid, int wm, int wn,
    float acc[2][8][4])
{
    const uint4* A4h = reinterpret_cast<const uint4*>(cx.Ah);
    const uint4* A4l = reinterpret_cast<const uint4*>(cx.Al);
    const uint4* W4h = reinterpret_cast<const uint4*>(cx.Wh);
    const uint4* W4l = reinterpret_cast<const uint4*>(cx.Wl);

    const int lr0 = tid >> 2;
    const int lq  = tid & 3;
    const uint32_t dA0 = (uint32_t)(lr0 * SA_STRIDE + lq * 8) * 2;
    const uint32_t dA1 = dA0 + (uint32_t)64 * SA_STRIDE * 2;

    auto stage_load = [&](int ch, int st) {
        const uint32_t a_h = SBASE + st * GSTAGE;
        const uint32_t a_l = a_h + 10240;
        const uint32_t b_h = a_h + 20480;
        const uint32_t b_l = a_h + 30720;
        cp16(a_h + dA0, A4h + cx.aoff0 + ch * 4);
        cp16(a_h + dA1, A4h + cx.aoff1 + ch * 4);
        cp16(a_l + dA0, A4l + cx.aoff0 + ch * 4);
        cp16(a_l + dA1, A4l + cx.aoff1 + ch * 4);
        cp16(b_h + dA0, W4h + cx.boff0 + ch * 4);
        cp16(b_h + dA1, W4h + cx.boff1 + ch * 4);
        cp16(b_l + dA0, W4l + cx.boff0 + ch * 4);
        cp16(b_l + dA1, W4l + cx.boff1 + ch * 4);
    };

    const int a_row = wm + ((lid >> 3) & 1) * 8 + (lid & 7);
    const uint32_t a_koff = ((lid >> 4) * 8) * 2;
    const int b_row = wn + ((lid >> 4) & 1) * 8 + (lid & 7);
    const uint32_t b_koff = (((lid >> 3) & 1) * 8) * 2;

    stage_load(0, 0); CP_COMMIT();
    stage_load(1, 1); CP_COMMIT();

    for (int ch = 0; ch < 32; ch++) {
        const int st = ch & 1;
        if (ch < 31) CP_WAIT1(); else CP_WAIT0();
        __syncthreads();

        const uint32_t sAh_base = SBASE + st * GSTAGE;
        const uint32_t sAl_base = sAh_base + 10240;
        const uint32_t sBh_base = sAh_base + 20480;
        const uint32_t sBl_base = sAh_base + 30720;

        #pragma unroll
        for (int ks = 0; ks < 2; ks++) {
            const uint32_t kbyte = ks * 32;
            uint32_t ah[2][4], al[2][4];
            #pragma unroll
            for (int mi = 0; mi < 2; mi++) {
                uint32_t ad = sAh_base + (uint32_t)(a_row + mi * 16) * (SA_STRIDE * 2) + kbyte + a_koff;
                ldsm_x4(ah[mi][0], ah[mi][1], ah[mi][2], ah[mi][3], ad);
                uint32_t ad2 = sAl_base + (uint32_t)(a_row + mi * 16) * (SA_STRIDE * 2) + kbyte + a_koff;
                ldsm_x4(al[mi][0], al[mi][1], al[mi][2], al[mi][3], ad2);
            }
            #pragma unroll
            for (int p = 0; p < 4; p++) {
                uint32_t bh0, bh1, bh2, bh3, bl0, bl1, bl2, bl3;
                uint32_t bd = sBh_base + (uint32_t)(b_row + p * 16) * (SA_STRIDE * 2) + kbyte + b_koff;
                ldsm_x4(bh0, bh1, bh2, bh3, bd);
                uint32_t bd2 = sBl_base + (uint32_t)(b_row + p * 16) * (SA_STRIDE * 2) + kbyte + b_koff;
                ldsm_x4(bl0, bl1, bl2, bl3, bd2);
                #pragma unroll
                for (int mi = 0; mi < 2; mi++) {
                    mma_bf16(acc[mi][2 * p],     ah[mi], bh0, bh1);
                    mma_bf16(acc[mi][2 * p + 1], ah[mi], bh2, bh3);
                }
                #pragma unroll
                for (int mi = 0; mi < 2; mi++) {
                    mma_bf16(acc[mi][2 * p],     ah[mi], bl0, bl1);
                    mma_bf16(acc[mi][2 * p + 1], ah[mi], bl2, bl3);
                }
                #pragma unroll
                for (int mi = 0; mi < 2; mi++) {
                    mma_bf16(acc[mi][2 * p],     al[mi], bh0, bh1);
                    mma_bf16(acc[mi][2 * p + 1], al[mi], bh2, bh3);
                }
            }
        }
        __syncthreads();
        if (ch + 2 < 32) { stage_load(ch + 2, st); CP_COMMIT(); }
    }
}

// ============================================================================
// Merged Q/K/V projection GEMM. blockIdx.z = kind (0=Q,1=K,2=V).
// ============================================================================
__global__ __launch_bounds__(256, 2) void gemm_qkv(
    const float* __restrict__ bq,
    const float* __restrict__ bk,
    const float* __restrict__ bv)
{
    extern __shared__ __align__(16) char dsm[];
    const uint32_t SBASE = smem_u32(dsm);

    const int kind = blockIdx.z;
    const int tid = threadIdx.x;
    const int wid = tid >> 5;
    const int lid = tid & 31;
    const int bn = blockIdx.x * 128;
    const int wm = (wid >> 1) * 32;
    const int wn = (wid & 1) * 64;

    int bm = 0, bb = 0, tile = 0, cnt = 0;
    if (kind >= 1) {
        bb   = blockIdx.y >> 4;
        tile = blockIdx.y & 15;
        cnt  = g_cnt[bb];
        if (tile * 128 >= cnt) return;
    } else {
        bm = blockIdx.y * 128;
    }

    GemmCtx cx;
    cx.Ah = g_Xh[kind]; cx.Al = g_Xl[kind];
    cx.Wh = g_Wh[kind]; cx.Wl = g_Wl[kind];

    const int lr0 = tid >> 2;
    const int lq  = tid & 3;
    if (kind >= 1) {
        int p0 = tile * 128 + lr0;
        int p1 = p0 + 64;
        int s0 = (p0 < cnt) ? g_inv[bb * SEQ + p0] : 0;
        int s1 = (p1 < cnt) ? g_inv[bb * SEQ + p1] : 0;
        cx.aoff0 = ((size_t)(bb * SEQ + s0)) * 128 + lq;
        cx.aoff1 = ((size_t)(bb * SEQ + s1)) * 128 + lq;
    } else {
        cx.aoff0 = (size_t)(bm + lr0) * 128 + lq;
        cx.aoff1 = cx.aoff0 + (size_t)64 * 128;
    }
    cx.boff0 = (size_t)(bn + lr0) * 128 + lq;
    cx.boff1 = cx.boff0 + (size_t)64 * 128;

    float acc[2][8][4];
    #pragma unroll
    for (int i = 0; i < 2; i++)
        #pragma unroll
        for (int j = 0; j < 8; j++)
            #pragma unroll
            for (int r = 0; r < 4; r++) acc[i][j][r] = 0.f;

    gemm_mainloop(cx, SBASE, tid, lid, wm, wn, acc);

    // ---- epilogue ----
    const float* bias = (kind == 0) ? bq : (kind == 1) ? bk : bv;
    const int fr = lid >> 2;
    const int fc = (lid & 3) * 2;

    #pragma unroll
    for (int mi = 0; mi < 2; mi++)
        #pragma unroll
        for (int nj = 0; nj < 8; nj++) {
            int n = bn + wn + nj * 8 + fc;
            float2 bvv = *reinterpret_cast<const float2*>(bias + n);
            #pragma unroll
            for (int half = 0; half < 2; half++) {
                float ox = acc[mi][nj][half * 2 + 0] + bvv.x;
                float oy = acc[mi][nj][half * 2 + 1] + bvv.y;
                int hh = n >> 6;
                int dh = n & (HDIM - 1);
                if (kind == 0) {
                    int m = bm + wm + mi * 16 + fr + half * 8;
                    int b  = m >> 11;
                    int s  = m & (SEQ - 1);
                    ox *= QSCALE; oy *= QSCALE;
                    size_t off = (((size_t)(b * NHEADS + hh)) * SEQ + s) * HDIM + dh;
                    float hx = rb(ox), hy = rb(oy);
                    *reinterpret_cast<uint32_t*>(g_Qh + off) = pack2(ox, oy);
                    *reinterpret_cast<uint32_t*>(g_Ql + off) = pack2(ox - hx, oy - hy);
                } else {
                    int pos = tile * 128 + wm + mi * 16 + fr + half * 8;
                    if (pos < cnt) {
                        size_t off = (((size_t)(bb * NHEADS + hh)) * SEQ + pos) * HDIM + dh;
                        float hx = rb(ox), hy = rb(oy);
                        if (kind == 1) {
                            *reinterpret_cast<uint32_t*>(g_Kh + off) = pack2(ox, oy);
                            *reinterpret_cast<uint32_t*>(g_Kl + off) = pack2(ox - hx, oy - hy);
                        } else {
                            *reinterpret_cast<uint32_t*>(g_Vh + off) = pack2(ox, oy);
                            *reinterpret_cast<uint32_t*>(g_Vl + off) = pack2(ox - hx, oy - hy);
                        }
                    }
                }
            }
        }
}

// ============================================================================
// Output projection GEMM: A = g_Ch/g_Cl, C = fp32 row-major.
// ============================================================================
__global__ __launch_bounds__(256, 2) void gemm_o(
    const float* __restrict__ bias,
    float* __restrict__ Cout)
{
    extern __shared__ __align__(16) char dsm[];
    const uint32_t SBASE = smem_u32(dsm);

    const int tid = threadIdx.x;
    const int wid = tid >> 5;
    const int lid = tid & 31;
    const int bn = blockIdx.x * 128;
    const int bm = blockIdx.y * 128;
    const int wm = (wid >> 1) * 32;
    const int wn = (wid & 1) * 64;

    GemmCtx cx;
    cx.Ah = g_Ch; cx.Al = g_Cl;
    cx.Wh = g_Wh[3]; cx.Wl = g_Wl[3];

    const int lr0 = tid >> 2;
    const int lq  = tid & 3;
    cx.aoff0 = (size_t)(bm + lr0) * 128 + lq;
    cx.aoff1 = cx.aoff0 + (size_t)64 * 128;
    cx.boff0 = (size_t)(bn + lr0) * 128 + lq;
    cx.boff1 = cx.boff0 + (size_t)64 * 128;

    float acc[2][8][4];
    #pragma unroll
    for (int i = 0; i < 2; i++)
        #pragma unroll
        for (int j = 0; j < 8; j++)
            #pragma unroll
            for (int r = 0; r < 4; r++) acc[i][j][r] = 0.f;

    gemm_mainloop(cx, SBASE, tid, lid, wm, wn, acc);

    const int fr = lid >> 2;
    const int fc = (lid & 3) * 2;
    #pragma unroll
    for (int mi = 0; mi < 2; mi++)
        #pragma unroll
        for (int nj = 0; nj < 8; nj++) {
            int n = bn + wn + nj * 8 + fc;
            float2 bvv = *reinterpret_cast<const float2*>(bias + n);
            #pragma unroll
            for (int half = 0; half < 2; half++) {
                int m = bm + wm + mi * 16 + fr + half * 8;
                float2 o;
                o.x = acc[mi][nj][half * 2 + 0] + bvv.x;
                o.y = acc[mi][nj][half * 2 + 1] + bvv.y;
                *reinterpret_cast<float2*>(Cout + (size_t)m * DMODEL + n) = o;
            }
        }
}

// ============================================================================
// Tensor-core flash attention.  2-stage cp.async K/V pipeline, 2 CTAs/SM
// (smem 73728 B, __launch_bounds__(256,2) -> 128 regs).
// Stage (36864 B): +0 Kh(9216) +9216 Kl +18432 Vh +27648 Vl (144B row stride)
// Q staged through stages 0-1 before the pipeline starts.
// ============================================================================
#define ASTAGE    36864
#define ATTN_SMEM (2 * ASTAGE)

__global__ __launch_bounds__(256, 2) void attn_mma()
{
    extern __shared__ __align__(16) char dsm[];
    const uint32_t SB = smem_u32(dsm);

    const int tid = threadIdx.x;
    const int wid = tid >> 5;
    const int lid = tid & 31;
    const int hh = blockIdx.y;
    const int b  = blockIdx.z;
    const int qb = blockIdx.x * 128;
    const int wq = wid * 16;
    const int cnt = g_cnt[b];

    const size_t hb = ((size_t)(b * NHEADS + hh)) * SEQ * HDIM;
    const uint4* Qh4 = reinterpret_cast<const uint4*>(g_Qh + hb + (size_t)qb * HDIM);
    const uint4* Ql4 = reinterpret_cast<const uint4*>(g_Ql + hb + (size_t)qb * HDIM);
    const uint4* Kh4 = reinterpret_cast<const uint4*>(g_Kh + hb);
    const uint4* Kl4 = reinterpret_cast<const uint4*>(g_Kl + hb);
    const uint4* Vh4 = reinterpret_cast<const uint4*>(g_Vh + hb);
    const uint4* Vl4 = reinterpret_cast<const uint4*>(g_Vl + hb);

    uint4* sb4 = reinterpret_cast<uint4*>(dsm);
    #pragma unroll
    for (int j = 0; j < 4; j++) {
        int idx = tid + 256 * j;
        int r = idx >> 3, q = idx & 7;
        sb4[9 * r + q]        = Qh4[r * 8 + q];
        sb4[1152 + 9 * r + q] = Ql4[r * 8 + q];
    }
    __syncthreads();

    uint32_t qfh[4][4], qfl[4][4];
    {
        const int arow = wq + (lid & 7) + ((lid >> 3) & 1) * 8;
        const int akoff = (lid >> 4) * 8;
        #pragma unroll
        for (int ks = 0; ks < 4; ks++) {
            uint32_t ad = SB + (uint32_t)(arow * 72 + ks * 16 + akoff) * 2;
            ldsm_x4(qfh[ks][0], qfh[ks][1], qfh[ks][2], qfh[ks][3], ad);
            ldsm_x4(qfl[ks][0], qfl[ks][1], qfl[ks][2], qfl[ks][3], ad + 18432);
        }
    }
    __syncthreads();

    const int ntl = (cnt + 63) >> 6;

    auto load_tile = [&](int kt, int st) {
        const uint32_t base = SB + st * ASTAGE;
        #pragma unroll
        for (int j = 0; j < 2; j++) {
            int idx = tid + 256 * j;
            int r = idx >> 3, q = idx & 7;
            uint32_t so = base + (uint32_t)(r * 144 + q * 16);
            int gi = (kt * 64 + r) * 8 + q;
            cp16(so,         Kh4 + gi);
            cp16(so + 9216,  Kl4 + gi);
            cp16(so + 18432, Vh4 + gi);
            cp16(so + 27648, Vl4 + gi);
        }
    };

    float oacc[8][4];
    #pragma unroll
    for (int ng = 0; ng < 8; ng++)
        #pragma unroll
        for (int r = 0; r < 4; r++) oacc[ng][r] = 0.f;

    float mrow0 = NEGI, mrow1 = NEGI, lrow0 = 0.f, lrow1 = 0.f;

    const int brow = (lid & 7) + ((lid >> 4) & 1) * 8;
    const int bko  = ((lid >> 3) & 1) * 8;
    const int vrow = lid & 15;
    const int vco  = (lid >> 4) * 8;
    const int fc   = (lid & 3) * 2;

    load_tile(0, 0); CP_COMMIT();
    if (ntl > 1) { load_tile(1, 1); CP_COMMIT(); }

    for (int kt = 0; kt < ntl; kt++) {
        const int st = kt & 1;
        if (kt + 1 < ntl) CP_WAIT1(); else CP_WAIT0();
        __syncthreads();
        const uint32_t SBS = SB + st * ASTAGE;

        float sacc[8][4];
        #pragma unroll
        for (int nt = 0; nt < 8; nt++)
            #pragma unroll
            for (int r = 0; r < 4; r++) sacc[nt][r] = 0.f;

        #pragma unroll
        for (int ks = 0; ks < 4; ks++) {
            uint32_t kh[8][2], kl[8][2];
            #pragma unroll
            for (int p = 0; p < 4; p++) {
                uint32_t r0, r1, r2, r3;
                uint32_t ad = SBS + (uint32_t)((p * 16 + brow) * 72 + ks * 16 + bko) * 2;
                ldsm_x4(r0, r1, r2, r3, ad);
                kh[p * 2][0] = r0; kh[p * 2][1] = r1;
                kh[p * 2 + 1][0] = r2; kh[p * 2 + 1][1] = r3;
                ldsm_x4(r0, r1, r2, r3, ad + 9216);
                kl[p * 2][0] = r0; kl[p * 2][1] = r1;
                kl[p * 2 + 1][0] = r2; kl[p * 2 + 1][1] = r3;
            }
            #pragma unroll
            for (int nt = 0; nt < 8; nt++) mma_bf16(sacc[nt], qfh[ks], kh[nt][0], kh[nt][1]);
            #pragma unroll
            for (int nt = 0; nt < 8; nt++) mma_bf16(sacc[nt], qfh[ks], kl[nt][0], kl[nt][1]);
            #pragma unroll
            for (int nt = 0; nt < 8; nt++) mma_bf16(sacc[nt], qfl[ks], kh[nt][0], kh[nt][1]);
        }

        const int key0 = kt * 64 + fc;
        float tm0 = NEGI, tm1 = NEGI;
        #pragma unroll
        for (int nt = 0; nt < 8; nt++) {
            bool v0 = (key0 + nt * 8) < cnt;
            bool v1 = (key0 + nt * 8 + 1) < cnt;
            if (!v0) { sacc[nt][0] = NEGI; sacc[nt][2] = NEGI; }
            if (!v1) { sacc[nt][1] = NEGI; sacc[nt][3] = NEGI; }
            tm0 = fmaxf(tm0, fmaxf(sacc[nt][0], sacc[nt][1]));
            tm1 = fmaxf(tm1, fmaxf(sacc[nt][2], sacc[nt][3]));
        }
        tm0 = fmaxf(tm0, __shfl_xor_sync(0xffffffffu, tm0, 1));
        tm0 = fmaxf(tm0, __shfl_xor_sync(0xffffffffu, tm0, 2));
        tm1 = fmaxf(tm1, __shfl_xor_sync(0xffffffffu, tm1, 1));
        tm1 = fmaxf(tm1, __shfl_xor_sync(0xffffffffu, tm1, 2));

        const float mn0 = fmaxf(mrow0, tm0), mn1 = fmaxf(mrow1, tm1);
        const float c0 = ex2(mrow0 - mn0), c1 = ex2(mrow1 - mn1);
        mrow0 = mn0; mrow1 = mn1;

        uint32_t pah[4][4], pal[4][4];
        float ls0 = 0.f, ls1 = 0.f;
        #pragma unroll
        for (int nt = 0; nt < 8; nt++) {
            float p0 = ex2(sacc[nt][0] - mn0), p1 = ex2(sacc[nt][1] - mn0);
            float p2 = ex2(sacc[nt][2] - mn1), p3 = ex2(sacc[nt][3] - mn1);
            ls0 += p0 + p1; ls1 += p2 + p3;
            float h0 = rb(p0), h1 = rb(p1), h2 = rb(p2), h3 = rb(p3);
            int kc = nt >> 1, o2 = (nt & 1) * 2;
            pah[kc][o2 + 0] = pack2(p0, p1);
            pah[kc][o2 + 1] = pack2(p2, p3);
            pal[kc][o2 + 0] = pack2(p0 - h0, p1 - h1);
            pal[kc][o2 + 1] = pack2(p2 - h2, p3 - h3);
        }
        lrow0 = lrow0 * c0 + ls0;
        lrow1 = lrow1 * c1 + ls1;
        #pragma unroll
        for (int ng = 0; ng < 8; ng++) {
            oacc[ng][0] *= c0; oacc[ng][1] *= c0;
            oacc[ng][2] *= c1; oacc[ng][3] *= c1;
        }

        #pragma unroll
        for (int kc = 0; kc < 4; kc++) {
            uint32_t vh[8][2], vl[8][2];
            #pragma unroll
            for (int p = 0; p < 4; p++) {
                uint32_t r0, r1, r2, r3;
                uint32_t ad = SBS + 18432 + (uint32_t)((kc * 16 + vrow) * 72 + p * 16 + vco) * 2;
                ldsm_x4t(r0, r1, r2, r3, ad);
                vh[p * 2][0] = r0; vh[p * 2][1] = r1;
                vh[p * 2 + 1][0] = r2; vh[p * 2 + 1][1] = r3;
                ldsm_x4t(r0, r1, r2, r3, ad + 9216);
                vl[p * 2][0] = r0; vl[p * 2][1] = r1;
                vl[p * 2 + 1][0] = r2; vl[p * 2 + 1][1] = r3;
            }
            #pragma unroll
            for (int ng = 0; ng < 8; ng++) mma_bf16(oacc[ng], pah[kc], vh[ng][0], vh[ng][1]);
            #pragma unroll
            for (int ng = 0; ng < 8; ng++) mma_bf16(oacc[ng], pah[kc], vl[ng][0], vl[ng][1]);
            #pragma unroll
            for (int ng = 0; ng < 8; ng++) mma_bf16(oacc[ng], pal[kc], vh[ng][0], vh[ng][1]);
        }
        __syncthreads();
        if (kt + 2 < ntl) { load_tile(kt + 2, st); CP_COMMIT(); }
    }

    lrow0 += __shfl_xor_sync(0xffffffffu, lrow0, 1);
    lrow0 += __shfl_xor_sync(0xffffffffu, lrow0, 2);
    lrow1 += __shfl_xor_sync(0xffffffffu, lrow1, 1);
    lrow1 += __shfl_xor_sync(0xffffffffu, lrow1, 2);

    const float inv0 = 1.0f / lrow0;
    const float inv1 = 1.0f / lrow1;
    const int r0 = qb + wq + (lid >> 2);
    const int r1 = r0 + 8;
    #pragma unroll
    for (int ng = 0; ng < 8; ng++) {
        int col = hh * HDIM + ng * 8 + fc;
        float a0 = oacc[ng][0] * inv0, a1 = oacc[ng][1] * inv0;
        float a2 = oacc[ng][2] * inv1, a3 = oacc[ng][3] * inv1;
        size_t off0 = ((size_t)(b * SEQ + r0)) * DMODEL + col;
        size_t off1 = ((size_t)(b * SEQ + r1)) * DMODEL + col;
        float h0 = rb(a0), h1 = rb(a1), h2 = rb(a2), h3 = rb(a3);
        *reinterpret_cast<uint32_t*>(g_Ch + off0) = pack2(a0, a1);
        *reinterpret_cast<uint32_t*>(g_Cl + off0) = pack2(a0 - h0, a1 - h1);
        *reinterpret_cast<uint32_t*>(g_Ch + off1) = pack2(a2, a3);
        *reinterpret_cast<uint32_t*>(g_Cl + off1) = pack2(a2 - h2, a3 - h3);
    }
}

// ============================================================================
// Launch
// ============================================================================
extern "C" void kernel_launch(void* const* d_in, const int* in_sizes, int n_in,
                              void* d_out, int out_size)
{
    const float* query = (const float*)d_in[0];
    const float* key   = (const float*)d_in[1];
    const float* value = (const float*)d_in[2];
    const int*   mask  = (const int*)  d_in[3];
    const float* Wq    = (const float*)d_in[4];
    const float* bq    = (const float*)d_in[5];
    const float* Wk    = (const float*)d_in[6];
    const float* bk    = (const float*)d_in[7];
    const float* Wv    = (const float*)d_in[8];
    const float* bv    = (const float*)d_in[9];
    const float* Wo    = (const float*)d_in[10];
    const float* bo    = (const float*)d_in[11];
    float* out = (float*)d_out;

    static bool attr_done = false;
    if (!attr_done) {
        cudaFuncSetAttribute(gemm_qkv, cudaFuncAttributeMaxDynamicSharedMemorySize, GEMM_SMEM);
        cudaFuncSetAttribute(gemm_o,   cudaFuncAttributeMaxDynamicSharedMemorySize, GEMM_SMEM);
        cudaFuncSetAttribute(attn_mma, cudaFuncAttributeMaxDynamicSharedMemorySize, ATTN_SMEM);
        attr_done = true;
    }

    const int nx4 = MTOT * DMODEL / 4;
    const int nw4 = DMODEL * DMODEL / 4;

    compact_mask<<<BATCH, 1024>>>(mask);
    convert_all<<<dim3(nx4 / 256, 7), 256>>>((const float4*)query, (const float4*)key,
                                             (const float4*)value,
                                             (const float4*)Wq, (const float4*)Wk,
                                             (const float4*)Wv, (const float4*)Wo,
                                             nx4, nw4);

    dim3 qkvGrid(DMODEL / 128, MTOT / 128, 3);   // (8, 64, 3)
    gemm_qkv<<<qkvGrid, 256, GEMM_SMEM>>>(bq, bk, bv);

    dim3 attnGrid(SEQ / 128, NHEADS, BATCH);     // (16, 16, 4)
    attn_mma<<<attnGrid, 256, ATTN_SMEM>>>();

    dim3 oGrid(DMODEL / 128, MTOT / 128);        // (8, 64)
    gemm_o<<<oGrid, 256, ATTN_SMEM ? GEMM_SMEM : GEMM_SMEM>>>(bo, out);
}

// round 16
// speedup vs baseline: 4.7727x; 1.0231x over previous
#include <cuda_runtime.h>
#include <cuda_bf16.h>
#include <cstdint>

#define BATCH  4
#define SEQ    2048
#define DMODEL 1024
#define NHEADS 16
#define HDIM   64
#define MTOT   (BATCH * SEQ)          // 8192
#define QSCALE 0.1803368801111204f   // 1/sqrt(HDIM) * log2(e)
#define NEGI   -1e30f

// ---- scratch (device globals; no allocation) ----
__device__ __nv_bfloat16 g_Xh[3][MTOT * DMODEL];
__device__ __nv_bfloat16 g_Xl[3][MTOT * DMODEL];
__device__ __nv_bfloat16 g_Wh[4][DMODEL * DMODEL];
__device__ __nv_bfloat16 g_Wl[4][DMODEL * DMODEL];
__device__ __nv_bfloat16 g_Qh[MTOT * DMODEL], g_Ql[MTOT * DMODEL]; // (B,H,S,Dh), scaled
__device__ __nv_bfloat16 g_Kh[MTOT * DMODEL], g_Kl[MTOT * DMODEL]; // compacted
__device__ __nv_bfloat16 g_Vh[MTOT * DMODEL], g_Vl[MTOT * DMODEL]; // compacted
__device__ __nv_bfloat16 g_Ch[MTOT * DMODEL], g_Cl[MTOT * DMODEL]; // ctx (B,S,D)
__device__ int g_inv[BATCH * SEQ];   // compact pos -> source row
__device__ int g_cnt[BATCH];

// ============================================================================
// Helpers
// ============================================================================
__device__ __forceinline__ uint32_t smem_u32(const void* p) {
    uint32_t a;
    asm("{ .reg .u64 t; cvta.to.shared.u64 t, %1; cvt.u32.u64 %0, t; }"
        : "=r"(a) : "l"(p));
    return a;
}

__device__ __forceinline__ void ldsm_x4(uint32_t& r0, uint32_t& r1,
                                        uint32_t& r2, uint32_t& r3, uint32_t addr) {
    asm volatile("ldmatrix.sync.aligned.m8n8.x4.shared.b16 {%0,%1,%2,%3}, [%4];"
                 : "=r"(r0), "=r"(r1), "=r"(r2), "=r"(r3) : "r"(addr));
}

__device__ __forceinline__ void ldsm_x4t(uint32_t& r0, uint32_t& r1,
                                         uint32_t& r2, uint32_t& r3, uint32_t addr) {
    asm volatile("ldmatrix.sync.aligned.m8n8.x4.trans.shared.b16 {%0,%1,%2,%3}, [%4];"
                 : "=r"(r0), "=r"(r1), "=r"(r2), "=r"(r3) : "r"(addr));
}

__device__ __forceinline__ void mma_bf16(float* c,
                                         const uint32_t* a,
                                         uint32_t b0, uint32_t b1) {
    asm volatile(
        "mma.sync.aligned.m16n8k16.row.col.f32.bf16.bf16.f32 "
        "{%0,%1,%2,%3}, {%4,%5,%6,%7}, {%8,%9}, {%0,%1,%2,%3};"
        : "+f"(c[0]), "+f"(c[1]), "+f"(c[2]), "+f"(c[3])
        : "r"(a[0]), "r"(a[1]), "r"(a[2]), "r"(a[3]), "r"(b0), "r"(b1));
}

__device__ __forceinline__ uint32_t pack2(float x, float y) {
    __nv_bfloat162 t = __floats2bfloat162_rn(x, y);
    return *reinterpret_cast<uint32_t*>(&t);
}
// Truncation split: hi = high 16 bits of each fp32 (exact bf16-truncate),
// packed by one PRMT; lo = x - hi is exact in fp32.
__device__ __forceinline__ uint32_t prmt_hi(float x, float y) {
    uint32_t r;
    asm("prmt.b32 %0, %1, %2, 0x7632;" : "=r"(r)
        : "r"(__float_as_uint(x)), "r"(__float_as_uint(y)));
    return r;
}
__device__ __forceinline__ float trunc_hi(float x) {
    return __uint_as_float(__float_as_uint(x) & 0xFFFF0000u);
}
__device__ __forceinline__ float rb(float x) {
    return __bfloat162float(__float2bfloat16(x));
}
__device__ __forceinline__ float ex2(float x) {
    float r;
    asm("ex2.approx.f32 %0, %1;" : "=f"(r) : "f"(x));
    return r;
}
__device__ __forceinline__ void cp16(uint32_t dst, const void* src) {
    asm volatile("cp.async.cg.shared.global [%0], [%1], 16;" :: "r"(dst), "l"(src));
}
#define CP_COMMIT() asm volatile("cp.async.commit_group;" ::: "memory")
#define CP_WAIT1()  asm volatile("cp.async.wait_group 1;" ::: "memory")
#define CP_WAIT0()  asm volatile("cp.async.wait_group 0;" ::: "memory")

// ============================================================================
// Mask compaction
// ============================================================================
__global__ void compact_mask(const int* __restrict__ mask) {
    __shared__ int ssum[1024];
    const int b = blockIdx.x, t = threadIdx.x;
    const int* mb = mask + b * SEQ;
    const int m0 = mb[2 * t] != 0, m1 = mb[2 * t + 1] != 0;
    ssum[t] = m0 + m1;
    __syncthreads();
    for (int off = 1; off < 1024; off <<= 1) {
        int v = (t >= off) ? ssum[t - off] : 0;
        __syncthreads();
        ssum[t] += v;
        __syncthreads();
    }
    const int excl = (t > 0) ? ssum[t - 1] : 0;
    if (m0) g_inv[b * SEQ + excl]      = 2 * t;
    if (m1) g_inv[b * SEQ + excl + m0] = 2 * t + 1;
    if (t == 1023) g_cnt[b] = ssum[1023];
}

// ============================================================================
// fp32 -> bf16 hi/lo truncation splits, 2 float4 per thread for ILP.
// kinds 0-2: activations, 3-6: weights.
// ============================================================================
__device__ __forceinline__ void split_store(__nv_bfloat16* H, __nv_bfloat16* L,
                                            const float4* src, int i) {
    const float4 v = src[i];
    uint2 uh, ul;
    uh.x = prmt_hi(v.x, v.y);
    uh.y = prmt_hi(v.z, v.w);
    ul.x = pack2(v.x - trunc_hi(v.x), v.y - trunc_hi(v.y));
    ul.y = pack2(v.z - trunc_hi(v.z), v.w - trunc_hi(v.w));
    reinterpret_cast<uint2*>(H)[i] = uh;
    reinterpret_cast<uint2*>(L)[i] = ul;
}

__global__ void convert_all(const float4* __restrict__ q,
                            const float4* __restrict__ k,
                            const float4* __restrict__ v,
                            const float4* __restrict__ wq,
                            const float4* __restrict__ wk,
                            const float4* __restrict__ wv,
                            const float4* __restrict__ wo,
                            int nx4, int nw4) {
    const int kind = blockIdx.y;
    const int i = blockIdx.x * blockDim.x + threadIdx.x;
    const float4* src;
    __nv_bfloat16 *H, *L;
    int half;
    if (kind < 3) {
        half = nx4 >> 1;
        if (i >= half) return;
        src = (kind == 0) ? q : (kind == 1) ? k : v;
        H = g_Xh[kind]; L = g_Xl[kind];
    } else {
        half = nw4 >> 1;
        if (i >= half) return;
        src = (kind == 3) ? wq : (kind == 4) ? wk : (kind == 5) ? wv : wo;
        H = g_Wh[kind - 3]; L = g_Wl[kind - 3];
    }
    split_store(H, L, src, i);
    split_store(H, L, src, i + half);
}

// ============================================================================
// GEMM mainloop core.  Block 128x128, warp tile 32x64, BK=32, 2-stage cp.async.
// Term-major mma ordering.  Stage (40960 B): Ah/Al/Bh/Bl.
// ============================================================================
#define SA_STRIDE 40
#define GSTAGE    40960
#define GEMM_SMEM (2 * GSTAGE)

struct GemmCtx {
    const __nv_bfloat16 *Ah, *Al, *Wh, *Wl;
    size_t aoff0, aoff1, boff0, boff1;   // uint4 indices (per-thread)
};

__device__ __forceinline__ void gemm_mainloop(
    const GemmCtx& cx, uint32_t SBASE, int tid, int lid, int wm, int wn,
    float acc[2][8][4])
{
    const uint4* A4h = reinterpret_cast<const uint4*>(cx.Ah);
    const uint4* A4l = reinterpret_cast<const uint4*>(cx.Al);
    const uint4* W4h = reinterpret_cast<const uint4*>(cx.Wh);
    const uint4* W4l = reinterpret_cast<const uint4*>(cx.Wl);

    const int lr0 = tid >> 2;
    const int lq  = tid & 3;
    const uint32_t dA0 = (uint32_t)(lr0 * SA_STRIDE + lq * 8) * 2;
    const uint32_t dA1 = dA0 + (uint32_t)64 * SA_STRIDE * 2;

    auto stage_load = [&](int ch, int st) {
        const uint32_t a_h = SBASE + st * GSTAGE;
        const uint32_t a_l = a_h + 10240;
        const uint32_t b_h = a_h + 20480;
        const uint32_t b_l = a_h + 30720;
        cp16(a_h + dA0, A4h + cx.aoff0 + ch * 4);
        cp16(a_h + dA1, A4h + cx.aoff1 + ch * 4);
        cp16(a_l + dA0, A4l + cx.aoff0 + ch * 4);
        cp16(a_l + dA1, A4l + cx.aoff1 + ch * 4);
        cp16(b_h + dA0, W4h + cx.boff0 + ch * 4);
        cp16(b_h + dA1, W4h + cx.boff1 + ch * 4);
        cp16(b_l + dA0, W4l + cx.boff0 + ch * 4);
        cp16(b_l + dA1, W4l + cx.boff1 + ch * 4);
    };

    const int a_row = wm + ((lid >> 3) & 1) * 8 + (lid & 7);
    const uint32_t a_koff = ((lid >> 4) * 8) * 2;
    const int b_row = wn + ((lid >> 4) & 1) * 8 + (lid & 7);
    const uint32_t b_koff = (((lid >> 3) & 1) * 8) * 2;

    stage_load(0, 0); CP_COMMIT();
    stage_load(1, 1); CP_COMMIT();

    for (int ch = 0; ch < 32; ch++) {
        const int st = ch & 1;
        if (ch < 31) CP_WAIT1(); else CP_WAIT0();
        __syncthreads();

        const uint32_t sAh_base = SBASE + st * GSTAGE;
        const uint32_t sAl_base = sAh_base + 10240;
        const uint32_t sBh_base = sAh_base + 20480;
        const uint32_t sBl_base = sAh_base + 30720;

        #pragma unroll
        for (int ks = 0; ks < 2; ks++) {
            const uint32_t kbyte = ks * 32;
            uint32_t ah[2][4], al[2][4];
            #pragma unroll
            for (int mi = 0; mi < 2; mi++) {
                uint32_t ad = sAh_base + (uint32_t)(a_row + mi * 16) * (SA_STRIDE * 2) + kbyte + a_koff;
                ldsm_x4(ah[mi][0], ah[mi][1], ah[mi][2], ah[mi][3], ad);
                uint32_t ad2 = sAl_base + (uint32_t)(a_row + mi * 16) * (SA_STRIDE * 2) + kbyte + a_koff;
                ldsm_x4(al[mi][0], al[mi][1], al[mi][2], al[mi][3], ad2);
            }
            #pragma unroll
            for (int p = 0; p < 4; p++) {
                uint32_t bh0, bh1, bh2, bh3, bl0, bl1, bl2, bl3;
                uint32_t bd = sBh_base + (uint32_t)(b_row + p * 16) * (SA_STRIDE * 2) + kbyte + b_koff;
                ldsm_x4(bh0, bh1, bh2, bh3, bd);
                uint32_t bd2 = sBl_base + (uint32_t)(b_row + p * 16) * (SA_STRIDE * 2) + kbyte + b_koff;
                ldsm_x4(bl0, bl1, bl2, bl3, bd2);
                #pragma unroll
                for (int mi = 0; mi < 2; mi++) {
                    mma_bf16(acc[mi][2 * p],     ah[mi], bh0, bh1);
                    mma_bf16(acc[mi][2 * p + 1], ah[mi], bh2, bh3);
                }
                #pragma unroll
                for (int mi = 0; mi < 2; mi++) {
                    mma_bf16(acc[mi][2 * p],     ah[mi], bl0, bl1);
                    mma_bf16(acc[mi][2 * p + 1], ah[mi], bl2, bl3);
                }
                #pragma unroll
                for (int mi = 0; mi < 2; mi++) {
                    mma_bf16(acc[mi][2 * p],     al[mi], bh0, bh1);
                    mma_bf16(acc[mi][2 * p + 1], al[mi], bh2, bh3);
                }
            }
        }
        __syncthreads();
        if (ch + 2 < 32) { stage_load(ch + 2, st); CP_COMMIT(); }
    }
}

// ============================================================================
// Merged Q/K/V projection GEMM. blockIdx.z = kind (0=Q,1=K,2=V).
// ============================================================================
__global__ __launch_bounds__(256, 2) void gemm_qkv(
    const float* __restrict__ bq,
    const float* __restrict__ bk,
    const float* __restrict__ bv)
{
    extern __shared__ __align__(16) char dsm[];
    const uint32_t SBASE = smem_u32(dsm);

    const int kind = blockIdx.z;
    const int tid = threadIdx.x;
    const int wid = tid >> 5;
    const int lid = tid & 31;
    const int bn = blockIdx.x * 128;
    const int wm = (wid >> 1) * 32;
    const int wn = (wid & 1) * 64;

    int bm = 0, bb = 0, tile = 0, cnt = 0;
    if (kind >= 1) {
        bb   = blockIdx.y >> 4;
        tile = blockIdx.y & 15;
        cnt  = g_cnt[bb];
        if (tile * 128 >= cnt) return;
    } else {
        bm = blockIdx.y * 128;
    }

    GemmCtx cx;
    cx.Ah = g_Xh[kind]; cx.Al = g_Xl[kind];
    cx.Wh = g_Wh[kind]; cx.Wl = g_Wl[kind];

    const int lr0 = tid >> 2;
    const int lq  = tid & 3;
    if (kind >= 1) {
        int p0 = tile * 128 + lr0;
        int p1 = p0 + 64;
        int s0 = (p0 < cnt) ? g_inv[bb * SEQ + p0] : 0;
        int s1 = (p1 < cnt) ? g_inv[bb * SEQ + p1] : 0;
        cx.aoff0 = ((size_t)(bb * SEQ + s0)) * 128 + lq;
        cx.aoff1 = ((size_t)(bb * SEQ + s1)) * 128 + lq;
    } else {
        cx.aoff0 = (size_t)(bm + lr0) * 128 + lq;
        cx.aoff1 = cx.aoff0 + (size_t)64 * 128;
    }
    cx.boff0 = (size_t)(bn + lr0) * 128 + lq;
    cx.boff1 = cx.boff0 + (size_t)64 * 128;

    float acc[2][8][4];
    #pragma unroll
    for (int i = 0; i < 2; i++)
        #pragma unroll
        for (int j = 0; j < 8; j++)
            #pragma unroll
            for (int r = 0; r < 4; r++) acc[i][j][r] = 0.f;

    gemm_mainloop(cx, SBASE, tid, lid, wm, wn, acc);

    // ---- epilogue ----
    const float* bias = (kind == 0) ? bq : (kind == 1) ? bk : bv;
    const int fr = lid >> 2;
    const int fc = (lid & 3) * 2;

    #pragma unroll
    for (int mi = 0; mi < 2; mi++)
        #pragma unroll
        for (int nj = 0; nj < 8; nj++) {
            int n = bn + wn + nj * 8 + fc;
            float2 bvv = *reinterpret_cast<const float2*>(bias + n);
            #pragma unroll
            for (int half = 0; half < 2; half++) {
                float ox = acc[mi][nj][half * 2 + 0] + bvv.x;
                float oy = acc[mi][nj][half * 2 + 1] + bvv.y;
                int hh = n >> 6;
                int dh = n & (HDIM - 1);
                if (kind == 0) {
                    int m = bm + wm + mi * 16 + fr + half * 8;
                    int b  = m >> 11;
                    int s  = m & (SEQ - 1);
                    ox *= QSCALE; oy *= QSCALE;
                    size_t off = (((size_t)(b * NHEADS + hh)) * SEQ + s) * HDIM + dh;
                    *reinterpret_cast<uint32_t*>(g_Qh + off) = prmt_hi(ox, oy);
                    *reinterpret_cast<uint32_t*>(g_Ql + off) =
                        pack2(ox - trunc_hi(ox), oy - trunc_hi(oy));
                } else {
                    int pos = tile * 128 + wm + mi * 16 + fr + half * 8;
                    if (pos < cnt) {
                        size_t off = (((size_t)(bb * NHEADS + hh)) * SEQ + pos) * HDIM + dh;
                        uint32_t uhi = prmt_hi(ox, oy);
                        uint32_t ulo = pack2(ox - trunc_hi(ox), oy - trunc_hi(oy));
                        if (kind == 1) {
                            *reinterpret_cast<uint32_t*>(g_Kh + off) = uhi;
                            *reinterpret_cast<uint32_t*>(g_Kl + off) = ulo;
                        } else {
                            *reinterpret_cast<uint32_t*>(g_Vh + off) = uhi;
                            *reinterpret_cast<uint32_t*>(g_Vl + off) = ulo;
                        }
                    }
                }
            }
        }
}

// ============================================================================
// Output projection GEMM: A = g_Ch/g_Cl, C = fp32 row-major.
// ============================================================================
__global__ __launch_bounds__(256, 2) void gemm_o(
    const float* __restrict__ bias,
    float* __restrict__ Cout)
{
    extern __shared__ __align__(16) char dsm[];
    const uint32_t SBASE = smem_u32(dsm);

    const int tid = threadIdx.x;
    const int wid = tid >> 5;
    const int lid = tid & 31;
    const int bn = blockIdx.x * 128;
    const int bm = blockIdx.y * 128;
    const int wm = (wid >> 1) * 32;
    const int wn = (wid & 1) * 64;

    GemmCtx cx;
    cx.Ah = g_Ch; cx.Al = g_Cl;
    cx.Wh = g_Wh[3]; cx.Wl = g_Wl[3];

    const int lr0 = tid >> 2;
    const int lq  = tid & 3;
    cx.aoff0 = (size_t)(bm + lr0) * 128 + lq;
    cx.aoff1 = cx.aoff0 + (size_t)64 * 128;
    cx.boff0 = (size_t)(bn + lr0) * 128 + lq;
    cx.boff1 = cx.boff0 + (size_t)64 * 128;

    float acc[2][8][4];
    #pragma unroll
    for (int i = 0; i < 2; i++)
        #pragma unroll
        for (int j = 0; j < 8; j++)
            #pragma unroll
            for (int r = 0; r < 4; r++) acc[i][j][r] = 0.f;

    gemm_mainloop(cx, SBASE, tid, lid, wm, wn, acc);

    const int fr = lid >> 2;
    const int fc = (lid & 3) * 2;
    #pragma unroll
    for (int mi = 0; mi < 2; mi++)
        #pragma unroll
        for (int nj = 0; nj < 8; nj++) {
            int n = bn + wn + nj * 8 + fc;
            float2 bvv = *reinterpret_cast<const float2*>(bias + n);
            #pragma unroll
            for (int half = 0; half < 2; half++) {
                int m = bm + wm + mi * 16 + fr + half * 8;
                float2 o;
                o.x = acc[mi][nj][half * 2 + 0] + bvv.x;
                o.y = acc[mi][nj][half * 2 + 1] + bvv.y;
                *reinterpret_cast<float2*>(Cout + (size_t)m * DMODEL + n) = o;
            }
        }
}

// ============================================================================
// Tensor-core flash attention.  2-stage cp.async K/V pipeline, 2 CTAs/SM.
// Tail masking hoisted to the final partial tile; PRMT truncation P-split.
// ============================================================================
#define ASTAGE    36864
#define ATTN_SMEM (2 * ASTAGE)

__global__ __launch_bounds__(256, 2) void attn_mma()
{
    extern __shared__ __align__(16) char dsm[];
    const uint32_t SB = smem_u32(dsm);

    const int tid = threadIdx.x;
    const int wid = tid >> 5;
    const int lid = tid & 31;
    const int hh = blockIdx.y;
    const int b  = blockIdx.z;
    const int qb = blockIdx.x * 128;
    const int wq = wid * 16;
    const int cnt = g_cnt[b];

    const size_t hb = ((size_t)(b * NHEADS + hh)) * SEQ * HDIM;
    const uint4* Qh4 = reinterpret_cast<const uint4*>(g_Qh + hb + (size_t)qb * HDIM);
    const uint4* Ql4 = reinterpret_cast<const uint4*>(g_Ql + hb + (size_t)qb * HDIM);
    const uint4* Kh4 = reinterpret_cast<const uint4*>(g_Kh + hb);
    const uint4* Kl4 = reinterpret_cast<const uint4*>(g_Kl + hb);
    const uint4* Vh4 = reinterpret_cast<const uint4*>(g_Vh + hb);
    const uint4* Vl4 = reinterpret_cast<const uint4*>(g_Vl + hb);

    uint4* sb4 = reinterpret_cast<uint4*>(dsm);
    #pragma unroll
    for (int j = 0; j < 4; j++) {
        int idx = tid + 256 * j;
        int r = idx >> 3, q = idx & 7;
        sb4[9 * r + q]        = Qh4[r * 8 + q];
        sb4[1152 + 9 * r + q] = Ql4[r * 8 + q];
    }
    __syncthreads();

    uint32_t qfh[4][4], qfl[4][4];
    {
        const int arow = wq + (lid & 7) + ((lid >> 3) & 1) * 8;
        const int akoff = (lid >> 4) * 8;
        #pragma unroll
        for (int ks = 0; ks < 4; ks++) {
            uint32_t ad = SB + (uint32_t)(arow * 72 + ks * 16 + akoff) * 2;
            ldsm_x4(qfh[ks][0], qfh[ks][1], qfh[ks][2], qfh[ks][3], ad);
            ldsm_x4(qfl[ks][0], qfl[ks][1], qfl[ks][2], qfl[ks][3], ad + 18432);
        }
    }
    __syncthreads();

    const int ntl = (cnt + 63) >> 6;
    const int rem = cnt & 63;

    auto load_tile = [&](int kt, int st) {
        const uint32_t base = SB + st * ASTAGE;
        #pragma unroll
        for (int j = 0; j < 2; j++) {
            int idx = tid + 256 * j;
            int r = idx >> 3, q = idx & 7;
            uint32_t so = base + (uint32_t)(r * 144 + q * 16);
            int gi = (kt * 64 + r) * 8 + q;
            cp16(so,         Kh4 + gi);
            cp16(so + 9216,  Kl4 + gi);
            cp16(so + 18432, Vh4 + gi);
            cp16(so + 27648, Vl4 + gi);
        }
    };

    float oacc[8][4];
    #pragma unroll
    for (int ng = 0; ng < 8; ng++)
        #pragma unroll
        for (int r = 0; r < 4; r++) oacc[ng][r] = 0.f;

    float mrow0 = NEGI, mrow1 = NEGI, lrow0 = 0.f, lrow1 = 0.f;

    const int brow = (lid & 7) + ((lid >> 4) & 1) * 8;
    const int bko  = ((lid >> 3) & 1) * 8;
    const int vrow = lid & 15;
    const int vco  = (lid >> 4) * 8;
    const int fc   = (lid & 3) * 2;

    load_tile(0, 0); CP_COMMIT();
    if (ntl > 1) { load_tile(1, 1); CP_COMMIT(); }

    for (int kt = 0; kt < ntl; kt++) {
        const int st = kt & 1;
        if (kt + 1 < ntl) CP_WAIT1(); else CP_WAIT0();
        __syncthreads();
        const uint32_t SBS = SB + st * ASTAGE;

        float sacc[8][4];
        #pragma unroll
        for (int nt = 0; nt < 8; nt++)
            #pragma unroll
            for (int r = 0; r < 4; r++) sacc[nt][r] = 0.f;

        #pragma unroll
        for (int ks = 0; ks < 4; ks++) {
            uint32_t kh[8][2], kl[8][2];
            #pragma unroll
            for (int p = 0; p < 4; p++) {
                uint32_t r0, r1, r2, r3;
                uint32_t ad = SBS + (uint32_t)((p * 16 + brow) * 72 + ks * 16 + bko) * 2;
                ldsm_x4(r0, r1, r2, r3, ad);
                kh[p * 2][0] = r0; kh[p * 2][1] = r1;
                kh[p * 2 + 1][0] = r2; kh[p * 2 + 1][1] = r3;
                ldsm_x4(r0, r1, r2, r3, ad + 9216);
                kl[p * 2][0] = r0; kl[p * 2][1] = r1;
                kl[p * 2 + 1][0] = r2; kl[p * 2 + 1][1] = r3;
            }
            #pragma unroll
            for (int nt = 0; nt < 8; nt++) mma_bf16(sacc[nt], qfh[ks], kh[nt][0], kh[nt][1]);
            #pragma unroll
            for (int nt = 0; nt < 8; nt++) mma_bf16(sacc[nt], qfh[ks], kl[nt][0], kl[nt][1]);
            #pragma unroll
            for (int nt = 0; nt < 8; nt++) mma_bf16(sacc[nt], qfl[ks], kh[nt][0], kh[nt][1]);
        }

        // ---- row max: masking only on the final partial tile ----
        float tm0 = NEGI, tm1 = NEGI;
        if (rem && kt == ntl - 1) {
            const int key0 = kt * 64 + fc;
            #pragma unroll
            for (int nt = 0; nt < 8; nt++) {
                bool v0 = (key0 + nt * 8) < cnt;
                bool v1 = (key0 + nt * 8 + 1) < cnt;
                if (!v0) { sacc[nt][0] = NEGI; sacc[nt][2] = NEGI; }
                if (!v1) { sacc[nt][1] = NEGI; sacc[nt][3] = NEGI; }
                tm0 = fmaxf(tm0, fmaxf(sacc[nt][0], sacc[nt][1]));
                tm1 = fmaxf(tm1, fmaxf(sacc[nt][2], sacc[nt][3]));
            }
        } else {
            #pragma unroll
            for (int nt = 0; nt < 8; nt++) {
                tm0 = fmaxf(tm0, fmaxf(sacc[nt][0], sacc[nt][1]));
                tm1 = fmaxf(tm1, fmaxf(sacc[nt][2], sacc[nt][3]));
            }
        }
        tm0 = fmaxf(tm0, __shfl_xor_sync(0xffffffffu, tm0, 1));
        tm0 = fmaxf(tm0, __shfl_xor_sync(0xffffffffu, tm0, 2));
        tm1 = fmaxf(tm1, __shfl_xor_sync(0xffffffffu, tm1, 1));
        tm1 = fmaxf(tm1, __shfl_xor_sync(0xffffffffu, tm1, 2));

        const float mn0 = fmaxf(mrow0, tm0), mn1 = fmaxf(mrow1, tm1);
        const float c0 = ex2(mrow0 - mn0), c1 = ex2(mrow1 - mn1);
        mrow0 = mn0; mrow1 = mn1;

        // ---- p = exp2(s - m); PRMT truncation split ----
        uint32_t pah[4][4], pal[4][4];
        float ls0 = 0.f, ls1 = 0.f;
        #pragma unroll
        for (int nt = 0; nt < 8; nt++) {
            float p0 = ex2(sacc[nt][0] - mn0), p1 = ex2(sacc[nt][1] - mn0);
            float p2 = ex2(sacc[nt][2] - mn1), p3 = ex2(sacc[nt][3] - mn1);
            ls0 += p0 + p1; ls1 += p2 + p3;
            int kc = nt >> 1, o2 = (nt & 1) * 2;
            pah[kc][o2 + 0] = prmt_hi(p0, p1);
            pah[kc][o2 + 1] = prmt_hi(p2, p3);
            pal[kc][o2 + 0] = pack2(p0 - trunc_hi(p0), p1 - trunc_hi(p1));
            pal[kc][o2 + 1] = pack2(p2 - trunc_hi(p2), p3 - trunc_hi(p3));
        }
        lrow0 = lrow0 * c0 + ls0;
        lrow1 = lrow1 * c1 + ls1;
        #pragma unroll
        for (int ng = 0; ng < 8; ng++) {
            oacc[ng][0] *= c0; oacc[ng][1] *= c0;
            oacc[ng][2] *= c1; oacc[ng][3] *= c1;
        }

        #pragma unroll
        for (int kc = 0; kc < 4; kc++) {
            uint32_t vh[8][2], vl[8][2];
            #pragma unroll
            for (int p = 0; p < 4; p++) {
                uint32_t r0, r1, r2, r3;
                uint32_t ad = SBS + 18432 + (uint32_t)((kc * 16 + vrow) * 72 + p * 16 + vco) * 2;
                ldsm_x4t(r0, r1, r2, r3, ad);
                vh[p * 2][0] = r0; vh[p * 2][1] = r1;
                vh[p * 2 + 1][0] = r2; vh[p * 2 + 1][1] = r3;
                ldsm_x4t(r0, r1, r2, r3, ad + 9216);
                vl[p * 2][0] = r0; vl[p * 2][1] = r1;
                vl[p * 2 + 1][0] = r2; vl[p * 2 + 1][1] = r3;
            }
            #pragma unroll
            for (int ng = 0; ng < 8; ng++) mma_bf16(oacc[ng], pah[kc], vh[ng][0], vh[ng][1]);
            #pragma unroll
            for (int ng = 0; ng < 8; ng++) mma_bf16(oacc[ng], pah[kc], vl[ng][0], vl[ng][1]);
            #pragma unroll
            for (int ng = 0; ng < 8; ng++) mma_bf16(oacc[ng], pal[kc], vh[ng][0], vh[ng][1]);
        }
        __syncthreads();
        if (kt + 2 < ntl) { load_tile(kt + 2, st); CP_COMMIT(); }
    }

    lrow0 += __shfl_xor_sync(0xffffffffu, lrow0, 1);
    lrow0 += __shfl_xor_sync(0xffffffffu, lrow0, 2);
    lrow1 += __shfl_xor_sync(0xffffffffu, lrow1, 1);
    lrow1 += __shfl_xor_sync(0xffffffffu, lrow1, 2);

    const float inv0 = 1.0f / lrow0;
    const float inv1 = 1.0f / lrow1;
    const int r0 = qb + wq + (lid >> 2);
    const int r1 = r0 + 8;
    #pragma unroll
    for (int ng = 0; ng < 8; ng++) {
        int col = hh * HDIM + ng * 8 + fc;
        float a0 = oacc[ng][0] * inv0, a1 = oacc[ng][1] * inv0;
        float a2 = oacc[ng][2] * inv1, a3 = oacc[ng][3] * inv1;
        size_t off0 = ((size_t)(b * SEQ + r0)) * DMODEL + col;
        size_t off1 = ((size_t)(b * SEQ + r1)) * DMODEL + col;
        *reinterpret_cast<uint32_t*>(g_Ch + off0) = prmt_hi(a0, a1);
        *reinterpret_cast<uint32_t*>(g_Cl + off0) =
            pack2(a0 - trunc_hi(a0), a1 - trunc_hi(a1));
        *reinterpret_cast<uint32_t*>(g_Ch + off1) = prmt_hi(a2, a3);
        *reinterpret_cast<uint32_t*>(g_Cl + off1) =
            pack2(a2 - trunc_hi(a2), a3 - trunc_hi(a3));
    }
}

// ============================================================================
// Launch
// ============================================================================
extern "C" void kernel_launch(void* const* d_in, const int* in_sizes, int n_in,
                              void* d_out, int out_size)
{
    const float* query = (const float*)d_in[0];
    const float* key   = (const float*)d_in[1];
    const float* value = (const float*)d_in[2];
    const int*   mask  = (const int*)  d_in[3];
    const float* Wq    = (const float*)d_in[4];
    const float* bq    = (const float*)d_in[5];
    const float* Wk    = (const float*)d_in[6];
    const float* bk    = (const float*)d_in[7];
    const float* Wv    = (const float*)d_in[8];
    const float* bv    = (const float*)d_in[9];
    const float* Wo    = (const float*)d_in[10];
    const float* bo    = (const float*)d_in[11];
    float* out = (float*)d_out;

    static bool attr_done = false;
    if (!attr_done) {
        cudaFuncSetAttribute(gemm_qkv, cudaFuncAttributeMaxDynamicSharedMemorySize, GEMM_SMEM);
        cudaFuncSetAttribute(gemm_o,   cudaFuncAttributeMaxDynamicSharedMemorySize, GEMM_SMEM);
        cudaFuncSetAttribute(attn_mma, cudaFuncAttributeMaxDynamicSharedMemorySize, ATTN_SMEM);
        attr_done = true;
    }

    const int nx4 = MTOT * DMODEL / 4;
    const int nw4 = DMODEL * DMODEL / 4;

    compact_mask<<<BATCH, 1024>>>(mask);
    convert_all<<<dim3(nx4 / 512, 7), 256>>>((const float4*)query, (const float4*)key,
                                             (const float4*)value,
                                             (const float4*)Wq, (const float4*)Wk,
                                             (const float4*)Wv, (const float4*)Wo,
                                             nx4, nw4);

    dim3 qkvGrid(DMODEL / 128, MTOT / 128, 3);   // (8, 64, 3)
    gemm_qkv<<<qkvGrid, 256, GEMM_SMEM>>>(bq, bk, bv);

    dim3 attnGrid(SEQ / 128, NHEADS, BATCH);     // (16, 16, 4)
    attn_mma<<<attnGrid, 256, ATTN_SMEM>>>();

    dim3 oGrid(DMODEL / 128, MTOT / 128);        // (8, 64)
    gemm_o<<<oGrid, 256, GEMM_SMEM>>>(bo, out);
}